// round 1
// baseline (speedup 1.0000x reference)
#include <cuda_runtime.h>
#include <math.h>

#define BB     8
#define CC     256
#define NN     16384          // 128*128
#define HEADS  8
#define DHH    64
#define KRR    64
#define INNER  512
#define KCONV  2304           // 9*C

// ---------------- scratch (device globals; no cudaMalloc allowed) -------------
__device__ float g_wr[(size_t)KCONV * INNER];        // conv weights [k=(ky*3+kx)*C+c][o]
__device__ float g_xc[(size_t)BB * NN * INNER];      // conv out [b][n][o]   (268 MB)
__device__ float g_colsum[BB * HEADS * KRR];
__device__ float g_kv[BB * HEADS * KRR * DHH];
__device__ float g_qkv[(size_t)BB * NN * INNER];     // attention out (268 MB)
__device__ float g_h1[(size_t)BB * NN * CC];         // MLP hidden (134 MB)

// ---------------- weight rearrange: conv_w [o][c][ky][kx] -> g_wr[k*C+c][o] ---
__global__ void k_wrearrange(const float* __restrict__ conv_w) {
    int idx = blockIdx.x * 256 + threadIdx.x;        // over KCONV*INNER
    if (idx >= KCONV * INNER) return;
    int o  = idx & (INNER - 1);
    int kc = idx >> 9;                // k*CC + c
    int c  = kc & (CC - 1);
    int k  = kc >> 8;
    g_wr[idx] = conv_w[(size_t)(o * CC + c) * 9 + k];
}

// ---------------- zero kv accumulators ---------------------------------------
__global__ void k_init() {
    int i = blockIdx.x * 256 + threadIdx.x;          // grid covers 262144
    g_kv[i] = 0.f;
    if (i < BB * HEADS * KRR) g_colsum[i] = 0.f;
}

// ---------------- conv as implicit GEMM --------------------------------------
// out[m=(b*N+p)][o] = sum_{k<2304} patch(m,k) * g_wr[k][o] + conv_b[o]
__global__ __launch_bounds__(256) void k_conv(const float* __restrict__ x,
                                              const float* __restrict__ conv_b) {
    __shared__ float As[64][36];     // [m][k]
    __shared__ float Bs[32][68];     // [k][o]
    const int tid = threadIdx.x;
    const int tx = tid & 15, ty = tid >> 4;
    const int otile = blockIdx.x * 64;               // 0..448
    const int mtile = blockIdx.y * 64;               // global row (b*N+p)
    const int b  = mtile >> 14;
    const int p0 = mtile & (NN - 1);

    // A-loader mapping
    const int mA  = tid >> 2;                        // 0..63
    const int kq4 = (tid & 3) * 4;                   // 0,4,8,12
    const int pA  = p0 + mA;
    const int pyA = pA >> 7, pxA = pA & 127;
    // B-loader mapping
    const int kB = tid >> 3;                         // 0..31
    const int oB = (tid & 7) * 8;                    // 0..56

    const float* xb = x + (size_t)b * NN * CC;
    float acc[4][4] = {};

    for (int s = 0; s < KCONV / 32; s++) {
        const int kk0 = s * 32;
        const int g = kk0 >> 8;                      // 0..8 = ky*3+kx
        const int dy = g / 3 - 1, dx = g % 3 - 1;
        const int cbase = kk0 & 255;
        const int yy = pyA + dy, xx = pxA + dx;
        const bool valid = ((unsigned)yy < 128u) && ((unsigned)xx < 128u);
        float4 a0 = make_float4(0.f, 0.f, 0.f, 0.f), a1 = a0;
        if (valid) {
            const float* src = xb + ((size_t)((yy << 7) + xx)) * CC + cbase;
            a0 = *(const float4*)(src + kq4);
            a1 = *(const float4*)(src + kq4 + 16);
        }
        const float* wsrc = g_wr + (size_t)(kk0 + kB) * INNER + otile + oB;
        const float4 b0 = *(const float4*)(wsrc);
        const float4 b1 = *(const float4*)(wsrc + 4);

        __syncthreads();
        *(float4*)&As[mA][kq4]      = a0;
        *(float4*)&As[mA][kq4 + 16] = a1;
        *(float4*)&Bs[kB][oB]       = b0;
        *(float4*)&Bs[kB][oB + 4]   = b1;
        __syncthreads();

        #pragma unroll
        for (int k = 0; k < 32; k++) {
            const float4 bv = *(const float4*)&Bs[k][tx * 4];
            float av[4];
            #pragma unroll
            for (int i = 0; i < 4; i++) av[i] = As[ty * 4 + i][k];
            #pragma unroll
            for (int i = 0; i < 4; i++) {
                acc[i][0] += av[i] * bv.x;
                acc[i][1] += av[i] * bv.y;
                acc[i][2] += av[i] * bv.z;
                acc[i][3] += av[i] * bv.w;
            }
        }
    }

    const float4 bias = *(const float4*)(conv_b + otile + tx * 4);
    #pragma unroll
    for (int i = 0; i < 4; i++) {
        const int m = mtile + ty * 4 + i;
        float4 r = make_float4(acc[i][0] + bias.x, acc[i][1] + bias.y,
                               acc[i][2] + bias.z, acc[i][3] + bias.w);
        *(float4*)(g_xc + (size_t)m * INNER + otile + tx * 4) = r;
    }
}

// ---------------- fused k,v -> partial kv + colsum ---------------------------
// One block = one (b,h) x 256 rows (4 sub-chunks of 64).
__global__ __launch_bounds__(256) void k_kv(const float* __restrict__ Wk,
                                            const float* __restrict__ Wv) {
    extern __shared__ float sm[];
    float* Xs  = sm;             // [64][68]
    float* Wks = sm + 4352;
    float* Wvs = sm + 8704;
    float* Ks  = sm + 13056;
    float* Vs  = sm + 17408;     // total 21760 floats = 87040 B

    const int tid = threadIdx.x;
    const int bh = blockIdx.y;
    const int b = bh >> 3, h = bh & 7;
    const int r  = tid >> 2;                 // 0..63
    const int c0 = (tid & 3) * 16;

    #pragma unroll
    for (int i = 0; i < 4; i++) {
        *(float4*)&Wks[r * 68 + c0 + i * 4] = *(const float4*)&Wk[r * 64 + c0 + i * 4];
        *(float4*)&Wvs[r * 68 + c0 + i * 4] = *(const float4*)&Wv[r * 64 + c0 + i * 4];
    }

    float kvacc[16] = {};
    float csum = 0.f;

    for (int sub = 0; sub < 4; sub++) {
        const int n0 = blockIdx.x * 256 + sub * 64;
        const float* xsrc = g_xc + ((size_t)(b * NN + n0 + r)) * INNER + h * 64 + c0;
        float4 xl[4];
        #pragma unroll
        for (int i = 0; i < 4; i++) xl[i] = *(const float4*)(xsrc + i * 4);
        __syncthreads();
        #pragma unroll
        for (int i = 0; i < 4; i++) *(float4*)&Xs[r * 68 + c0 + i * 4] = xl[i];
        __syncthreads();

        float kreg[16] = {}, vreg[16] = {};
        for (int d = 0; d < 64; d += 4) {
            const float4 xv = *(const float4*)&Xs[r * 68 + d];
            #pragma unroll
            for (int j = 0; j < 16; j++) {
                const float4 wk = *(const float4*)&Wks[(c0 + j) * 68 + d];
                kreg[j] += xv.x * wk.x + xv.y * wk.y + xv.z * wk.z + xv.w * wk.w;
            }
            #pragma unroll
            for (int j = 0; j < 16; j++) {
                const float4 wv = *(const float4*)&Wvs[(c0 + j) * 68 + d];
                vreg[j] += xv.x * wv.x + xv.y * wv.y + xv.z * wv.z + xv.w * wv.w;
            }
        }
        #pragma unroll
        for (int j = 0; j < 16; j++) {
            Ks[r * 68 + c0 + j] = __expf(kreg[j]);
            Vs[r * 68 + c0 + j] = vreg[j];
        }
        __syncthreads();

        // partial kv: this thread owns kr=r, dh = c0..c0+15
        for (int row = 0; row < 64; row++) {
            const float kk = Ks[row * 68 + r];
            csum += kk;
            #pragma unroll
            for (int jj = 0; jj < 4; jj++) {
                const float4 vv = *(const float4*)&Vs[row * 68 + c0 + jj * 4];
                kvacc[jj * 4 + 0] += kk * vv.x;
                kvacc[jj * 4 + 1] += kk * vv.y;
                kvacc[jj * 4 + 2] += kk * vv.z;
                kvacc[jj * 4 + 3] += kk * vv.w;
            }
        }
    }

    float* kvp = g_kv + (size_t)bh * KRR * DHH + r * DHH + c0;
    #pragma unroll
    for (int j = 0; j < 16; j++) atomicAdd(kvp + j, kvacc[j]);
    if ((tid & 3) == 0) atomicAdd(g_colsum + bh * KRR + r, csum);
}

// ---------------- kv normalize by column softmax denominator -----------------
__global__ void k_kvnorm() {
    int i = blockIdx.x * 256 + threadIdx.x;          // grid covers 262144 exactly
    g_kv[i] = g_kv[i] / g_colsum[i >> 6];
}

// ---------------- fused q -> softmax -> q @ kv --------------------------------
__global__ __launch_bounds__(256) void k_qkv(const float* __restrict__ Wq) {
    __shared__ float Xs[64 * 68];
    __shared__ float Ws[64 * 68];
    const int tid = threadIdx.x;
    const int bh = blockIdx.y;
    const int b = bh >> 3, h = bh & 7;
    const int n0 = blockIdx.x * 64;
    const int r  = tid >> 2;
    const int c0 = (tid & 3) * 16;

    #pragma unroll
    for (int i = 0; i < 4; i++)
        *(float4*)&Ws[r * 68 + c0 + i * 4] = *(const float4*)&Wq[r * 64 + c0 + i * 4];
    const float* xsrc = g_xc + ((size_t)(b * NN + n0 + r)) * INNER + h * 64 + c0;
    #pragma unroll
    for (int i = 0; i < 4; i++)
        *(float4*)&Xs[r * 68 + c0 + i * 4] = *(const float4*)(xsrc + i * 4);
    __syncthreads();

    float qv[16] = {};
    for (int d = 0; d < 64; d += 4) {
        const float4 xv = *(const float4*)&Xs[r * 68 + d];
        #pragma unroll
        for (int j = 0; j < 16; j++) {
            const float4 w = *(const float4*)&Ws[(c0 + j) * 68 + d];
            qv[j] += xv.x * w.x + xv.y * w.y + xv.z * w.z + xv.w * w.w;
        }
    }
    float ssum = 0.f;
    #pragma unroll
    for (int j = 0; j < 16; j++) { qv[j] = __expf(qv[j]); ssum += qv[j]; }
    ssum += __shfl_xor_sync(0xffffffffu, ssum, 1);
    ssum += __shfl_xor_sync(0xffffffffu, ssum, 2);
    const float inv = 1.f / ssum;

    __syncthreads();
    #pragma unroll
    for (int j = 0; j < 16; j++) Xs[r * 68 + c0 + j] = qv[j] * inv;   // Xs := q_softmax
    const float* kvsrc = g_kv + (size_t)bh * KRR * DHH;
    #pragma unroll
    for (int i = 0; i < 4; i++)                                        // Ws := kv
        *(float4*)&Ws[r * 68 + c0 + i * 4] = *(const float4*)(kvsrc + r * 64 + c0 + i * 4);
    __syncthreads();

    float acc[16] = {};
    for (int d = 0; d < 64; d++) {
        const float q = Xs[r * 68 + d];
        #pragma unroll
        for (int jj = 0; jj < 4; jj++) {
            const float4 kvv = *(const float4*)&Ws[d * 68 + c0 + jj * 4];
            acc[jj * 4 + 0] += q * kvv.x;
            acc[jj * 4 + 1] += q * kvv.y;
            acc[jj * 4 + 2] += q * kvv.z;
            acc[jj * 4 + 3] += q * kvv.w;
        }
    }
    float* dst = g_qkv + ((size_t)(b * NN + n0 + r)) * INNER + h * 64 + c0;
    #pragma unroll
    for (int jj = 0; jj < 4; jj++)
        *(float4*)(dst + jj * 4) = make_float4(acc[jj * 4 + 0], acc[jj * 4 + 1],
                                               acc[jj * 4 + 2], acc[jj * 4 + 3]);
}

// ---------------- MLP NT-GEMM: out = act(A @ Wt + bias) ----------------------
// MODE 0: A=g_qkv (K=512), out=g_h1, exact GELU.  MODE 1: A=g_h1 (K=256), out=d_out.
template <int MODE>
__global__ __launch_bounds__(256) void k_mlp(const float* __restrict__ Bw,
                                             const float* __restrict__ bias,
                                             float* __restrict__ out_ext) {
    constexpr int K = MODE ? 256 : 512;
    const float* A = MODE ? g_h1 : g_qkv;
    float* out = MODE ? out_ext : g_h1;

    __shared__ float As[64][36];     // [m][k]
    __shared__ float Bs[32][68];     // [k][o]
    const int tid = threadIdx.x;
    const int tx = tid & 15, ty = tid >> 4;
    const int otile = blockIdx.x * 64;
    const int m0 = blockIdx.y * 64;
    const int mA  = tid >> 2;
    const int kq4 = (tid & 3) * 4;
    const int oB  = tid >> 2;
    float acc[4][4] = {};

    #pragma unroll 2
    for (int kk0 = 0; kk0 < K; kk0 += 32) {
        const float* asrc = A + (size_t)(m0 + mA) * K + kk0 + kq4;
        const float4 a0 = *(const float4*)(asrc);
        const float4 a1 = *(const float4*)(asrc + 16);
        const float* wsrc = Bw + (size_t)(otile + oB) * K + kk0 + kq4;
        const float4 w0 = *(const float4*)(wsrc);
        const float4 w1 = *(const float4*)(wsrc + 16);

        __syncthreads();
        *(float4*)&As[mA][kq4]      = a0;
        *(float4*)&As[mA][kq4 + 16] = a1;
        Bs[kq4 + 0][oB] = w0.x;  Bs[kq4 + 1][oB] = w0.y;
        Bs[kq4 + 2][oB] = w0.z;  Bs[kq4 + 3][oB] = w0.w;
        Bs[kq4 + 16][oB] = w1.x; Bs[kq4 + 17][oB] = w1.y;
        Bs[kq4 + 18][oB] = w1.z; Bs[kq4 + 19][oB] = w1.w;
        __syncthreads();

        #pragma unroll
        for (int k = 0; k < 32; k++) {
            const float4 bv = *(const float4*)&Bs[k][tx * 4];
            float av[4];
            #pragma unroll
            for (int i = 0; i < 4; i++) av[i] = As[ty * 4 + i][k];
            #pragma unroll
            for (int i = 0; i < 4; i++) {
                acc[i][0] += av[i] * bv.x;
                acc[i][1] += av[i] * bv.y;
                acc[i][2] += av[i] * bv.z;
                acc[i][3] += av[i] * bv.w;
            }
        }
    }

    const float4 bb = *(const float4*)(bias + otile + tx * 4);
    #pragma unroll
    for (int i = 0; i < 4; i++) {
        float v[4] = {acc[i][0] + bb.x, acc[i][1] + bb.y, acc[i][2] + bb.z, acc[i][3] + bb.w};
        if (MODE == 0) {
            #pragma unroll
            for (int j = 0; j < 4; j++)
                v[j] = 0.5f * v[j] * (1.0f + erff(v[j] * 0.70710678118654752f));
        }
        const int m = m0 + ty * 4 + i;
        *(float4*)(out + (size_t)m * CC + otile + tx * 4) =
            make_float4(v[0], v[1], v[2], v[3]);
    }
}

// ------------------------------------------------------------------------------
extern "C" void kernel_launch(void* const* d_in, const int* in_sizes, int n_in,
                              void* d_out, int out_size) {
    const float* x      = (const float*)d_in[0];
    const float* conv_w = (const float*)d_in[1];
    const float* conv_b = (const float*)d_in[2];
    const float* Wq     = (const float*)d_in[3];
    const float* Wk     = (const float*)d_in[4];
    const float* Wv     = (const float*)d_in[5];
    const float* W1     = (const float*)d_in[6];
    const float* b1     = (const float*)d_in[7];
    const float* W2     = (const float*)d_in[8];
    const float* b2     = (const float*)d_in[9];
    float* out = (float*)d_out;

    cudaFuncSetAttribute(k_kv, cudaFuncAttributeMaxDynamicSharedMemorySize, 87040);

    k_wrearrange<<<(KCONV * INNER + 255) / 256, 256>>>(conv_w);
    k_init<<<(BB * HEADS * KRR * DHH) / 256, 256>>>();
    k_conv<<<dim3(INNER / 64, (BB * NN) / 64), 256>>>(x, conv_b);
    k_kv<<<dim3(NN / 256, BB * HEADS), 256, 87040>>>(Wk, Wv);
    k_kvnorm<<<(BB * HEADS * KRR * DHH) / 256, 256>>>();
    k_qkv<<<dim3(NN / 64, BB * HEADS), 256>>>(Wq);
    k_mlp<0><<<dim3(CC / 64, (BB * NN) / 64), 256>>>(W1, b1, nullptr);
    k_mlp<1><<<dim3(CC / 64, (BB * NN) / 64), 256>>>(W2, b2, out);
}

// round 2
// speedup vs baseline: 1.0022x; 1.0022x over previous
#include <cuda_runtime.h>
#include <math.h>

#define BB     8
#define CC     256
#define NN     16384          // 128*128
#define HEADS  8
#define DHH    64
#define KRR    64
#define INNER  512
#define KCONV  2304           // 9*C

// ---------------- scratch (device globals; no cudaMalloc allowed) -------------
__device__ float g_wr[(size_t)KCONV * INNER];        // conv weights [k=(ky*3+kx)*C+c][o]
__device__ float g_xc[(size_t)BB * NN * INNER];      // conv out [b][n][o]   (268 MB)
__device__ float g_colsum[BB * HEADS * KRR];
__device__ float g_kv[BB * HEADS * KRR * DHH];
__device__ float g_qkv[(size_t)BB * NN * INNER];     // attention out (268 MB)
__device__ float g_h1[(size_t)BB * NN * CC];         // MLP hidden (134 MB)

// ---------------- weight rearrange: conv_w [o][c][ky][kx] -> g_wr[k*C+c][o] ---
__global__ void k_wrearrange(const float* __restrict__ conv_w) {
    int idx = blockIdx.x * 256 + threadIdx.x;        // over KCONV*INNER
    if (idx >= KCONV * INNER) return;
    int o  = idx & (INNER - 1);
    int kc = idx >> 9;                // k*CC + c
    int c  = kc & (CC - 1);
    int k  = kc >> 8;
    g_wr[idx] = conv_w[(size_t)(o * CC + c) * 9 + k];
}

// ---------------- zero kv accumulators ---------------------------------------
__global__ void k_init() {
    int i = blockIdx.x * 256 + threadIdx.x;          // grid covers 262144
    g_kv[i] = 0.f;
    if (i < BB * HEADS * KRR) g_colsum[i] = 0.f;
}

// ---------------- conv as implicit GEMM --------------------------------------
// out[m=(b*N+p)][o] = sum_{k<2304} patch(m,k) * g_wr[k][o] + conv_b[o]
__global__ __launch_bounds__(256) void k_conv(const float* __restrict__ x,
                                              const float* __restrict__ conv_b) {
    __shared__ float As[64][36];     // [m][k]
    __shared__ float Bs[32][68];     // [k][o]
    const int tid = threadIdx.x;
    const int tx = tid & 15, ty = tid >> 4;
    const int otile = blockIdx.x * 64;               // 0..448
    const int mtile = blockIdx.y * 64;               // global row (b*N+p)
    const int b  = mtile >> 14;
    const int p0 = mtile & (NN - 1);

    // A-loader mapping
    const int mA  = tid >> 2;                        // 0..63
    const int kq4 = (tid & 3) * 4;                   // 0,4,8,12
    const int pA  = p0 + mA;
    const int pyA = pA >> 7, pxA = pA & 127;
    // B-loader mapping
    const int kB = tid >> 3;                         // 0..31
    const int oB = (tid & 7) * 8;                    // 0..56

    const float* xb = x + (size_t)b * NN * CC;
    float acc[4][4] = {};

    for (int s = 0; s < KCONV / 32; s++) {
        const int kk0 = s * 32;
        const int g = kk0 >> 8;                      // 0..8 = ky*3+kx
        const int dy = g / 3 - 1, dx = g % 3 - 1;
        const int cbase = kk0 & 255;
        const int yy = pyA + dy, xx = pxA + dx;
        const bool valid = ((unsigned)yy < 128u) && ((unsigned)xx < 128u);
        float4 a0 = make_float4(0.f, 0.f, 0.f, 0.f), a1 = a0;
        if (valid) {
            const float* src = xb + ((size_t)((yy << 7) + xx)) * CC + cbase;
            a0 = *(const float4*)(src + kq4);
            a1 = *(const float4*)(src + kq4 + 16);
        }
        const float* wsrc = g_wr + (size_t)(kk0 + kB) * INNER + otile + oB;
        const float4 b0 = *(const float4*)(wsrc);
        const float4 b1 = *(const float4*)(wsrc + 4);

        __syncthreads();
        *(float4*)&As[mA][kq4]      = a0;
        *(float4*)&As[mA][kq4 + 16] = a1;
        *(float4*)&Bs[kB][oB]       = b0;
        *(float4*)&Bs[kB][oB + 4]   = b1;
        __syncthreads();

        #pragma unroll
        for (int k = 0; k < 32; k++) {
            const float4 bv = *(const float4*)&Bs[k][tx * 4];
            float av[4];
            #pragma unroll
            for (int i = 0; i < 4; i++) av[i] = As[ty * 4 + i][k];
            #pragma unroll
            for (int i = 0; i < 4; i++) {
                acc[i][0] += av[i] * bv.x;
                acc[i][1] += av[i] * bv.y;
                acc[i][2] += av[i] * bv.z;
                acc[i][3] += av[i] * bv.w;
            }
        }
    }

    const float4 bias = *(const float4*)(conv_b + otile + tx * 4);
    #pragma unroll
    for (int i = 0; i < 4; i++) {
        const int m = mtile + ty * 4 + i;
        float4 r = make_float4(acc[i][0] + bias.x, acc[i][1] + bias.y,
                               acc[i][2] + bias.z, acc[i][3] + bias.w);
        *(float4*)(g_xc + (size_t)m * INNER + otile + tx * 4) = r;
    }
}

// ---------------- fused k,v -> partial kv + colsum ---------------------------
// One block = one (b,h) x 256 rows (4 sub-chunks of 64).
__global__ __launch_bounds__(256) void k_kv(const float* __restrict__ Wk,
                                            const float* __restrict__ Wv) {
    extern __shared__ float sm[];
    float* Xs  = sm;             // [64][68]
    float* Wks = sm + 4352;
    float* Wvs = sm + 8704;
    float* Ks  = sm + 13056;
    float* Vs  = sm + 17408;     // total 21760 floats = 87040 B

    const int tid = threadIdx.x;
    const int bh = blockIdx.y;
    const int b = bh >> 3, h = bh & 7;
    const int r  = tid >> 2;                 // 0..63
    const int c0 = (tid & 3) * 16;

    #pragma unroll
    for (int i = 0; i < 4; i++) {
        *(float4*)&Wks[r * 68 + c0 + i * 4] = *(const float4*)&Wk[r * 64 + c0 + i * 4];
        *(float4*)&Wvs[r * 68 + c0 + i * 4] = *(const float4*)&Wv[r * 64 + c0 + i * 4];
    }

    float kvacc[16] = {};
    float csum = 0.f;

    for (int sub = 0; sub < 4; sub++) {
        const int n0 = blockIdx.x * 256 + sub * 64;
        const float* xsrc = g_xc + ((size_t)(b * NN + n0 + r)) * INNER + h * 64 + c0;
        float4 xl[4];
        #pragma unroll
        for (int i = 0; i < 4; i++) xl[i] = *(const float4*)(xsrc + i * 4);
        __syncthreads();
        #pragma unroll
        for (int i = 0; i < 4; i++) *(float4*)&Xs[r * 68 + c0 + i * 4] = xl[i];
        __syncthreads();

        float kreg[16] = {}, vreg[16] = {};
        for (int d = 0; d < 64; d += 4) {
            const float4 xv = *(const float4*)&Xs[r * 68 + d];
            #pragma unroll
            for (int j = 0; j < 16; j++) {
                const float4 wk = *(const float4*)&Wks[(c0 + j) * 68 + d];
                kreg[j] += xv.x * wk.x + xv.y * wk.y + xv.z * wk.z + xv.w * wk.w;
            }
            #pragma unroll
            for (int j = 0; j < 16; j++) {
                const float4 wv = *(const float4*)&Wvs[(c0 + j) * 68 + d];
                vreg[j] += xv.x * wv.x + xv.y * wv.y + xv.z * wv.z + xv.w * wv.w;
            }
        }
        #pragma unroll
        for (int j = 0; j < 16; j++) {
            Ks[r * 68 + c0 + j] = __expf(kreg[j]);
            Vs[r * 68 + c0 + j] = vreg[j];
        }
        __syncthreads();

        // partial kv: this thread owns kr=r, dh = c0..c0+15
        for (int row = 0; row < 64; row++) {
            const float kk = Ks[row * 68 + r];
            csum += kk;
            #pragma unroll
            for (int jj = 0; jj < 4; jj++) {
                const float4 vv = *(const float4*)&Vs[row * 68 + c0 + jj * 4];
                kvacc[jj * 4 + 0] += kk * vv.x;
                kvacc[jj * 4 + 1] += kk * vv.y;
                kvacc[jj * 4 + 2] += kk * vv.z;
                kvacc[jj * 4 + 3] += kk * vv.w;
            }
        }
    }

    float* kvp = g_kv + (size_t)bh * KRR * DHH + r * DHH + c0;
    #pragma unroll
    for (int j = 0; j < 16; j++) atomicAdd(kvp + j, kvacc[j]);
    if ((tid & 3) == 0) atomicAdd(g_colsum + bh * KRR + r, csum);
}

// ---------------- kv normalize by column softmax denominator -----------------
__global__ void k_kvnorm() {
    int i = blockIdx.x * 256 + threadIdx.x;          // grid covers 262144 exactly
    g_kv[i] = g_kv[i] / g_colsum[i >> 6];
}

// ---------------- fused q -> softmax -> q @ kv --------------------------------
__global__ __launch_bounds__(256) void k_qkv(const float* __restrict__ Wq) {
    __shared__ float Xs[64 * 68];
    __shared__ float Ws[64 * 68];
    const int tid = threadIdx.x;
    const int bh = blockIdx.y;
    const int b = bh >> 3, h = bh & 7;
    const int n0 = blockIdx.x * 64;
    const int r  = tid >> 2;
    const int c0 = (tid & 3) * 16;

    #pragma unroll
    for (int i = 0; i < 4; i++)
        *(float4*)&Ws[r * 68 + c0 + i * 4] = *(const float4*)&Wq[r * 64 + c0 + i * 4];
    const float* xsrc = g_xc + ((size_t)(b * NN + n0 + r)) * INNER + h * 64 + c0;
    #pragma unroll
    for (int i = 0; i < 4; i++)
        *(float4*)&Xs[r * 68 + c0 + i * 4] = *(const float4*)(xsrc + i * 4);
    __syncthreads();

    float qv[16] = {};
    for (int d = 0; d < 64; d += 4) {
        const float4 xv = *(const float4*)&Xs[r * 68 + d];
        #pragma unroll
        for (int j = 0; j < 16; j++) {
            const float4 w = *(const float4*)&Ws[(c0 + j) * 68 + d];
            qv[j] += xv.x * w.x + xv.y * w.y + xv.z * w.z + xv.w * w.w;
        }
    }
    float ssum = 0.f;
    #pragma unroll
    for (int j = 0; j < 16; j++) { qv[j] = __expf(qv[j]); ssum += qv[j]; }
    ssum += __shfl_xor_sync(0xffffffffu, ssum, 1);
    ssum += __shfl_xor_sync(0xffffffffu, ssum, 2);
    const float inv = 1.f / ssum;

    __syncthreads();
    #pragma unroll
    for (int j = 0; j < 16; j++) Xs[r * 68 + c0 + j] = qv[j] * inv;   // Xs := q_softmax
    const float* kvsrc = g_kv + (size_t)bh * KRR * DHH;
    #pragma unroll
    for (int i = 0; i < 4; i++)                                        // Ws := kv
        *(float4*)&Ws[r * 68 + c0 + i * 4] = *(const float4*)(kvsrc + r * 64 + c0 + i * 4);
    __syncthreads();

    float acc[16] = {};
    for (int d = 0; d < 64; d++) {
        const float q = Xs[r * 68 + d];
        #pragma unroll
        for (int jj = 0; jj < 4; jj++) {
            const float4 kvv = *(const float4*)&Ws[d * 68 + c0 + jj * 4];
            acc[jj * 4 + 0] += q * kvv.x;
            acc[jj * 4 + 1] += q * kvv.y;
            acc[jj * 4 + 2] += q * kvv.z;
            acc[jj * 4 + 3] += q * kvv.w;
        }
    }
    float* dst = g_qkv + ((size_t)(b * NN + n0 + r)) * INNER + h * 64 + c0;
    #pragma unroll
    for (int jj = 0; jj < 4; jj++)
        *(float4*)(dst + jj * 4) = make_float4(acc[jj * 4 + 0], acc[jj * 4 + 1],
                                               acc[jj * 4 + 2], acc[jj * 4 + 3]);
}

// ---------------- MLP NT-GEMM: out = act(A @ Wt + bias) ----------------------
// MODE 0: A=g_qkv (K=512), out=g_h1, exact GELU.  MODE 1: A=g_h1 (K=256), out=d_out.
template <int MODE>
__global__ __launch_bounds__(256) void k_mlp(const float* __restrict__ Bw,
                                             const float* __restrict__ bias,
                                             float* __restrict__ out_ext) {
    constexpr int K = MODE ? 256 : 512;
    const float* A = MODE ? g_h1 : g_qkv;
    float* out = MODE ? out_ext : g_h1;

    __shared__ float As[64][36];     // [m][k]
    __shared__ float Bs[32][68];     // [k][o]
    const int tid = threadIdx.x;
    const int tx = tid & 15, ty = tid >> 4;
    const int otile = blockIdx.x * 64;
    const int m0 = blockIdx.y * 64;
    const int mA  = tid >> 2;
    const int kq4 = (tid & 3) * 4;
    const int oB  = tid >> 2;
    float acc[4][4] = {};

    #pragma unroll 2
    for (int kk0 = 0; kk0 < K; kk0 += 32) {
        const float* asrc = A + (size_t)(m0 + mA) * K + kk0 + kq4;
        const float4 a0 = *(const float4*)(asrc);
        const float4 a1 = *(const float4*)(asrc + 16);
        const float* wsrc = Bw + (size_t)(otile + oB) * K + kk0 + kq4;
        const float4 w0 = *(const float4*)(wsrc);
        const float4 w1 = *(const float4*)(wsrc + 16);

        __syncthreads();
        *(float4*)&As[mA][kq4]      = a0;
        *(float4*)&As[mA][kq4 + 16] = a1;
        Bs[kq4 + 0][oB] = w0.x;  Bs[kq4 + 1][oB] = w0.y;
        Bs[kq4 + 2][oB] = w0.z;  Bs[kq4 + 3][oB] = w0.w;
        Bs[kq4 + 16][oB] = w1.x; Bs[kq4 + 17][oB] = w1.y;
        Bs[kq4 + 18][oB] = w1.z; Bs[kq4 + 19][oB] = w1.w;
        __syncthreads();

        #pragma unroll
        for (int k = 0; k < 32; k++) {
            const float4 bv = *(const float4*)&Bs[k][tx * 4];
            float av[4];
            #pragma unroll
            for (int i = 0; i < 4; i++) av[i] = As[ty * 4 + i][k];
            #pragma unroll
            for (int i = 0; i < 4; i++) {
                acc[i][0] += av[i] * bv.x;
                acc[i][1] += av[i] * bv.y;
                acc[i][2] += av[i] * bv.z;
                acc[i][3] += av[i] * bv.w;
            }
        }
    }

    const float4 bb = *(const float4*)(bias + otile + tx * 4);
    #pragma unroll
    for (int i = 0; i < 4; i++) {
        float v[4] = {acc[i][0] + bb.x, acc[i][1] + bb.y, acc[i][2] + bb.z, acc[i][3] + bb.w};
        if (MODE == 0) {
            #pragma unroll
            for (int j = 0; j < 4; j++)
                v[j] = 0.5f * v[j] * (1.0f + erff(v[j] * 0.70710678118654752f));
        }
        const int m = m0 + ty * 4 + i;
        *(float4*)(out + (size_t)m * CC + otile + tx * 4) =
            make_float4(v[0], v[1], v[2], v[3]);
    }
}

// ------------------------------------------------------------------------------
extern "C" void kernel_launch(void* const* d_in, const int* in_sizes, int n_in,
                              void* d_out, int out_size) {
    const float* x      = (const float*)d_in[0];
    const float* conv_w = (const float*)d_in[1];
    const float* conv_b = (const float*)d_in[2];
    const float* Wq     = (const float*)d_in[3];
    const float* Wk     = (const float*)d_in[4];
    const float* Wv     = (const float*)d_in[5];
    const float* W1     = (const float*)d_in[6];
    const float* b1     = (const float*)d_in[7];
    const float* W2     = (const float*)d_in[8];
    const float* b2     = (const float*)d_in[9];
    float* out = (float*)d_out;

    cudaFuncSetAttribute(k_kv, cudaFuncAttributeMaxDynamicSharedMemorySize, 87040);

    k_wrearrange<<<(KCONV * INNER + 255) / 256, 256>>>(conv_w);
    k_init<<<(BB * HEADS * KRR * DHH) / 256, 256>>>();
    k_conv<<<dim3(INNER / 64, (BB * NN) / 64), 256>>>(x, conv_b);
    k_kv<<<dim3(NN / 256, BB * HEADS), 256, 87040>>>(Wk, Wv);
    k_kvnorm<<<(BB * HEADS * KRR * DHH) / 256, 256>>>();
    k_qkv<<<dim3(NN / 64, BB * HEADS), 256>>>(Wq);
    k_mlp<0><<<dim3(CC / 64, (BB * NN) / 64), 256>>>(W1, b1, nullptr);
    k_mlp<1><<<dim3(CC / 64, (BB * NN) / 64), 256>>>(W2, b2, out);
}

// round 3
// speedup vs baseline: 1.5557x; 1.5523x over previous
#include <cuda_runtime.h>
#include <math.h>

#define BB 8
#define CC 256
#define NN 16384
#define HEADS 8
#define INNER 512
#define KCONV 2304
#define KRR 64
#define DHH 64

__device__ float g_wcat[(size_t)INNER * KCONV];
__device__ float g_xc[(size_t)BB * NN * INNER];
__device__ float g_colsum[BB * HEADS * KRR];
__device__ float g_kv[BB * HEADS * KRR * DHH];
__device__ float g_qkv[(size_t)BB * NN * INNER];
__device__ float g_h1[(size_t)BB * NN * CC];

__device__ __forceinline__ unsigned f2tf(float f) {
    unsigned u; asm("cvt.rna.tf32.f32 %0, %1;" : "=r"(u) : "f"(f)); return u;
}
__device__ __forceinline__ float f2tf_f(float f) { return __uint_as_float(f2tf(f)); }
__device__ __forceinline__ void split_tf(float f, float& hi, float& lo) {
    hi = __uint_as_float(f2tf(f)); lo = __uint_as_float(f2tf(f - hi));
}
__device__ __forceinline__ void mma_tf32(float c[4], const unsigned a[4], const unsigned b[2]) {
    asm volatile("mma.sync.aligned.m16n8k8.row.col.f32.tf32.tf32.f32 "
        "{%0,%1,%2,%3}, {%4,%5,%6,%7}, {%8,%9}, {%0,%1,%2,%3};"
        : "+f"(c[0]), "+f"(c[1]), "+f"(c[2]), "+f"(c[3])
        : "r"(a[0]), "r"(a[1]), "r"(a[2]), "r"(a[3]), "r"(b[0]), "r"(b[1]));
}
template <int STR>
__device__ __forceinline__ void lda_row(unsigned a[4], const float* S, int r, int kc) {
    a[0] = __float_as_uint(S[r * STR + kc]);
    a[1] = __float_as_uint(S[(r + 8) * STR + kc]);
    a[2] = __float_as_uint(S[r * STR + kc + 4]);
    a[3] = __float_as_uint(S[(r + 8) * STR + kc + 4]);
}
template <int STR>
__device__ __forceinline__ void ldb_row(unsigned b[2], const float* S, int n, int kc) {
    b[0] = __float_as_uint(S[n * STR + kc]);
    b[1] = __float_as_uint(S[n * STR + kc + 4]);
}

__global__ void k_wprep(const float* __restrict__ conv_w) {
    int t = blockIdx.x * 256 + threadIdx.x;
    if (t >= INNER * KCONV) return;
    int o = t / KCONV, k = t - o * KCONV;
    int c = k & 255, g = k >> 8;
    g_wcat[t] = f2tf_f(conv_w[(size_t)(o * CC + c) * 9 + g]);
}
__global__ void k_init() {
    int i = blockIdx.x * 256 + threadIdx.x;
    g_kv[i] = 0.f;
    if (i < BB * HEADS * KRR) g_colsum[i] = 0.f;
}

// ---------------- conv: implicit-GEMM tf32 mma, 128x128x32 tiles --------------
__global__ __launch_bounds__(256) void k_conv(const float* __restrict__ x,
                                              const float* __restrict__ conv_b) {
    __shared__ float As[128 * 36];
    __shared__ float Bs[128 * 36];
    const int tid = threadIdx.x, lane = tid & 31, wid = tid >> 5;
    const int wm = wid & 3, wn = wid >> 2;
    const int grp = lane >> 2, tig = lane & 3;
    const int otile = blockIdx.x * 128, mtile = blockIdx.y * 128;
    const int b = mtile >> 14;
    const int lrow = tid >> 1, lk = (tid & 1) * 16;
    const int prow = (mtile & (NN - 1)) + lrow;
    const int py = prow >> 7, px = prow & 127;

    float acc[2][8][4] = {};
    float4 af[4], bf[4];
    {
        const int yy = py - 1, xx = px - 1;
        const bool valid = ((unsigned)yy < 128u) && ((unsigned)xx < 128u);
        const float* src = x + (((size_t)b << 14) + (yy << 7) + xx) * CC + lk;
        #pragma unroll
        for (int j = 0; j < 4; j++)
            af[j] = valid ? *(const float4*)(src + j * 4) : make_float4(0.f,0.f,0.f,0.f);
        const float* wsrc = g_wcat + (size_t)(otile + lrow) * KCONV + lk;
        #pragma unroll
        for (int j = 0; j < 4; j++) bf[j] = *(const float4*)(wsrc + j * 4);
    }
    for (int s = 0; s < 72; s++) {
        __syncthreads();
        #pragma unroll
        for (int j = 0; j < 4; j++) {
            float4 v = af[j];
            *(float4*)&As[lrow * 36 + lk + j * 4] =
                make_float4(f2tf_f(v.x), f2tf_f(v.y), f2tf_f(v.z), f2tf_f(v.w));
            *(float4*)&Bs[lrow * 36 + lk + j * 4] = bf[j];
        }
        __syncthreads();
        if (s + 1 < 72) {
            const int s1 = s + 1, g = s1 >> 3;
            const int dy = g / 3 - 1, dx = g % 3 - 1;
            const int cb = ((s1 & 7) << 5) + lk;
            const int yy = py + dy, xx = px + dx;
            const bool valid = ((unsigned)yy < 128u) && ((unsigned)xx < 128u);
            const float* src = x + (((size_t)b << 14) + (yy << 7) + xx) * CC + cb;
            #pragma unroll
            for (int j = 0; j < 4; j++)
                af[j] = valid ? *(const float4*)(src + j * 4) : make_float4(0.f,0.f,0.f,0.f);
            const float* wsrc = g_wcat + (size_t)(otile + lrow) * KCONV + (s1 << 5) + lk;
            #pragma unroll
            for (int j = 0; j < 4; j++) bf[j] = *(const float4*)(wsrc + j * 4);
        }
        #pragma unroll
        for (int ks = 0; ks < 4; ks++) {
            const int k0 = ks * 8 + tig;
            unsigned a[2][4], bb[2];
            #pragma unroll
            for (int mt = 0; mt < 2; mt++) lda_row<36>(a[mt], As, wm * 32 + mt * 16 + grp, k0);
            #pragma unroll
            for (int nt = 0; nt < 8; nt++) {
                ldb_row<36>(bb, Bs, wn * 64 + nt * 8 + grp, k0);
                mma_tf32(acc[0][nt], a[0], bb);
                mma_tf32(acc[1][nt], a[1], bb);
            }
        }
    }
    #pragma unroll
    for (int mt = 0; mt < 2; mt++)
        #pragma unroll
        for (int nt = 0; nt < 8; nt++) {
            const int r = wm * 32 + mt * 16 + grp;
            const int c = wn * 64 + nt * 8 + tig * 2;
            const float b0 = conv_b[otile + c], b1 = conv_b[otile + c + 1];
            *(float2*)(g_xc + (size_t)(mtile + r) * INNER + otile + c) =
                make_float2(acc[mt][nt][0] + b0, acc[mt][nt][1] + b1);
            *(float2*)(g_xc + (size_t)(mtile + r + 8) * INNER + otile + c) =
                make_float2(acc[mt][nt][2] + b0, acc[mt][nt][3] + b1);
        }
}

// ---------------- MLP: tf32 mma with hi/lo split (3-term) ---------------------
template <int MODE>
__global__ __launch_bounds__(256) void k_mlp(const float* __restrict__ Bw,
                                             const float* __restrict__ bias,
                                             float* __restrict__ out_ext) {
    constexpr int K = MODE ? CC : INNER;
    constexpr int NSTG = K / 32;
    const float* A = MODE ? g_h1 : g_qkv;
    float* out = MODE ? out_ext : g_h1;

    extern __shared__ float sm[];
    float *Ah = sm, *Al = sm + 4608, *Bh = sm + 9216, *Bl = sm + 13824;
    const int tid = threadIdx.x, lane = tid & 31, wid = tid >> 5;
    const int wm = wid & 3, wn = wid >> 2;
    const int grp = lane >> 2, tig = lane & 3;
    const int otile = blockIdx.x * 128, m0 = blockIdx.y * 128;
    const int lrow = tid >> 1, lk = (tid & 1) * 16;

    float acc[2][8][4] = {};
    float4 af[4], bf[4];
    {
        const float* asrc = A + (size_t)(m0 + lrow) * K + lk;
        const float* wsrc = Bw + (size_t)(otile + lrow) * K + lk;
        #pragma unroll
        for (int j = 0; j < 4; j++) { af[j] = *(const float4*)(asrc + j * 4);
                                      bf[j] = *(const float4*)(wsrc + j * 4); }
    }
    for (int s = 0; s < NSTG; s++) {
        __syncthreads();
        #pragma unroll
        for (int j = 0; j < 4; j++) {
            int o = lrow * 36 + lk + j * 4;
            split_tf(af[j].x, Ah[o],   Al[o]);   split_tf(af[j].y, Ah[o+1], Al[o+1]);
            split_tf(af[j].z, Ah[o+2], Al[o+2]); split_tf(af[j].w, Ah[o+3], Al[o+3]);
            split_tf(bf[j].x, Bh[o],   Bl[o]);   split_tf(bf[j].y, Bh[o+1], Bl[o+1]);
            split_tf(bf[j].z, Bh[o+2], Bl[o+2]); split_tf(bf[j].w, Bh[o+3], Bl[o+3]);
        }
        __syncthreads();
        if (s + 1 < NSTG) {
            const int kk = (s + 1) * 32 + lk;
            const float* asrc = A + (size_t)(m0 + lrow) * K + kk;
            const float* wsrc = Bw + (size_t)(otile + lrow) * K + kk;
            #pragma unroll
            for (int j = 0; j < 4; j++) { af[j] = *(const float4*)(asrc + j * 4);
                                          bf[j] = *(const float4*)(wsrc + j * 4); }
        }
        #pragma unroll
        for (int ks = 0; ks < 4; ks++) {
            const int k0 = ks * 8 + tig;
            unsigned ah[2][4], al[2][4], bh2[2], bl2[2];
            #pragma unroll
            for (int mt = 0; mt < 2; mt++) {
                lda_row<36>(ah[mt], Ah, wm * 32 + mt * 16 + grp, k0);
                lda_row<36>(al[mt], Al, wm * 32 + mt * 16 + grp, k0);
            }
            #pragma unroll
            for (int nt = 0; nt < 8; nt++) {
                ldb_row<36>(bh2, Bh, wn * 64 + nt * 8 + grp, k0);
                ldb_row<36>(bl2, Bl, wn * 64 + nt * 8 + grp, k0);
                #pragma unroll
                for (int mt = 0; mt < 2; mt++) {
                    mma_tf32(acc[mt][nt], ah[mt], bh2);
                    mma_tf32(acc[mt][nt], ah[mt], bl2);
                    mma_tf32(acc[mt][nt], al[mt], bh2);
                }
            }
        }
    }
    #pragma unroll
    for (int mt = 0; mt < 2; mt++)
        #pragma unroll
        for (int nt = 0; nt < 8; nt++) {
            const int r = wm * 32 + mt * 16 + grp;
            const int c = wn * 64 + nt * 8 + tig * 2;
            const float b0 = bias[otile + c], b1 = bias[otile + c + 1];
            float v[4] = {acc[mt][nt][0] + b0, acc[mt][nt][1] + b1,
                          acc[mt][nt][2] + b0, acc[mt][nt][3] + b1};
            if (MODE == 0) {
                #pragma unroll
                for (int j = 0; j < 4; j++)
                    v[j] = 0.5f * v[j] * (1.0f + erff(v[j] * 0.70710678118654752f));
            }
            *(float2*)(out + (size_t)(m0 + r) * CC + otile + c)     = make_float2(v[0], v[1]);
            *(float2*)(out + (size_t)(m0 + r + 8) * CC + otile + c) = make_float2(v[2], v[3]);
        }
}

// ---------------- attention (fp32 SIMT, unchanged from passing baseline) ------
__global__ __launch_bounds__(256) void k_kv(const float* __restrict__ Wk,
                                            const float* __restrict__ Wv) {
    extern __shared__ float sm[];
    float* Xs = sm; float* Wks = sm + 4352; float* Wvs = sm + 8704;
    float* Ks = sm + 13056; float* Vs = sm + 17408;
    const int tid = threadIdx.x;
    const int bh = blockIdx.y, b = bh >> 3, h = bh & 7;
    const int r = tid >> 2, c0 = (tid & 3) * 16;
    #pragma unroll
    for (int i = 0; i < 4; i++) {
        *(float4*)&Wks[r * 68 + c0 + i * 4] = *(const float4*)&Wk[r * 64 + c0 + i * 4];
        *(float4*)&Wvs[r * 68 + c0 + i * 4] = *(const float4*)&Wv[r * 64 + c0 + i * 4];
    }
    float kvacc[16] = {}; float csum = 0.f;
    for (int sub = 0; sub < 4; sub++) {
        const int n0 = blockIdx.x * 256 + sub * 64;
        const float* xsrc = g_xc + ((size_t)(b * NN + n0 + r)) * INNER + h * 64 + c0;
        float4 xl[4];
        #pragma unroll
        for (int i = 0; i < 4; i++) xl[i] = *(const float4*)(xsrc + i * 4);
        __syncthreads();
        #pragma unroll
        for (int i = 0; i < 4; i++) *(float4*)&Xs[r * 68 + c0 + i * 4] = xl[i];
        __syncthreads();
        float kreg[16] = {}, vreg[16] = {};
        for (int d = 0; d < 64; d += 4) {
            const float4 xv = *(const float4*)&Xs[r * 68 + d];
            #pragma unroll
            for (int j = 0; j < 16; j++) {
                const float4 wk = *(const float4*)&Wks[(c0 + j) * 68 + d];
                kreg[j] += xv.x * wk.x + xv.y * wk.y + xv.z * wk.z + xv.w * wk.w;
            }
            #pragma unroll
            for (int j = 0; j < 16; j++) {
                const float4 wv = *(const float4*)&Wvs[(c0 + j) * 68 + d];
                vreg[j] += xv.x * wv.x + xv.y * wv.y + xv.z * wv.z + xv.w * wv.w;
            }
        }
        #pragma unroll
        for (int j = 0; j < 16; j++) {
            Ks[r * 68 + c0 + j] = __expf(kreg[j]);
            Vs[r * 68 + c0 + j] = vreg[j];
        }
        __syncthreads();
        for (int row = 0; row < 64; row++) {
            const float kk = Ks[row * 68 + r];
            csum += kk;
            #pragma unroll
            for (int jj = 0; jj < 4; jj++) {
                const float4 vv = *(const float4*)&Vs[row * 68 + c0 + jj * 4];
                kvacc[jj*4+0] += kk * vv.x; kvacc[jj*4+1] += kk * vv.y;
                kvacc[jj*4+2] += kk * vv.z; kvacc[jj*4+3] += kk * vv.w;
            }
        }
    }
    float* kvp = g_kv + (size_t)bh * KRR * DHH + r * DHH + c0;
    #pragma unroll
    for (int j = 0; j < 16; j++) atomicAdd(kvp + j, kvacc[j]);
    if ((tid & 3) == 0) atomicAdd(g_colsum + bh * KRR + r, csum);
}

__global__ void k_kvnorm() {
    int i = blockIdx.x * 256 + threadIdx.x;
    g_kv[i] = g_kv[i] / g_colsum[i >> 6];
}

__global__ __launch_bounds__(256) void k_qkv(const float* __restrict__ Wq) {
    __shared__ float Xs[64 * 68];
    __shared__ float Ws[64 * 68];
    const int tid = threadIdx.x;
    const int bh = blockIdx.y, b = bh >> 3, h = bh & 7;
    const int n0 = blockIdx.x * 64;
    const int r = tid >> 2, c0 = (tid & 3) * 16;
    #pragma unroll
    for (int i = 0; i < 4; i++)
        *(float4*)&Ws[r * 68 + c0 + i * 4] = *(const float4*)&Wq[r * 64 + c0 + i * 4];
    const float* xsrc = g_xc + ((size_t)(b * NN + n0 + r)) * INNER + h * 64 + c0;
    #pragma unroll
    for (int i = 0; i < 4; i++)
        *(float4*)&Xs[r * 68 + c0 + i * 4] = *(const float4*)(xsrc + i * 4);
    __syncthreads();
    float qv[16] = {};
    for (int d = 0; d < 64; d += 4) {
        const float4 xv = *(const float4*)&Xs[r * 68 + d];
        #pragma unroll
        for (int j = 0; j < 16; j++) {
            const float4 w = *(const float4*)&Ws[(c0 + j) * 68 + d];
            qv[j] += xv.x * w.x + xv.y * w.y + xv.z * w.z + xv.w * w.w;
        }
    }
    float ssum = 0.f;
    #pragma unroll
    for (int j = 0; j < 16; j++) { qv[j] = __expf(qv[j]); ssum += qv[j]; }
    ssum += __shfl_xor_sync(0xffffffffu, ssum, 1);
    ssum += __shfl_xor_sync(0xffffffffu, ssum, 2);
    const float inv = 1.f / ssum;
    __syncthreads();
    #pragma unroll
    for (int j = 0; j < 16; j++) Xs[r * 68 + c0 + j] = qv[j] * inv;
    const float* kvsrc = g_kv + (size_t)bh * KRR * DHH;
    #pragma unroll
    for (int i = 0; i < 4; i++)
        *(float4*)&Ws[r * 68 + c0 + i * 4] = *(const float4*)(kvsrc + r * 64 + c0 + i * 4);
    __syncthreads();
    float acc2[16] = {};
    for (int d = 0; d < 64; d++) {
        const float q = Xs[r * 68 + d];
        #pragma unroll
        for (int jj = 0; jj < 4; jj++) {
            const float4 kvv = *(const float4*)&Ws[d * 68 + c0 + jj * 4];
            acc2[jj*4+0] += q * kvv.x; acc2[jj*4+1] += q * kvv.y;
            acc2[jj*4+2] += q * kvv.z; acc2[jj*4+3] += q * kvv.w;
        }
    }
    float* dst = g_qkv + ((size_t)(b * NN + n0 + r)) * INNER + h * 64 + c0;
    #pragma unroll
    for (int jj = 0; jj < 4; jj++)
        *(float4*)(dst + jj * 4) = make_float4(acc2[jj*4+0], acc2[jj*4+1],
                                               acc2[jj*4+2], acc2[jj*4+3]);
}

// ------------------------------------------------------------------------------
extern "C" void kernel_launch(void* const* d_in, const int* in_sizes, int n_in,
                              void* d_out, int out_size) {
    const float* x      = (const float*)d_in[0];
    const float* conv_w = (const float*)d_in[1];
    const float* conv_b = (const float*)d_in[2];
    const float* Wq     = (const float*)d_in[3];
    const float* Wk     = (const float*)d_in[4];
    const float* Wv     = (const float*)d_in[5];
    const float* W1     = (const float*)d_in[6];
    const float* b1     = (const float*)d_in[7];
    const float* W2     = (const float*)d_in[8];
    const float* b2     = (const float*)d_in[9];
    float* out = (float*)d_out;

    cudaFuncSetAttribute(k_kv, cudaFuncAttributeMaxDynamicSharedMemorySize, 87040);
    cudaFuncSetAttribute(k_mlp<0>, cudaFuncAttributeMaxDynamicSharedMemorySize, 73728);
    cudaFuncSetAttribute(k_mlp<1>, cudaFuncAttributeMaxDynamicSharedMemorySize, 73728);

    k_wprep<<<(INNER * KCONV + 255) / 256, 256>>>(conv_w);
    k_init<<<(BB * HEADS * KRR * DHH) / 256, 256>>>();
    k_conv<<<dim3(INNER / 128, (BB * NN) / 128), 256>>>(x, conv_b);
    k_kv<<<dim3(NN / 256, BB * HEADS), 256, 87040>>>(Wk, Wv);
    k_kvnorm<<<(BB * HEADS * KRR * DHH) / 256, 256>>>();
    k_qkv<<<dim3(NN / 64, BB * HEADS), 256>>>(Wq);
    k_mlp<0><<<dim3(CC / 128, (BB * NN) / 128), 256, 73728>>>(W1, b1, nullptr);
    k_mlp<1><<<dim3(CC / 128, (BB * NN) / 128), 256, 73728>>>(W2, b2, out);
}

// round 4
// speedup vs baseline: 1.6131x; 1.0369x over previous
#include <cuda_runtime.h>
#include <math.h>

#define BB 8
#define CC 256
#define NN 16384
#define HEADS 8
#define INNER 512
#define KCONV 2304
#define KRR 64
#define DHH 64

__device__ float g_wcat[(size_t)INNER * KCONV];
__device__ float g_xtf[(size_t)BB * NN * CC];
__device__ float g_w1tf[CC * INNER];
__device__ float g_w2tf[CC * CC];
__device__ float g_xc[(size_t)BB * NN * INNER];
__device__ float g_colsum[BB * HEADS * KRR];
__device__ float g_kv[BB * HEADS * KRR * DHH];
__device__ float g_qkv[(size_t)BB * NN * INNER];
__device__ float g_h1[(size_t)BB * NN * CC];

__device__ __forceinline__ unsigned f2tf(float f) {
    unsigned u; asm("cvt.rna.tf32.f32 %0, %1;" : "=r"(u) : "f"(f)); return u;
}
__device__ __forceinline__ float f2tf_f(float f) { return __uint_as_float(f2tf(f)); }
__device__ __forceinline__ void mma_tf32(float c[4], const unsigned a[4], const unsigned b[2]) {
    asm volatile("mma.sync.aligned.m16n8k8.row.col.f32.tf32.tf32.f32 "
        "{%0,%1,%2,%3}, {%4,%5,%6,%7}, {%8,%9}, {%0,%1,%2,%3};"
        : "+f"(c[0]), "+f"(c[1]), "+f"(c[2]), "+f"(c[3])
        : "r"(a[0]), "r"(a[1]), "r"(a[2]), "r"(a[3]), "r"(b[0]), "r"(b[1]));
}
__device__ __forceinline__ void lda_row(unsigned a[4], const float* S, int r, int kc) {
    a[0] = __float_as_uint(S[r * 36 + kc]);
    a[1] = __float_as_uint(S[(r + 8) * 36 + kc]);
    a[2] = __float_as_uint(S[r * 36 + kc + 4]);
    a[3] = __float_as_uint(S[(r + 8) * 36 + kc + 4]);
}
__device__ __forceinline__ void ldb_row(unsigned b[2], const float* S, int n, int kc) {
    b[0] = __float_as_uint(S[n * 36 + kc]);
    b[1] = __float_as_uint(S[n * 36 + kc + 4]);
}
__device__ __forceinline__ void cp16(float* dst, const float* src, bool valid) {
    unsigned saddr = (unsigned)__cvta_generic_to_shared(dst);
    int sz = valid ? 16 : 0;
    asm volatile("cp.async.ca.shared.global [%0], [%1], 16, %2;"
                 :: "r"(saddr), "l"(src), "r"(sz));
}
__device__ __forceinline__ void cp_commit() { asm volatile("cp.async.commit_group;"); }

// ---------------- prep kernels -------------------------------------------------
__global__ void k_wprep(const float* __restrict__ conv_w) {
    int t = blockIdx.x * 256 + threadIdx.x;
    if (t >= INNER * KCONV) return;
    int o = t / KCONV, k = t - o * KCONV;
    g_wcat[t] = f2tf_f(conv_w[(size_t)(o * CC + (k & 255)) * 9 + (k >> 8)]);
}
__global__ void k_xprep(const float* __restrict__ x) {
    int t = blockIdx.x * 256 + threadIdx.x;            // over 8388608 float4s
    float4 v = ((const float4*)x)[t];
    ((float4*)g_xtf)[t] = make_float4(f2tf_f(v.x), f2tf_f(v.y), f2tf_f(v.z), f2tf_f(v.w));
}
__global__ void k_wmlp(const float* __restrict__ W1, const float* __restrict__ W2) {
    int t = blockIdx.x * 256 + threadIdx.x;            // 131072 threads
    g_w1tf[t] = f2tf_f(W1[t]);
    if (t < CC * CC) g_w2tf[t] = f2tf_f(W2[t]);
}
__global__ void k_init() {
    int i = blockIdx.x * 256 + threadIdx.x;
    g_kv[i] = 0.f;
    if (i < BB * HEADS * KRR) g_colsum[i] = 0.f;
}

// ---------------- conv: implicit-GEMM tf32, cp.async 2-stage pipeline ----------
__global__ __launch_bounds__(256) void k_conv(const float* __restrict__ conv_b) {
    extern __shared__ float sm[];                      // A0 A1 B0 B1, 4608 floats each
    const int tid = threadIdx.x, lane = tid & 31, wid = tid >> 5;
    const int wm = wid & 3, wn = wid >> 2;
    const int grp = lane >> 2, tig = lane & 3;
    const int otile = blockIdx.x * 128, mtile = blockIdx.y * 128;
    const int b = mtile >> 14;
    const int lrow = tid >> 1, lk = (tid & 1) * 16;
    const int prow = (mtile & (NN - 1)) + lrow;
    const int py = prow >> 7, px = prow & 127;
    const float* xb = g_xtf + ((size_t)b << 14) * CC;
    const float* wrow = g_wcat + (size_t)(otile + lrow) * KCONV + lk;

    float acc[2][8][4] = {};

    auto issue = [&](int s) {
        const int buf = s & 1;
        const int g = s >> 3;
        const int dy = g / 3 - 1, dx = g % 3 - 1;
        const int yy = py + dy, xx = px + dx;
        const bool valid = ((unsigned)yy < 128u) && ((unsigned)xx < 128u);
        const float* asrc = xb + (size_t)((yy << 7) + xx) * CC + ((s & 7) << 5) + lk;
        float* adst = sm + buf * 4608 + lrow * 36 + lk;
        const float* bsrc = wrow + (s << 5);
        float* bdst = sm + 9216 + buf * 4608 + lrow * 36 + lk;
        #pragma unroll
        for (int j = 0; j < 4; j++) {
            cp16(adst + j * 4, asrc + j * 4, valid);
            cp16(bdst + j * 4, bsrc + j * 4, true);
        }
        cp_commit();
    };

    issue(0);
    for (int s = 0; s < 72; s++) {
        if (s + 1 < 72) {
            issue(s + 1);
            asm volatile("cp.async.wait_group 1;");
        } else {
            asm volatile("cp.async.wait_group 0;");
        }
        __syncthreads();
        const float* A = sm + (s & 1) * 4608;
        const float* Bm = sm + 9216 + (s & 1) * 4608;
        #pragma unroll
        for (int ks = 0; ks < 4; ks++) {
            const int k0 = ks * 8 + tig;
            unsigned a[2][4], bb[2];
            lda_row(a[0], A, wm * 32 + grp, k0);
            lda_row(a[1], A, wm * 32 + 16 + grp, k0);
            #pragma unroll
            for (int nt = 0; nt < 8; nt++) {
                ldb_row(bb, Bm, wn * 64 + nt * 8 + grp, k0);
                mma_tf32(acc[0][nt], a[0], bb);
                mma_tf32(acc[1][nt], a[1], bb);
            }
        }
        __syncthreads();
    }
    #pragma unroll
    for (int mt = 0; mt < 2; mt++)
        #pragma unroll
        for (int nt = 0; nt < 8; nt++) {
            const int r = wm * 32 + mt * 16 + grp;
            const int c = wn * 64 + nt * 8 + tig * 2;
            const float b0 = conv_b[otile + c], b1 = conv_b[otile + c + 1];
            *(float2*)(g_xc + (size_t)(mtile + r) * INNER + otile + c) =
                make_float2(acc[mt][nt][0] + b0, acc[mt][nt][1] + b1);
            *(float2*)(g_xc + (size_t)(mtile + r + 8) * INNER + otile + c) =
                make_float2(acc[mt][nt][2] + b0, acc[mt][nt][3] + b1);
        }
}

// ---------------- MLP: single tf32, cp.async pipeline --------------------------
template <int MODE>
__global__ __launch_bounds__(256) void k_mlp(const float* __restrict__ bias,
                                             float* __restrict__ out_ext) {
    constexpr int K = MODE ? CC : INNER;
    constexpr int NS = K / 32;
    const float* A_g = MODE ? g_h1 : g_qkv;
    const float* B_g = MODE ? g_w2tf : g_w1tf;
    float* out = MODE ? out_ext : g_h1;

    extern __shared__ float sm[];
    const int tid = threadIdx.x, lane = tid & 31, wid = tid >> 5;
    const int wm = wid & 3, wn = wid >> 2;
    const int grp = lane >> 2, tig = lane & 3;
    const int otile = blockIdx.x * 128, m0 = blockIdx.y * 128;
    const int lrow = tid >> 1, lk = (tid & 1) * 16;
    const float* arow = A_g + (size_t)(m0 + lrow) * K + lk;
    const float* brow = B_g + (size_t)(otile + lrow) * K + lk;

    float acc[2][8][4] = {};

    auto issue = [&](int s) {
        const int buf = s & 1;
        float* adst = sm + buf * 4608 + lrow * 36 + lk;
        float* bdst = sm + 9216 + buf * 4608 + lrow * 36 + lk;
        #pragma unroll
        for (int j = 0; j < 4; j++) {
            cp16(adst + j * 4, arow + (s << 5) + j * 4, true);
            cp16(bdst + j * 4, brow + (s << 5) + j * 4, true);
        }
        cp_commit();
    };

    issue(0);
    for (int s = 0; s < NS; s++) {
        if (s + 1 < NS) {
            issue(s + 1);
            asm volatile("cp.async.wait_group 1;");
        } else {
            asm volatile("cp.async.wait_group 0;");
        }
        __syncthreads();
        const float* A = sm + (s & 1) * 4608;
        const float* Bm = sm + 9216 + (s & 1) * 4608;
        #pragma unroll
        for (int ks = 0; ks < 4; ks++) {
            const int k0 = ks * 8 + tig;
            unsigned a[2][4], bb[2];
            lda_row(a[0], A, wm * 32 + grp, k0);
            lda_row(a[1], A, wm * 32 + 16 + grp, k0);
            #pragma unroll
            for (int nt = 0; nt < 8; nt++) {
                ldb_row(bb, Bm, wn * 64 + nt * 8 + grp, k0);
                mma_tf32(acc[0][nt], a[0], bb);
                mma_tf32(acc[1][nt], a[1], bb);
            }
        }
        __syncthreads();
    }
    #pragma unroll
    for (int mt = 0; mt < 2; mt++)
        #pragma unroll
        for (int nt = 0; nt < 8; nt++) {
            const int r = wm * 32 + mt * 16 + grp;
            const int c = wn * 64 + nt * 8 + tig * 2;
            const float b0 = bias[otile + c], b1 = bias[otile + c + 1];
            float v[4] = {acc[mt][nt][0] + b0, acc[mt][nt][1] + b1,
                          acc[mt][nt][2] + b0, acc[mt][nt][3] + b1};
            if (MODE == 0) {
                #pragma unroll
                for (int j = 0; j < 4; j++)
                    v[j] = f2tf_f(0.5f * v[j] * (1.0f + erff(v[j] * 0.70710678118654752f)));
            }
            *(float2*)(out + (size_t)(m0 + r) * CC + otile + c)     = make_float2(v[0], v[1]);
            *(float2*)(out + (size_t)(m0 + r + 8) * CC + otile + c) = make_float2(v[2], v[3]);
        }
}

// ---------------- attention (exact fp32 SIMT) ----------------------------------
__global__ __launch_bounds__(256) void k_kv(const float* __restrict__ Wk,
                                            const float* __restrict__ Wv) {
    extern __shared__ float sm[];
    float* Xs = sm; float* Wks = sm + 4352; float* Wvs = sm + 8704;
    float* Ks = sm + 13056; float* Vs = sm + 17408;
    const int tid = threadIdx.x;
    const int bh = blockIdx.y, b = bh >> 3, h = bh & 7;
    const int r = tid >> 2, c0 = (tid & 3) * 16;
    #pragma unroll
    for (int i = 0; i < 4; i++) {
        *(float4*)&Wks[r * 68 + c0 + i * 4] = *(const float4*)&Wk[r * 64 + c0 + i * 4];
        *(float4*)&Wvs[r * 68 + c0 + i * 4] = *(const float4*)&Wv[r * 64 + c0 + i * 4];
    }
    float kvacc[16] = {}; float csum = 0.f;
    for (int sub = 0; sub < 4; sub++) {
        const int n0 = blockIdx.x * 256 + sub * 64;
        const float* xsrc = g_xc + ((size_t)(b * NN + n0 + r)) * INNER + h * 64 + c0;
        float4 xl[4];
        #pragma unroll
        for (int i = 0; i < 4; i++) xl[i] = *(const float4*)(xsrc + i * 4);
        __syncthreads();
        #pragma unroll
        for (int i = 0; i < 4; i++) *(float4*)&Xs[r * 68 + c0 + i * 4] = xl[i];
        __syncthreads();
        float kreg[16] = {}, vreg[16] = {};
        for (int d = 0; d < 64; d += 4) {
            const float4 xv = *(const float4*)&Xs[r * 68 + d];
            #pragma unroll
            for (int j = 0; j < 16; j++) {
                const float4 wk = *(const float4*)&Wks[(c0 + j) * 68 + d];
                kreg[j] += xv.x * wk.x + xv.y * wk.y + xv.z * wk.z + xv.w * wk.w;
            }
            #pragma unroll
            for (int j = 0; j < 16; j++) {
                const float4 wv = *(const float4*)&Wvs[(c0 + j) * 68 + d];
                vreg[j] += xv.x * wv.x + xv.y * wv.y + xv.z * wv.z + xv.w * wv.w;
            }
        }
        #pragma unroll
        for (int j = 0; j < 16; j++) {
            Ks[r * 68 + c0 + j] = __expf(kreg[j]);
            Vs[r * 68 + c0 + j] = vreg[j];
        }
        __syncthreads();
        for (int row = 0; row < 64; row++) {
            const float kk = Ks[row * 68 + r];
            csum += kk;
            #pragma unroll
            for (int jj = 0; jj < 4; jj++) {
                const float4 vv = *(const float4*)&Vs[row * 68 + c0 + jj * 4];
                kvacc[jj*4+0] += kk * vv.x; kvacc[jj*4+1] += kk * vv.y;
                kvacc[jj*4+2] += kk * vv.z; kvacc[jj*4+3] += kk * vv.w;
            }
        }
    }
    float* kvp = g_kv + (size_t)bh * KRR * DHH + r * DHH + c0;
    #pragma unroll
    for (int j = 0; j < 16; j++) atomicAdd(kvp + j, kvacc[j]);
    if ((tid & 3) == 0) atomicAdd(g_colsum + bh * KRR + r, csum);
}

__global__ void k_kvnorm() {
    int i = blockIdx.x * 256 + threadIdx.x;
    g_kv[i] = g_kv[i] / g_colsum[i >> 6];
}

__global__ __launch_bounds__(256) void k_qkv(const float* __restrict__ Wq) {
    __shared__ float Xs[64 * 68];
    __shared__ float Ws[64 * 68];
    const int tid = threadIdx.x;
    const int bh = blockIdx.y, b = bh >> 3, h = bh & 7;
    const int n0 = blockIdx.x * 64;
    const int r = tid >> 2, c0 = (tid & 3) * 16;
    #pragma unroll
    for (int i = 0; i < 4; i++)
        *(float4*)&Ws[r * 68 + c0 + i * 4] = *(const float4*)&Wq[r * 64 + c0 + i * 4];
    const float* xsrc = g_xc + ((size_t)(b * NN + n0 + r)) * INNER + h * 64 + c0;
    #pragma unroll
    for (int i = 0; i < 4; i++)
        *(float4*)&Xs[r * 68 + c0 + i * 4] = *(const float4*)(xsrc + i * 4);
    __syncthreads();
    float qv[16] = {};
    for (int d = 0; d < 64; d += 4) {
        const float4 xv = *(const float4*)&Xs[r * 68 + d];
        #pragma unroll
        for (int j = 0; j < 16; j++) {
            const float4 w = *(const float4*)&Ws[(c0 + j) * 68 + d];
            qv[j] += xv.x * w.x + xv.y * w.y + xv.z * w.z + xv.w * w.w;
        }
    }
    float ssum = 0.f;
    #pragma unroll
    for (int j = 0; j < 16; j++) { qv[j] = __expf(qv[j]); ssum += qv[j]; }
    ssum += __shfl_xor_sync(0xffffffffu, ssum, 1);
    ssum += __shfl_xor_sync(0xffffffffu, ssum, 2);
    const float inv = 1.f / ssum;
    __syncthreads();
    #pragma unroll
    for (int j = 0; j < 16; j++) Xs[r * 68 + c0 + j] = qv[j] * inv;
    const float* kvsrc = g_kv + (size_t)bh * KRR * DHH;
    #pragma unroll
    for (int i = 0; i < 4; i++)
        *(float4*)&Ws[r * 68 + c0 + i * 4] = *(const float4*)(kvsrc + r * 64 + c0 + i * 4);
    __syncthreads();
    float acc2[16] = {};
    for (int d = 0; d < 64; d++) {
        const float q = Xs[r * 68 + d];
        #pragma unroll
        for (int jj = 0; jj < 4; jj++) {
            const float4 kvv = *(const float4*)&Ws[d * 68 + c0 + jj * 4];
            acc2[jj*4+0] += q * kvv.x; acc2[jj*4+1] += q * kvv.y;
            acc2[jj*4+2] += q * kvv.z; acc2[jj*4+3] += q * kvv.w;
        }
    }
    float* dst = g_qkv + ((size_t)(b * NN + n0 + r)) * INNER + h * 64 + c0;
    #pragma unroll
    for (int jj = 0; jj < 4; jj++)
        *(float4*)(dst + jj * 4) = make_float4(f2tf_f(acc2[jj*4+0]), f2tf_f(acc2[jj*4+1]),
                                               f2tf_f(acc2[jj*4+2]), f2tf_f(acc2[jj*4+3]));
}

// ------------------------------------------------------------------------------
extern "C" void kernel_launch(void* const* d_in, const int* in_sizes, int n_in,
                              void* d_out, int out_size) {
    const float* x      = (const float*)d_in[0];
    const float* conv_w = (const float*)d_in[1];
    const float* conv_b = (const float*)d_in[2];
    const float* Wq     = (const float*)d_in[3];
    const float* Wk     = (const float*)d_in[4];
    const float* Wv     = (const float*)d_in[5];
    const float* W1     = (const float*)d_in[6];
    const float* b1     = (const float*)d_in[7];
    const float* W2     = (const float*)d_in[8];
    const float* b2     = (const float*)d_in[9];
    float* out = (float*)d_out;

    cudaFuncSetAttribute(k_conv, cudaFuncAttributeMaxDynamicSharedMemorySize, 73728);
    cudaFuncSetAttribute(k_mlp<0>, cudaFuncAttributeMaxDynamicSharedMemorySize, 73728);
    cudaFuncSetAttribute(k_mlp<1>, cudaFuncAttributeMaxDynamicSharedMemorySize, 73728);
    cudaFuncSetAttribute(k_kv, cudaFuncAttributeMaxDynamicSharedMemorySize, 87040);

    k_wprep<<<(INNER * KCONV + 255) / 256, 256>>>(conv_w);
    k_xprep<<<((BB * NN * CC) / 4 + 255) / 256, 256>>>(x);
    k_wmlp<<<(CC * INNER + 255) / 256, 256>>>(W1, W2);
    k_init<<<(BB * HEADS * KRR * DHH) / 256, 256>>>();
    k_conv<<<dim3(INNER / 128, (BB * NN) / 128), 256, 73728>>>(conv_b);
    k_kv<<<dim3(NN / 256, BB * HEADS), 256, 87040>>>(Wk, Wv);
    k_kvnorm<<<(BB * HEADS * KRR * DHH) / 256, 256>>>();
    k_qkv<<<dim3(NN / 64, BB * HEADS), 256>>>(Wq);
    k_mlp<0><<<dim3(CC / 128, (BB * NN) / 128), 256, 73728>>>(b1, nullptr);
    k_mlp<1><<<dim3(CC / 128, (BB * NN) / 128), 256, 73728>>>(b2, out);
}

// round 5
// speedup vs baseline: 3.6035x; 2.2339x over previous
#include <cuda_runtime.h>
#include <math.h>

#define BB 8
#define CC 256
#define NN 16384
#define HEADS 8
#define INNER 512
#define KCONV 2304
#define KRR 64
#define DHH 64

__device__ float g_wcat[(size_t)INNER * KCONV];
__device__ float g_xtf[(size_t)BB * NN * CC];
__device__ float g_w1tf[CC * INNER];
__device__ float g_w2tf[CC * CC];
__device__ float g_xc[(size_t)BB * NN * INNER];
__device__ float g_colsum[BB * HEADS * KRR];
__device__ float g_kv[BB * HEADS * KRR * DHH];
__device__ float g_qkv[(size_t)BB * NN * INNER];
__device__ float g_h1[(size_t)BB * NN * CC];

__device__ __forceinline__ unsigned f2tf(float f) {
    unsigned u; asm("cvt.rna.tf32.f32 %0, %1;" : "=r"(u) : "f"(f)); return u;
}
__device__ __forceinline__ float f2tf_f(float f) { return __uint_as_float(f2tf(f)); }
__device__ __forceinline__ void split_tf(float f, float& hi, float& lo) {
    hi = __uint_as_float(f2tf(f)); lo = __uint_as_float(f2tf(f - hi));
}
__device__ __forceinline__ void mma_tf32(float c[4], const unsigned a[4], const unsigned b[2]) {
    asm volatile("mma.sync.aligned.m16n8k8.row.col.f32.tf32.tf32.f32 "
        "{%0,%1,%2,%3}, {%4,%5,%6,%7}, {%8,%9}, {%0,%1,%2,%3};"
        : "+f"(c[0]), "+f"(c[1]), "+f"(c[2]), "+f"(c[3])
        : "r"(a[0]), "r"(a[1]), "r"(a[2]), "r"(a[3]), "r"(b[0]), "r"(b[1]));
}
template <int STR>
__device__ __forceinline__ void lda_row(unsigned a[4], const float* S, int r, int kc) {
    a[0] = __float_as_uint(S[r * STR + kc]);
    a[1] = __float_as_uint(S[(r + 8) * STR + kc]);
    a[2] = __float_as_uint(S[r * STR + kc + 4]);
    a[3] = __float_as_uint(S[(r + 8) * STR + kc + 4]);
}
template <int STR>
__device__ __forceinline__ void ldb_row(unsigned b[2], const float* S, int n, int kc) {
    b[0] = __float_as_uint(S[n * STR + kc]);
    b[1] = __float_as_uint(S[n * STR + kc + 4]);
}
__device__ __forceinline__ void cp16(float* dst, const float* src, bool valid) {
    unsigned saddr = (unsigned)__cvta_generic_to_shared(dst);
    int sz = valid ? 16 : 0;
    asm volatile("cp.async.ca.shared.global [%0], [%1], 16, %2;"
                 :: "r"(saddr), "l"(src), "r"(sz));
}
__device__ __forceinline__ void cp_commit() { asm volatile("cp.async.commit_group;"); }

// ---------------- prep ---------------------------------------------------------
__global__ void k_wprep(const float* __restrict__ conv_w) {
    int t = blockIdx.x * 256 + threadIdx.x;
    if (t >= INNER * KCONV) return;
    int o = t / KCONV, k = t - o * KCONV;
    g_wcat[t] = f2tf_f(conv_w[(size_t)(o * CC + (k & 255)) * 9 + (k >> 8)]);
}
__global__ void k_xprep(const float* __restrict__ x) {
    int t = blockIdx.x * 256 + threadIdx.x;
    float4 v = ((const float4*)x)[t];
    ((float4*)g_xtf)[t] = make_float4(f2tf_f(v.x), f2tf_f(v.y), f2tf_f(v.z), f2tf_f(v.w));
}
__global__ void k_wmlp(const float* __restrict__ W1, const float* __restrict__ W2) {
    int t = blockIdx.x * 256 + threadIdx.x;
    g_w1tf[t] = f2tf_f(W1[t]);
    if (t < CC * CC) g_w2tf[t] = f2tf_f(W2[t]);
}
__global__ void k_init() {
    int i = blockIdx.x * 256 + threadIdx.x;
    g_kv[i] = 0.f;
    if (i < BB * HEADS * KRR) g_colsum[i] = 0.f;
}

// ---------------- conv: implicit-GEMM tf32, 3-stage cp.async, 1 sync/stage -----
__global__ __launch_bounds__(256) void k_conv(const float* __restrict__ conv_b) {
    extern __shared__ float sm[];                      // A0..A2 @0, B0..B2 @13824
    const int tid = threadIdx.x, lane = tid & 31, wid = tid >> 5;
    const int wm = wid & 3, wn = wid >> 2;
    const int grp = lane >> 2, tig = lane & 3;
    const int otile = blockIdx.x * 128, mtile = blockIdx.y * 128;
    const int b = mtile >> 14;
    const int lrow = tid >> 1, lk = (tid & 1) * 16;
    const int prow = (mtile & (NN - 1)) + lrow;
    const int py = prow >> 7, px = prow & 127;
    const float* xb = g_xtf + ((size_t)b << 14) * CC;
    const float* wrow = g_wcat + (size_t)(otile + lrow) * KCONV + lk;

    float acc[2][8][4] = {};

    auto issue = [&](int s) {
        const int buf = s % 3;
        const int g = s >> 3;
        const int dy = g / 3 - 1, dx = g % 3 - 1;
        const int yy = py + dy, xx = px + dx;
        const bool valid = ((unsigned)yy < 128u) && ((unsigned)xx < 128u);
        const float* asrc = xb + (size_t)((yy << 7) + xx) * CC + ((s & 7) << 5) + lk;
        float* adst = sm + buf * 4608 + lrow * 36 + lk;
        const float* bsrc = wrow + (s << 5);
        float* bdst = sm + 13824 + buf * 4608 + lrow * 36 + lk;
        #pragma unroll
        for (int j = 0; j < 4; j++) {
            cp16(adst + j * 4, asrc + j * 4, valid);
            cp16(bdst + j * 4, bsrc + j * 4, true);
        }
        cp_commit();
    };

    issue(0); issue(1);
    for (int s = 0; s < 72; s++) {
        if (s + 1 < 72) asm volatile("cp.async.wait_group 1;");
        else            asm volatile("cp.async.wait_group 0;");
        __syncthreads();
        if (s + 2 < 72) issue(s + 2);
        const float* A = sm + (s % 3) * 4608;
        const float* Bm = sm + 13824 + (s % 3) * 4608;
        #pragma unroll
        for (int ks = 0; ks < 4; ks++) {
            const int k0 = ks * 8 + tig;
            unsigned a[2][4], bb[2];
            lda_row<36>(a[0], A, wm * 32 + grp, k0);
            lda_row<36>(a[1], A, wm * 32 + 16 + grp, k0);
            #pragma unroll
            for (int nt = 0; nt < 8; nt++) {
                ldb_row<36>(bb, Bm, wn * 64 + nt * 8 + grp, k0);
                mma_tf32(acc[0][nt], a[0], bb);
                mma_tf32(acc[1][nt], a[1], bb);
            }
        }
    }
    #pragma unroll
    for (int mt = 0; mt < 2; mt++)
        #pragma unroll
        for (int nt = 0; nt < 8; nt++) {
            const int r = wm * 32 + mt * 16 + grp;
            const int c = wn * 64 + nt * 8 + tig * 2;
            const float b0 = conv_b[otile + c], b1 = conv_b[otile + c + 1];
            *(float2*)(g_xc + (size_t)(mtile + r) * INNER + otile + c) =
                make_float2(acc[mt][nt][0] + b0, acc[mt][nt][1] + b1);
            *(float2*)(g_xc + (size_t)(mtile + r + 8) * INNER + otile + c) =
                make_float2(acc[mt][nt][2] + b0, acc[mt][nt][3] + b1);
        }
}

// ---------------- MLP: single tf32, 3-stage cp.async ---------------------------
template <int MODE>
__global__ __launch_bounds__(256) void k_mlp(const float* __restrict__ bias,
                                             float* __restrict__ out_ext) {
    constexpr int K = MODE ? CC : INNER;
    constexpr int NS = K / 32;
    const float* A_g = MODE ? g_h1 : g_qkv;
    const float* B_g = MODE ? g_w2tf : g_w1tf;
    float* out = MODE ? out_ext : g_h1;

    extern __shared__ float sm[];
    const int tid = threadIdx.x, lane = tid & 31, wid = tid >> 5;
    const int wm = wid & 3, wn = wid >> 2;
    const int grp = lane >> 2, tig = lane & 3;
    const int otile = blockIdx.x * 128, m0 = blockIdx.y * 128;
    const int lrow = tid >> 1, lk = (tid & 1) * 16;
    const float* arow = A_g + (size_t)(m0 + lrow) * K + lk;
    const float* brow = B_g + (size_t)(otile + lrow) * K + lk;

    float acc[2][8][4] = {};

    auto issue = [&](int s) {
        const int buf = s % 3;
        float* adst = sm + buf * 4608 + lrow * 36 + lk;
        float* bdst = sm + 13824 + buf * 4608 + lrow * 36 + lk;
        #pragma unroll
        for (int j = 0; j < 4; j++) {
            cp16(adst + j * 4, arow + (s << 5) + j * 4, true);
            cp16(bdst + j * 4, brow + (s << 5) + j * 4, true);
        }
        cp_commit();
    };

    issue(0); issue(1);
    for (int s = 0; s < NS; s++) {
        if (s + 1 < NS) asm volatile("cp.async.wait_group 1;");
        else            asm volatile("cp.async.wait_group 0;");
        __syncthreads();
        if (s + 2 < NS) issue(s + 2);
        const float* A = sm + (s % 3) * 4608;
        const float* Bm = sm + 13824 + (s % 3) * 4608;
        #pragma unroll
        for (int ks = 0; ks < 4; ks++) {
            const int k0 = ks * 8 + tig;
            unsigned a[2][4], bb[2];
            lda_row<36>(a[0], A, wm * 32 + grp, k0);
            lda_row<36>(a[1], A, wm * 32 + 16 + grp, k0);
            #pragma unroll
            for (int nt = 0; nt < 8; nt++) {
                ldb_row<36>(bb, Bm, wn * 64 + nt * 8 + grp, k0);
                mma_tf32(acc[0][nt], a[0], bb);
                mma_tf32(acc[1][nt], a[1], bb);
            }
        }
    }
    #pragma unroll
    for (int mt = 0; mt < 2; mt++)
        #pragma unroll
        for (int nt = 0; nt < 8; nt++) {
            const int r = wm * 32 + mt * 16 + grp;
            const int c = wn * 64 + nt * 8 + tig * 2;
            const float b0 = bias[otile + c], b1 = bias[otile + c + 1];
            float v[4] = {acc[mt][nt][0] + b0, acc[mt][nt][1] + b1,
                          acc[mt][nt][2] + b0, acc[mt][nt][3] + b1};
            if (MODE == 0) {
                #pragma unroll
                for (int j = 0; j < 4; j++)
                    v[j] = f2tf_f(0.5f * v[j] * (1.0f + erff(v[j] * 0.70710678118654752f)));
            }
            *(float2*)(out + (size_t)(m0 + r) * CC + otile + c)     = make_float2(v[0], v[1]);
            *(float2*)(out + (size_t)(m0 + r + 8) * CC + otile + c) = make_float2(v[2], v[3]);
        }
}

// ---------------- k_kv: tf32 mma K,V proj + exp + K^T V ------------------------
// grid (8, 64): block = (b,h) x 2048 rows, 32 chunks of 64.
__global__ __launch_bounds__(256) void k_kv(const float* __restrict__ Wk,
                                            const float* __restrict__ Wv) {
    extern __shared__ float sm[];
    float *Xs  = sm;             // [64][68] tf32
    float *Wkh = sm + 4352,  *Wkl = sm + 8704;
    float *Wvh = sm + 13056, *Wvl = sm + 17408;
    float *Kth = sm + 21760, *Ktl = sm + 26112;   // [kr][seq]
    float *Vth = sm + 30464, *Vtl = sm + 34816;   // [dh][seq]

    const int tid = threadIdx.x, lane = tid & 31, wid = tid >> 5;
    const int wm = wid & 3, wn = wid >> 2;
    const int grp = lane >> 2, tig = lane & 3;
    const int bh = blockIdx.y, b = bh >> 3, h = bh & 7;

    {   // weights, split hi/lo
        const int r = tid >> 2, c0 = (tid & 3) * 16;
        #pragma unroll
        for (int j = 0; j < 4; j++) {
            float4 kw = *(const float4*)(Wk + r * 64 + c0 + j * 4);
            float4 vw = *(const float4*)(Wv + r * 64 + c0 + j * 4);
            int o = r * 68 + c0 + j * 4;
            split_tf(kw.x, Wkh[o],   Wkl[o]);   split_tf(kw.y, Wkh[o+1], Wkl[o+1]);
            split_tf(kw.z, Wkh[o+2], Wkl[o+2]); split_tf(kw.w, Wkh[o+3], Wkl[o+3]);
            split_tf(vw.x, Wvh[o],   Wvl[o]);   split_tf(vw.y, Wvh[o+1], Wvl[o+1]);
            split_tf(vw.z, Wvh[o+2], Wvl[o+2]); split_tf(vw.w, Wvh[o+3], Wvl[o+3]);
        }
    }

    float kvacc[4][4] = {};
    float csum[8] = {};
    const int mrow = wm * 16 + grp;

    for (int ch = 0; ch < 32; ch++) {
        const int n0 = blockIdx.x * 2048 + ch * 64;
        __syncthreads();
        {   // X chunk -> tf32 smem
            const int r = tid >> 2, c0 = (tid & 3) * 16;
            const float* xsrc = g_xc + (size_t)(b * NN + n0 + r) * INNER + h * 64 + c0;
            #pragma unroll
            for (int j = 0; j < 4; j++) {
                float4 v = *(const float4*)(xsrc + j * 4);
                *(float4*)&Xs[r * 68 + c0 + j * 4] =
                    make_float4(f2tf_f(v.x), f2tf_f(v.y), f2tf_f(v.z), f2tf_f(v.w));
            }
        }
        __syncthreads();

        float ka[4][4] = {}, va[4][4] = {};
        #pragma unroll
        for (int ks = 0; ks < 8; ks++) {
            const int k0 = ks * 8 + tig;
            unsigned a[4], bh2[2], bl2[2];
            lda_row<68>(a, Xs, mrow, k0);
            #pragma unroll
            for (int nt = 0; nt < 4; nt++) {
                const int n = wn * 32 + nt * 8 + grp;
                ldb_row<68>(bh2, Wkh, n, k0); ldb_row<68>(bl2, Wkl, n, k0);
                mma_tf32(ka[nt], a, bh2); mma_tf32(ka[nt], a, bl2);
                ldb_row<68>(bh2, Wvh, n, k0); ldb_row<68>(bl2, Wvl, n, k0);
                mma_tf32(va[nt], a, bh2); mma_tf32(va[nt], a, bl2);
            }
        }
        // exp(K), transpose+split into Kt; V transpose+split into Vt
        #pragma unroll
        for (int nt = 0; nt < 4; nt++) {
            const int c = wn * 32 + nt * 8 + tig * 2;
            float e;
            e = __expf(ka[nt][0]); csum[nt*2]   += e; split_tf(e, Kth[c*68+mrow],       Ktl[c*68+mrow]);
            e = __expf(ka[nt][1]); csum[nt*2+1] += e; split_tf(e, Kth[(c+1)*68+mrow],   Ktl[(c+1)*68+mrow]);
            e = __expf(ka[nt][2]); csum[nt*2]   += e; split_tf(e, Kth[c*68+mrow+8],     Ktl[c*68+mrow+8]);
            e = __expf(ka[nt][3]); csum[nt*2+1] += e; split_tf(e, Kth[(c+1)*68+mrow+8], Ktl[(c+1)*68+mrow+8]);
            split_tf(va[nt][0], Vth[c*68+mrow],       Vtl[c*68+mrow]);
            split_tf(va[nt][1], Vth[(c+1)*68+mrow],   Vtl[(c+1)*68+mrow]);
            split_tf(va[nt][2], Vth[c*68+mrow+8],     Vtl[c*68+mrow+8]);
            split_tf(va[nt][3], Vth[(c+1)*68+mrow+8], Vtl[(c+1)*68+mrow+8]);
        }
        __syncthreads();

        // kv += K^T V   (3-term split)
        #pragma unroll
        for (int ks = 0; ks < 8; ks++) {
            const int k0 = ks * 8 + tig;
            unsigned ah[4], al[4], bh2[2], bl2[2];
            lda_row<68>(ah, Kth, mrow, k0);
            lda_row<68>(al, Ktl, mrow, k0);
            #pragma unroll
            for (int nt = 0; nt < 4; nt++) {
                const int n = wn * 32 + nt * 8 + grp;
                ldb_row<68>(bh2, Vth, n, k0); ldb_row<68>(bl2, Vtl, n, k0);
                mma_tf32(kvacc[nt], ah, bh2);
                mma_tf32(kvacc[nt], ah, bl2);
                mma_tf32(kvacc[nt], al, bh2);
            }
        }
    }

    float* kvbase = g_kv + (size_t)bh * (KRR * DHH);
    #pragma unroll
    for (int nt = 0; nt < 4; nt++) {
        const int c = wn * 32 + nt * 8 + tig * 2;
        atomicAdd(kvbase + mrow * 64 + c,           kvacc[nt][0]);
        atomicAdd(kvbase + mrow * 64 + c + 1,       kvacc[nt][1]);
        atomicAdd(kvbase + (mrow + 8) * 64 + c,     kvacc[nt][2]);
        atomicAdd(kvbase + (mrow + 8) * 64 + c + 1, kvacc[nt][3]);
    }
    #pragma unroll
    for (int idx = 0; idx < 8; idx++) {
        const int c = wn * 32 + (idx >> 1) * 8 + tig * 2 + (idx & 1);
        atomicAdd(g_colsum + bh * 64 + c, csum[idx]);
    }
}

__global__ void k_kvnorm() {
    int i = blockIdx.x * 256 + threadIdx.x;
    g_kv[i] = g_kv[i] / g_colsum[i >> 6];
}

// ---------------- k_qkv: tf32 mma q proj -> softmax scale -> q @ kv ------------
// grid (128, 64): block = (b,h) x 128 rows.
__global__ __launch_bounds__(256) void k_qkv(const float* __restrict__ Wq) {
    extern __shared__ float sm[];
    float *Xs   = sm;                     // [128][68]
    float *Qh   = sm + 8704, *Ql = sm + 17408;   // [128][68] exp(q) hi/lo
    float *Wqh  = sm + 26112, *Wql = sm + 30464; // [64][68]
    float *kvth = sm + 34816, *kvtl = sm + 39168;// [dh][kr]
    float *rsum = sm + 43520;             // [128]
    float *inv  = sm + 43648;             // [128]

    const int tid = threadIdx.x, lane = tid & 31, wid = tid >> 5;
    const int wm = wid & 3, wn = wid >> 2;
    const int grp = lane >> 2, tig = lane & 3;
    const int bh = blockIdx.y, b = bh >> 3, h = bh & 7;
    const int n0 = blockIdx.x * 128;

    if (tid < 128) rsum[tid] = 0.f;
    {   // Wq split + kv^T split
        const int r = tid >> 2, c0 = (tid & 3) * 16;
        const float* kvsrc = g_kv + (size_t)bh * (KRR * DHH) + r * 64 + c0;
        #pragma unroll
        for (int j = 0; j < 4; j++) {
            float4 qw = *(const float4*)(Wq + r * 64 + c0 + j * 4);
            int o = r * 68 + c0 + j * 4;
            split_tf(qw.x, Wqh[o],   Wql[o]);   split_tf(qw.y, Wqh[o+1], Wql[o+1]);
            split_tf(qw.z, Wqh[o+2], Wql[o+2]); split_tf(qw.w, Wqh[o+3], Wql[o+3]);
            float4 kv4 = *(const float4*)(kvsrc + j * 4);
            split_tf(kv4.x, kvth[(c0+j*4+0)*68 + r], kvtl[(c0+j*4+0)*68 + r]);
            split_tf(kv4.y, kvth[(c0+j*4+1)*68 + r], kvtl[(c0+j*4+1)*68 + r]);
            split_tf(kv4.z, kvth[(c0+j*4+2)*68 + r], kvtl[(c0+j*4+2)*68 + r]);
            split_tf(kv4.w, kvth[(c0+j*4+3)*68 + r], kvtl[(c0+j*4+3)*68 + r]);
        }
    }
    {   // X 128 rows -> tf32
        const int xr = tid >> 1, xc0 = (tid & 1) * 32;
        const float* xsrc = g_xc + (size_t)(b * NN + n0 + xr) * INNER + h * 64 + xc0;
        #pragma unroll
        for (int j = 0; j < 8; j++) {
            float4 v = *(const float4*)(xsrc + j * 4);
            *(float4*)&Xs[xr * 68 + xc0 + j * 4] =
                make_float4(f2tf_f(v.x), f2tf_f(v.y), f2tf_f(v.z), f2tf_f(v.w));
        }
    }
    __syncthreads();

    // q proj (X single, W split)
    float qa[2][4][4] = {};
    #pragma unroll
    for (int ks = 0; ks < 8; ks++) {
        const int k0 = ks * 8 + tig;
        unsigned a[2][4], bh2[2], bl2[2];
        lda_row<68>(a[0], Xs, wm * 32 + grp, k0);
        lda_row<68>(a[1], Xs, wm * 32 + 16 + grp, k0);
        #pragma unroll
        for (int nt = 0; nt < 4; nt++) {
            const int n = wn * 32 + nt * 8 + grp;
            ldb_row<68>(bh2, Wqh, n, k0); ldb_row<68>(bl2, Wql, n, k0);
            #pragma unroll
            for (int mt = 0; mt < 2; mt++) {
                mma_tf32(qa[mt][nt], a[mt], bh2);
                mma_tf32(qa[mt][nt], a[mt], bl2);
            }
        }
    }
    // exp, store split, row partial sums
    float rp[2][2] = {};     // [mt][row parity (grp / grp+8)]
    #pragma unroll
    for (int mt = 0; mt < 2; mt++)
        #pragma unroll
        for (int nt = 0; nt < 4; nt++) {
            const int r = wm * 32 + mt * 16 + grp;
            const int c = wn * 32 + nt * 8 + tig * 2;
            float e0 = __expf(qa[mt][nt][0]), e1 = __expf(qa[mt][nt][1]);
            float e2 = __expf(qa[mt][nt][2]), e3 = __expf(qa[mt][nt][3]);
            rp[mt][0] += e0 + e1; rp[mt][1] += e2 + e3;
            split_tf(e0, Qh[r*68+c],       Ql[r*68+c]);
            split_tf(e1, Qh[r*68+c+1],     Ql[r*68+c+1]);
            split_tf(e2, Qh[(r+8)*68+c],   Ql[(r+8)*68+c]);
            split_tf(e3, Qh[(r+8)*68+c+1], Ql[(r+8)*68+c+1]);
        }
    #pragma unroll
    for (int mt = 0; mt < 2; mt++)
        #pragma unroll
        for (int p = 0; p < 2; p++) {
            float v = rp[mt][p];
            v += __shfl_xor_sync(0xffffffffu, v, 1);
            v += __shfl_xor_sync(0xffffffffu, v, 2);
            if (tig == 0) atomicAdd(&rsum[wm * 32 + mt * 16 + grp + p * 8], v);
        }
    __syncthreads();
    if (tid < 128) inv[tid] = 1.f / rsum[tid];
    __syncthreads();

    // qkv = exp(q) @ kv (3-term), scaled by inv[row]
    float acc[2][4][4] = {};
    #pragma unroll
    for (int ks = 0; ks < 8; ks++) {
        const int k0 = ks * 8 + tig;
        unsigned ah[2][4], al[2][4], bh2[2], bl2[2];
        #pragma unroll
        for (int mt = 0; mt < 2; mt++) {
            lda_row<68>(ah[mt], Qh, wm * 32 + mt * 16 + grp, k0);
            lda_row<68>(al[mt], Ql, wm * 32 + mt * 16 + grp, k0);
        }
        #pragma unroll
        for (int nt = 0; nt < 4; nt++) {
            const int n = wn * 32 + nt * 8 + grp;
            ldb_row<68>(bh2, kvth, n, k0); ldb_row<68>(bl2, kvtl, n, k0);
            #pragma unroll
            for (int mt = 0; mt < 2; mt++) {
                mma_tf32(acc[mt][nt], ah[mt], bh2);
                mma_tf32(acc[mt][nt], ah[mt], bl2);
                mma_tf32(acc[mt][nt], al[mt], bh2);
            }
        }
    }
    #pragma unroll
    for (int mt = 0; mt < 2; mt++)
        #pragma unroll
        for (int nt = 0; nt < 4; nt++) {
            const int r = wm * 32 + mt * 16 + grp;
            const int c = wn * 32 + nt * 8 + tig * 2;
            const float i0 = inv[r], i1 = inv[r + 8];
            float* d0 = g_qkv + (size_t)(b * NN + n0 + r) * INNER + h * 64 + c;
            float* d1 = g_qkv + (size_t)(b * NN + n0 + r + 8) * INNER + h * 64 + c;
            *(float2*)d0 = make_float2(f2tf_f(acc[mt][nt][0] * i0), f2tf_f(acc[mt][nt][1] * i0));
            *(float2*)d1 = make_float2(f2tf_f(acc[mt][nt][2] * i1), f2tf_f(acc[mt][nt][3] * i1));
        }
}

// ------------------------------------------------------------------------------
extern "C" void kernel_launch(void* const* d_in, const int* in_sizes, int n_in,
                              void* d_out, int out_size) {
    const float* x      = (const float*)d_in[0];
    const float* conv_w = (const float*)d_in[1];
    const float* conv_b = (const float*)d_in[2];
    const float* Wq     = (const float*)d_in[3];
    const float* Wk     = (const float*)d_in[4];
    const float* Wv     = (const float*)d_in[5];
    const float* W1     = (const float*)d_in[6];
    const float* b1     = (const float*)d_in[7];
    const float* W2     = (const float*)d_in[8];
    const float* b2     = (const float*)d_in[9];
    float* out = (float*)d_out;

    cudaFuncSetAttribute(k_conv, cudaFuncAttributeMaxDynamicSharedMemorySize, 110592);
    cudaFuncSetAttribute(k_mlp<0>, cudaFuncAttributeMaxDynamicSharedMemorySize, 110592);
    cudaFuncSetAttribute(k_mlp<1>, cudaFuncAttributeMaxDynamicSharedMemorySize, 110592);
    cudaFuncSetAttribute(k_kv,   cudaFuncAttributeMaxDynamicSharedMemorySize, 156672);
    cudaFuncSetAttribute(k_qkv,  cudaFuncAttributeMaxDynamicSharedMemorySize, 175104);

    k_wprep<<<(INNER * KCONV + 255) / 256, 256>>>(conv_w);
    k_xprep<<<((BB * NN * CC) / 4 + 255) / 256, 256>>>(x);
    k_wmlp<<<(CC * INNER + 255) / 256, 256>>>(W1, W2);
    k_init<<<(BB * HEADS * KRR * DHH) / 256, 256>>>();
    k_conv<<<dim3(INNER / 128, (BB * NN) / 128), 256, 110592>>>(conv_b);
    k_kv<<<dim3(8, BB * HEADS), 256, 156672>>>(Wk, Wv);
    k_kvnorm<<<(BB * HEADS * KRR * DHH) / 256, 256>>>();
    k_qkv<<<dim3(128, BB * HEADS), 256, 175104>>>(Wq);
    k_mlp<0><<<dim3(CC / 128, (BB * NN) / 128), 256, 110592>>>(b1, nullptr);
    k_mlp<1><<<dim3(CC / 128, (BB * NN) / 128), 256, 110592>>>(b2, out);
}

// round 7
// speedup vs baseline: 5.6760x; 1.5752x over previous
#include <cuda_runtime.h>
#include <cuda_fp16.h>
#include <math.h>

#define BB 8
#define CC 256
#define NN 16384
#define HEADS 8
#define INNER 512
#define KCONV 2304
#define KRR 64
#define DHH 64

__device__ __half g_wch[(size_t)INNER * KCONV];
__device__ __half g_xh[(size_t)BB * NN * CC];
__device__ __half g_w1h[CC * INNER];
__device__ __half g_w2h[CC * CC];
__device__ float  g_xc[(size_t)BB * NN * INNER];
__device__ float  g_colsum[BB * HEADS * KRR];
__device__ float  g_kv[BB * HEADS * KRR * DHH];
__device__ __half g_qkv[(size_t)BB * NN * INNER];
__device__ __half g_h1[(size_t)BB * NN * CC];

__device__ __forceinline__ unsigned f2tf(float f) {
    unsigned u; asm("cvt.rna.tf32.f32 %0, %1;" : "=r"(u) : "f"(f)); return u;
}
__device__ __forceinline__ float f2tf_f(float f) { return __uint_as_float(f2tf(f)); }
__device__ __forceinline__ void split_tf(float f, float& hi, float& lo) {
    hi = __uint_as_float(f2tf(f)); lo = __uint_as_float(f2tf(f - hi));
}
__device__ __forceinline__ void mma_tf32(float c[4], const unsigned a[4], const unsigned b[2]) {
    asm volatile("mma.sync.aligned.m16n8k8.row.col.f32.tf32.tf32.f32 "
        "{%0,%1,%2,%3}, {%4,%5,%6,%7}, {%8,%9}, {%0,%1,%2,%3};"
        : "+f"(c[0]), "+f"(c[1]), "+f"(c[2]), "+f"(c[3])
        : "r"(a[0]), "r"(a[1]), "r"(a[2]), "r"(a[3]), "r"(b[0]), "r"(b[1]));
}
__device__ __forceinline__ void mma_f16(float c[4], const unsigned a[4], const unsigned b[2]) {
    asm volatile("mma.sync.aligned.m16n8k16.row.col.f32.f16.f16.f32 "
        "{%0,%1,%2,%3}, {%4,%5,%6,%7}, {%8,%9}, {%0,%1,%2,%3};"
        : "+f"(c[0]), "+f"(c[1]), "+f"(c[2]), "+f"(c[3])
        : "r"(a[0]), "r"(a[1]), "r"(a[2]), "r"(a[3]), "r"(b[0]), "r"(b[1]));
}
template <int STR>   // fp32/tf32 smem fragments (attention)
__device__ __forceinline__ void lda_row(unsigned a[4], const float* S, int r, int kc) {
    a[0] = __float_as_uint(S[r * STR + kc]);
    a[1] = __float_as_uint(S[(r + 8) * STR + kc]);
    a[2] = __float_as_uint(S[r * STR + kc + 4]);
    a[3] = __float_as_uint(S[(r + 8) * STR + kc + 4]);
}
template <int STR>
__device__ __forceinline__ void ldb_row(unsigned b[2], const float* S, int n, int kc) {
    b[0] = __float_as_uint(S[n * STR + kc]);
    b[1] = __float_as_uint(S[n * STR + kc + 4]);
}
// fp16 smem fragments: S is [row][k] halves, stride STR halves, tile base kk, quad lane tig
template <int STR>
__device__ __forceinline__ void lda16(unsigned a[4], const __half* S, int r, int kc) {
    a[0] = *(const unsigned*)&S[r * STR + kc];
    a[1] = *(const unsigned*)&S[(r + 8) * STR + kc];
    a[2] = *(const unsigned*)&S[r * STR + kc + 8];
    a[3] = *(const unsigned*)&S[(r + 8) * STR + kc + 8];
}
template <int STR>
__device__ __forceinline__ void ldb16(unsigned b[2], const __half* S, int n, int kc) {
    b[0] = *(const unsigned*)&S[n * STR + kc];
    b[1] = *(const unsigned*)&S[n * STR + kc + 8];
}
__device__ __forceinline__ void cp16(void* dst, const void* src, bool valid) {
    unsigned saddr = (unsigned)__cvta_generic_to_shared(dst);
    int sz = valid ? 16 : 0;
    asm volatile("cp.async.ca.shared.global [%0], [%1], 16, %2;"
                 :: "r"(saddr), "l"(src), "r"(sz));
}
__device__ __forceinline__ void cp_commit() { asm volatile("cp.async.commit_group;"); }

// ---------------- prep ---------------------------------------------------------
__global__ void k_wprep(const float* __restrict__ conv_w) {
    int t = blockIdx.x * 256 + threadIdx.x;
    if (t >= INNER * KCONV) return;
    int o = t / KCONV, k = t - o * KCONV;
    g_wch[t] = __float2half_rn(conv_w[(size_t)(o * CC + (k & 255)) * 9 + (k >> 8)]);
}
__global__ void k_xprep(const float* __restrict__ x) {
    int t = blockIdx.x * 256 + threadIdx.x;            // over BB*NN*CC/4
    float4 v = ((const float4*)x)[t];
    ((__half2*)g_xh)[t * 2]     = __floats2half2_rn(v.x, v.y);
    ((__half2*)g_xh)[t * 2 + 1] = __floats2half2_rn(v.z, v.w);
}
__global__ void k_wmlp(const float* __restrict__ W1, const float* __restrict__ W2) {
    int t = blockIdx.x * 256 + threadIdx.x;
    g_w1h[t] = __float2half_rn(W1[t]);
    if (t < CC * CC) g_w2h[t] = __float2half_rn(W2[t]);
}
__global__ void k_init() {
    int i = blockIdx.x * 256 + threadIdx.x;
    g_kv[i] = 0.f;
    if (i < BB * HEADS * KRR) g_colsum[i] = 0.f;
}

// ---------------- conv: fp16 m16n8k16 implicit GEMM, K-chunk 64, 3-stage -------
// smem halves: A bufs @ {0,9216,18432}, B bufs @ {27648,36864,46080}; stride 72
__global__ __launch_bounds__(256) void k_conv(const float* __restrict__ conv_b) {
    extern __shared__ __half sh[];
    const int tid = threadIdx.x, lane = tid & 31, wid = tid >> 5;
    const int wm = wid & 3, wn = wid >> 2;
    const int grp = lane >> 2, tig = lane & 3;
    const int otile = blockIdx.x * 128, mtile = blockIdx.y * 128;
    const int b = mtile >> 14;
    const int lrow = tid >> 1, lhalf = (tid & 1) * 32;
    const int prow = (mtile & (NN - 1)) + lrow;
    const int py = prow >> 7, px = prow & 127;
    const __half* xb = g_xh + (((size_t)b << 14)) * CC;
    const __half* wrow = g_wch + (size_t)(otile + lrow) * KCONV + lhalf;

    float acc[2][8][4] = {};

    auto issue = [&](int s) {
        const int buf = s % 3;
        const int g = s >> 2;
        const int dy = g / 3 - 1, dx = g % 3 - 1;
        const int cb = ((s & 3) << 6) + lhalf;
        const int yy = py + dy, xx = px + dx;
        const bool valid = ((unsigned)yy < 128u) && ((unsigned)xx < 128u);
        const __half* asrc = xb + (size_t)((yy << 7) + xx) * CC + cb;
        __half* adst = sh + buf * 9216 + lrow * 72 + lhalf;
        const __half* bsrc = wrow + (s << 6);
        __half* bdst = sh + 27648 + buf * 9216 + lrow * 72 + lhalf;
        #pragma unroll
        for (int j = 0; j < 4; j++) {
            cp16(adst + j * 8, asrc + j * 8, valid);
            cp16(bdst + j * 8, bsrc + j * 8, true);
        }
        cp_commit();
    };

    issue(0); issue(1);
    for (int s = 0; s < 36; s++) {
        if (s + 1 < 36) asm volatile("cp.async.wait_group 1;");
        else            asm volatile("cp.async.wait_group 0;");
        __syncthreads();
        if (s + 2 < 36) issue(s + 2);
        const __half* A  = sh + (s % 3) * 9216;
        const __half* Bm = sh + 27648 + (s % 3) * 9216;
        #pragma unroll
        for (int ks = 0; ks < 4; ks++) {
            const int kc = ks * 16 + tig * 2;
            unsigned a[2][4], bb[2];
            lda16<72>(a[0], A, wm * 32 + grp, kc);
            lda16<72>(a[1], A, wm * 32 + 16 + grp, kc);
            #pragma unroll
            for (int nt = 0; nt < 8; nt++) {
                ldb16<72>(bb, Bm, wn * 64 + nt * 8 + grp, kc);
                mma_f16(acc[0][nt], a[0], bb);
                mma_f16(acc[1][nt], a[1], bb);
            }
        }
    }
    #pragma unroll
    for (int mt = 0; mt < 2; mt++)
        #pragma unroll
        for (int nt = 0; nt < 8; nt++) {
            const int r = wm * 32 + mt * 16 + grp;
            const int c = wn * 64 + nt * 8 + tig * 2;
            const float b0 = conv_b[otile + c], b1 = conv_b[otile + c + 1];
            *(float2*)(g_xc + (size_t)(mtile + r) * INNER + otile + c) =
                make_float2(acc[mt][nt][0] + b0, acc[mt][nt][1] + b1);
            *(float2*)(g_xc + (size_t)(mtile + r + 8) * INNER + otile + c) =
                make_float2(acc[mt][nt][2] + b0, acc[mt][nt][3] + b1);
        }
}

// ---------------- MLP: fp16 m16n8k16, K-chunk 64, 3-stage ----------------------
template <int MODE>
__global__ __launch_bounds__(256) void k_mlp(const float* __restrict__ bias,
                                             float* __restrict__ out_ext) {
    constexpr int K = MODE ? CC : INNER;
    constexpr int NS = K / 64;
    const __half* A_g = MODE ? g_h1 : g_qkv;
    const __half* B_g = MODE ? g_w2h : g_w1h;

    extern __shared__ __half sh[];
    const int tid = threadIdx.x, lane = tid & 31, wid = tid >> 5;
    const int wm = wid & 3, wn = wid >> 2;
    const int grp = lane >> 2, tig = lane & 3;
    const int otile = blockIdx.x * 128, m0 = blockIdx.y * 128;
    const int lrow = tid >> 1, lhalf = (tid & 1) * 32;
    const __half* arow = A_g + (size_t)(m0 + lrow) * K + lhalf;
    const __half* brow = B_g + (size_t)(otile + lrow) * K + lhalf;

    float acc[2][8][4] = {};

    auto issue = [&](int s) {
        const int buf = s % 3;
        __half* adst = sh + buf * 9216 + lrow * 72 + lhalf;
        __half* bdst = sh + 27648 + buf * 9216 + lrow * 72 + lhalf;
        #pragma unroll
        for (int j = 0; j < 4; j++) {
            cp16(adst + j * 8, arow + (s << 6) + j * 8, true);
            cp16(bdst + j * 8, brow + (s << 6) + j * 8, true);
        }
        cp_commit();
    };

    issue(0); if (NS > 1) issue(1);
    for (int s = 0; s < NS; s++) {
        if (s + 1 < NS) asm volatile("cp.async.wait_group 1;");
        else            asm volatile("cp.async.wait_group 0;");
        __syncthreads();
        if (s + 2 < NS) issue(s + 2);
        const __half* A  = sh + (s % 3) * 9216;
        const __half* Bm = sh + 27648 + (s % 3) * 9216;
        #pragma unroll
        for (int ks = 0; ks < 4; ks++) {
            const int kc = ks * 16 + tig * 2;
            unsigned a[2][4], bb[2];
            lda16<72>(a[0], A, wm * 32 + grp, kc);
            lda16<72>(a[1], A, wm * 32 + 16 + grp, kc);
            #pragma unroll
            for (int nt = 0; nt < 8; nt++) {
                ldb16<72>(bb, Bm, wn * 64 + nt * 8 + grp, kc);
                mma_f16(acc[0][nt], a[0], bb);
                mma_f16(acc[1][nt], a[1], bb);
            }
        }
    }
    #pragma unroll
    for (int mt = 0; mt < 2; mt++)
        #pragma unroll
        for (int nt = 0; nt < 8; nt++) {
            const int r = wm * 32 + mt * 16 + grp;
            const int c = wn * 64 + nt * 8 + tig * 2;
            const float b0 = bias[otile + c], b1 = bias[otile + c + 1];
            float v[4] = {acc[mt][nt][0] + b0, acc[mt][nt][1] + b1,
                          acc[mt][nt][2] + b0, acc[mt][nt][3] + b1};
            if (MODE == 0) {
                #pragma unroll
                for (int j = 0; j < 4; j++)
                    v[j] = 0.5f * v[j] * (1.0f + erff(v[j] * 0.70710678118654752f));
                *(__half2*)(g_h1 + (size_t)(m0 + r) * CC + otile + c) =
                    __floats2half2_rn(v[0], v[1]);
                *(__half2*)(g_h1 + (size_t)(m0 + r + 8) * CC + otile + c) =
                    __floats2half2_rn(v[2], v[3]);
            } else {
                *(float2*)(out_ext + (size_t)(m0 + r) * CC + otile + c) =
                    make_float2(v[0], v[1]);
                *(float2*)(out_ext + (size_t)(m0 + r + 8) * CC + otile + c) =
                    make_float2(v[2], v[3]);
            }
        }
}

// ---------------- k_kv: tf32 split mma (unchanged) ------------------------------
__global__ __launch_bounds__(256) void k_kv(const float* __restrict__ Wk,
                                            const float* __restrict__ Wv) {
    extern __shared__ float sm[];
    float *Xs  = sm;
    float *Wkh = sm + 4352,  *Wkl = sm + 8704;
    float *Wvh = sm + 13056, *Wvl = sm + 17408;
    float *Kth = sm + 21760, *Ktl = sm + 26112;
    float *Vth = sm + 30464, *Vtl = sm + 34816;

    const int tid = threadIdx.x, lane = tid & 31, wid = tid >> 5;
    const int wm = wid & 3, wn = wid >> 2;
    const int grp = lane >> 2, tig = lane & 3;
    const int bh = blockIdx.y, b = bh >> 3, h = bh & 7;

    {
        const int r = tid >> 2, c0 = (tid & 3) * 16;
        #pragma unroll
        for (int j = 0; j < 4; j++) {
            float4 kw = *(const float4*)(Wk + r * 64 + c0 + j * 4);
            float4 vw = *(const float4*)(Wv + r * 64 + c0 + j * 4);
            int o = r * 68 + c0 + j * 4;
            split_tf(kw.x, Wkh[o],   Wkl[o]);   split_tf(kw.y, Wkh[o+1], Wkl[o+1]);
            split_tf(kw.z, Wkh[o+2], Wkl[o+2]); split_tf(kw.w, Wkh[o+3], Wkl[o+3]);
            split_tf(vw.x, Wvh[o],   Wvl[o]);   split_tf(vw.y, Wvh[o+1], Wvl[o+1]);
            split_tf(vw.z, Wvh[o+2], Wvl[o+2]); split_tf(vw.w, Wvh[o+3], Wvl[o+3]);
        }
    }

    float kvacc[4][4] = {};
    float csum[8] = {};
    const int mrow = wm * 16 + grp;

    for (int ch = 0; ch < 32; ch++) {
        const int n0 = blockIdx.x * 2048 + ch * 64;
        __syncthreads();
        {
            const int r = tid >> 2, c0 = (tid & 3) * 16;
            const float* xsrc = g_xc + (size_t)(b * NN + n0 + r) * INNER + h * 64 + c0;
            #pragma unroll
            for (int j = 0; j < 4; j++) {
                float4 v = *(const float4*)(xsrc + j * 4);
                *(float4*)&Xs[r * 68 + c0 + j * 4] =
                    make_float4(f2tf_f(v.x), f2tf_f(v.y), f2tf_f(v.z), f2tf_f(v.w));
            }
        }
        __syncthreads();

        float ka[4][4] = {}, va[4][4] = {};
        #pragma unroll
        for (int ks = 0; ks < 8; ks++) {
            const int k0 = ks * 8 + tig;
            unsigned a[4], bh2[2], bl2[2];
            lda_row<68>(a, Xs, mrow, k0);
            #pragma unroll
            for (int nt = 0; nt < 4; nt++) {
                const int n = wn * 32 + nt * 8 + grp;
                ldb_row<68>(bh2, Wkh, n, k0); ldb_row<68>(bl2, Wkl, n, k0);
                mma_tf32(ka[nt], a, bh2); mma_tf32(ka[nt], a, bl2);
                ldb_row<68>(bh2, Wvh, n, k0); ldb_row<68>(bl2, Wvl, n, k0);
                mma_tf32(va[nt], a, bh2); mma_tf32(va[nt], a, bl2);
            }
        }
        #pragma unroll
        for (int nt = 0; nt < 4; nt++) {
            const int c = wn * 32 + nt * 8 + tig * 2;
            float e;
            e = __expf(ka[nt][0]); csum[nt*2]   += e; split_tf(e, Kth[c*68+mrow],       Ktl[c*68+mrow]);
            e = __expf(ka[nt][1]); csum[nt*2+1] += e; split_tf(e, Kth[(c+1)*68+mrow],   Ktl[(c+1)*68+mrow]);
            e = __expf(ka[nt][2]); csum[nt*2]   += e; split_tf(e, Kth[c*68+mrow+8],     Ktl[c*68+mrow+8]);
            e = __expf(ka[nt][3]); csum[nt*2+1] += e; split_tf(e, Kth[(c+1)*68+mrow+8], Ktl[(c+1)*68+mrow+8]);
            split_tf(va[nt][0], Vth[c*68+mrow],       Vtl[c*68+mrow]);
            split_tf(va[nt][1], Vth[(c+1)*68+mrow],   Vtl[(c+1)*68+mrow]);
            split_tf(va[nt][2], Vth[c*68+mrow+8],     Vtl[c*68+mrow+8]);
            split_tf(va[nt][3], Vth[(c+1)*68+mrow+8], Vtl[(c+1)*68+mrow+8]);
        }
        __syncthreads();

        #pragma unroll
        for (int ks = 0; ks < 8; ks++) {
            const int k0 = ks * 8 + tig;
            unsigned ah[4], al[4], bh2[2], bl2[2];
            lda_row<68>(ah, Kth, mrow, k0);
            lda_row<68>(al, Ktl, mrow, k0);
            #pragma unroll
            for (int nt = 0; nt < 4; nt++) {
                const int n = wn * 32 + nt * 8 + grp;
                ldb_row<68>(bh2, Vth, n, k0); ldb_row<68>(bl2, Vtl, n, k0);
                mma_tf32(kvacc[nt], ah, bh2);
                mma_tf32(kvacc[nt], ah, bl2);
                mma_tf32(kvacc[nt], al, bh2);
            }
        }
    }

    float* kvbase = g_kv + (size_t)bh * (KRR * DHH);
    #pragma unroll
    for (int nt = 0; nt < 4; nt++) {
        const int c = wn * 32 + nt * 8 + tig * 2;
        atomicAdd(kvbase + mrow * 64 + c,           kvacc[nt][0]);
        atomicAdd(kvbase + mrow * 64 + c + 1,       kvacc[nt][1]);
        atomicAdd(kvbase + (mrow + 8) * 64 + c,     kvacc[nt][2]);
        atomicAdd(kvbase + (mrow + 8) * 64 + c + 1, kvacc[nt][3]);
    }
    #pragma unroll
    for (int idx = 0; idx < 8; idx++) {
        const int c = wn * 32 + (idx >> 1) * 8 + tig * 2 + (idx & 1);
        atomicAdd(g_colsum + bh * 64 + c, csum[idx]);
    }
}

__global__ void k_kvnorm() {
    int i = blockIdx.x * 256 + threadIdx.x;
    g_kv[i] = g_kv[i] / g_colsum[i >> 6];
}

// ---------------- k_qkv: tf32 split mma, half output ----------------------------
__global__ __launch_bounds__(256) void k_qkv(const float* __restrict__ Wq) {
    extern __shared__ float sm[];
    float *Xs   = sm;
    float *Qh   = sm + 8704, *Ql = sm + 17408;
    float *Wqh  = sm + 26112, *Wql = sm + 30464;
    float *kvth = sm + 34816, *kvtl = sm + 39168;
    float *rsum = sm + 43520;
    float *inv  = sm + 43648;

    const int tid = threadIdx.x, lane = tid & 31, wid = tid >> 5;
    const int wm = wid & 3, wn = wid >> 2;
    const int grp = lane >> 2, tig = lane & 3;
    const int bh = blockIdx.y, b = bh >> 3, h = bh & 7;
    const int n0 = blockIdx.x * 128;

    if (tid < 128) rsum[tid] = 0.f;
    {
        const int r = tid >> 2, c0 = (tid & 3) * 16;
        const float* kvsrc = g_kv + (size_t)bh * (KRR * DHH) + r * 64 + c0;
        #pragma unroll
        for (int j = 0; j < 4; j++) {
            float4 qw = *(const float4*)(Wq + r * 64 + c0 + j * 4);
            int o = r * 68 + c0 + j * 4;
            split_tf(qw.x, Wqh[o],   Wql[o]);   split_tf(qw.y, Wqh[o+1], Wql[o+1]);
            split_tf(qw.z, Wqh[o+2], Wql[o+2]); split_tf(qw.w, Wqh[o+3], Wql[o+3]);
            float4 kv4 = *(const float4*)(kvsrc + j * 4);
            split_tf(kv4.x, kvth[(c0+j*4+0)*68 + r], kvtl[(c0+j*4+0)*68 + r]);
            split_tf(kv4.y, kvth[(c0+j*4+1)*68 + r], kvtl[(c0+j*4+1)*68 + r]);
            split_tf(kv4.z, kvth[(c0+j*4+2)*68 + r], kvtl[(c0+j*4+2)*68 + r]);
            split_tf(kv4.w, kvth[(c0+j*4+3)*68 + r], kvtl[(c0+j*4+3)*68 + r]);
        }
    }
    {
        const int xr = tid >> 1, xc0 = (tid & 1) * 32;
        const float* xsrc = g_xc + (size_t)(b * NN + n0 + xr) * INNER + h * 64 + xc0;
        #pragma unroll
        for (int j = 0; j < 8; j++) {
            float4 v = *(const float4*)(xsrc + j * 4);
            *(float4*)&Xs[xr * 68 + xc0 + j * 4] =
                make_float4(f2tf_f(v.x), f2tf_f(v.y), f2tf_f(v.z), f2tf_f(v.w));
        }
    }
    __syncthreads();

    float qa[2][4][4] = {};
    #pragma unroll
    for (int ks = 0; ks < 8; ks++) {
        const int k0 = ks * 8 + tig;
        unsigned a[2][4], bh2[2], bl2[2];
        lda_row<68>(a[0], Xs, wm * 32 + grp, k0);
        lda_row<68>(a[1], Xs, wm * 32 + 16 + grp, k0);
        #pragma unroll
        for (int nt = 0; nt < 4; nt++) {
            const int n = wn * 32 + nt * 8 + grp;
            ldb_row<68>(bh2, Wqh, n, k0); ldb_row<68>(bl2, Wql, n, k0);
            #pragma unroll
            for (int mt = 0; mt < 2; mt++) {
                mma_tf32(qa[mt][nt], a[mt], bh2);
                mma_tf32(qa[mt][nt], a[mt], bl2);
            }
        }
    }
    float rp[2][2] = {};
    #pragma unroll
    for (int mt = 0; mt < 2; mt++)
        #pragma unroll
        for (int nt = 0; nt < 4; nt++) {
            const int r = wm * 32 + mt * 16 + grp;
            const int c = wn * 32 + nt * 8 + tig * 2;
            float e0 = __expf(qa[mt][nt][0]), e1 = __expf(qa[mt][nt][1]);
            float e2 = __expf(qa[mt][nt][2]), e3 = __expf(qa[mt][nt][3]);
            rp[mt][0] += e0 + e1; rp[mt][1] += e2 + e3;
            split_tf(e0, Qh[r*68+c],       Ql[r*68+c]);
            split_tf(e1, Qh[r*68+c+1],     Ql[r*68+c+1]);
            split_tf(e2, Qh[(r+8)*68+c],   Ql[(r+8)*68+c]);
            split_tf(e3, Qh[(r+8)*68+c+1], Ql[(r+8)*68+c+1]);
        }
    #pragma unroll
    for (int mt = 0; mt < 2; mt++)
        #pragma unroll
        for (int p = 0; p < 2; p++) {
            float v = rp[mt][p];
            v += __shfl_xor_sync(0xffffffffu, v, 1);
            v += __shfl_xor_sync(0xffffffffu, v, 2);
            if (tig == 0) atomicAdd(&rsum[wm * 32 + mt * 16 + grp + p * 8], v);
        }
    __syncthreads();
    if (tid < 128) inv[tid] = 1.f / rsum[tid];
    __syncthreads();

    float acc[2][4][4] = {};
    #pragma unroll
    for (int ks = 0; ks < 8; ks++) {
        const int k0 = ks * 8 + tig;
        unsigned ah[2][4], al[2][4], bh2[2], bl2[2];
        #pragma unroll
        for (int mt = 0; mt < 2; mt++) {
            lda_row<68>(ah[mt], Qh, wm * 32 + mt * 16 + grp, k0);
            lda_row<68>(al[mt], Ql, wm * 32 + mt * 16 + grp, k0);
        }
        #pragma unroll
        for (int nt = 0; nt < 4; nt++) {
            const int n = wn * 32 + nt * 8 + grp;
            ldb_row<68>(bh2, kvth, n, k0); ldb_row<68>(bl2, kvtl, n, k0);
            #pragma unroll
            for (int mt = 0; mt < 2; mt++) {
                mma_tf32(acc[mt][nt], ah[mt], bh2);
                mma_tf32(acc[mt][nt], ah[mt], bl2);
                mma_tf32(acc[mt][nt], al[mt], bh2);
            }
        }
    }
    #pragma unroll
    for (int mt = 0; mt < 2; mt++)
        #pragma unroll
        for (int nt = 0; nt < 4; nt++) {
            const int r = wm * 32 + mt * 16 + grp;
            const int c = wn * 32 + nt * 8 + tig * 2;
            const float i0 = inv[r], i1 = inv[r + 8];
            __half* d0 = g_qkv + (size_t)(b * NN + n0 + r) * INNER + h * 64 + c;
            __half* d1 = g_qkv + (size_t)(b * NN + n0 + r + 8) * INNER + h * 64 + c;
            *(__half2*)d0 = __floats2half2_rn(acc[mt][nt][0] * i0, acc[mt][nt][1] * i0);
            *(__half2*)d1 = __floats2half2_rn(acc[mt][nt][2] * i1, acc[mt][nt][3] * i1);
        }
}

// ------------------------------------------------------------------------------
extern "C" void kernel_launch(void* const* d_in, const int* in_sizes, int n_in,
                              void* d_out, int out_size) {
    const float* x      = (const float*)d_in[0];
    const float* conv_w = (const float*)d_in[1];
    const float* conv_b = (const float*)d_in[2];
    const float* Wq     = (const float*)d_in[3];
    const float* Wk     = (const float*)d_in[4];
    const float* Wv     = (const float*)d_in[5];
    const float* W1     = (const float*)d_in[6];
    const float* b1     = (const float*)d_in[7];
    const float* W2     = (const float*)d_in[8];
    const float* b2     = (const float*)d_in[9];
    float* out = (float*)d_out;

    cudaFuncSetAttribute(k_conv, cudaFuncAttributeMaxDynamicSharedMemorySize, 110592);
    cudaFuncSetAttribute(k_mlp<0>, cudaFuncAttributeMaxDynamicSharedMemorySize, 110592);
    cudaFuncSetAttribute(k_mlp<1>, cudaFuncAttributeMaxDynamicSharedMemorySize, 110592);
    cudaFuncSetAttribute(k_kv,   cudaFuncAttributeMaxDynamicSharedMemorySize, 156672);
    cudaFuncSetAttribute(k_qkv,  cudaFuncAttributeMaxDynamicSharedMemorySize, 175104);

    k_wprep<<<(INNER * KCONV + 255) / 256, 256>>>(conv_w);
    k_xprep<<<((BB * NN * CC) / 4 + 255) / 256, 256>>>(x);
    k_wmlp<<<(CC * INNER + 255) / 256, 256>>>(W1, W2);
    k_init<<<(BB * HEADS * KRR * DHH) / 256, 256>>>();
    k_conv<<<dim3(INNER / 128, (BB * NN) / 128), 256, 110592>>>(conv_b);
    k_kv<<<dim3(8, BB * HEADS), 256, 156672>>>(Wk, Wv);
    k_kvnorm<<<(BB * HEADS * KRR * DHH) / 256, 256>>>();
    k_qkv<<<dim3(128, BB * HEADS), 256, 175104>>>(Wq);
    k_mlp<0><<<dim3(CC / 128, (BB * NN) / 128), 256, 110592>>>(b1, nullptr);
    k_mlp<1><<<dim3(CC / 128, (BB * NN) / 128), 256, 110592>>>(b2, out);
}

// round 8
// speedup vs baseline: 6.8800x; 1.2121x over previous
#include <cuda_runtime.h>
#include <cuda_fp16.h>
#include <math.h>

#define BB 8
#define CC 256
#define NN 16384
#define HEADS 8
#define INNER 512
#define KCONV 2304
#define KRR 64
#define DHH 64

__device__ __half g_wch[(size_t)INNER * KCONV];
__device__ __half g_xh[(size_t)BB * NN * CC];
__device__ __half g_w1h[CC * INNER];
__device__ __half g_w2h[CC * CC];
__device__ __half g_xc[(size_t)BB * NN * INNER];
__device__ float  g_colsum[BB * HEADS * KRR];
__device__ float  g_kv[BB * HEADS * KRR * DHH];
__device__ __half g_qkv[(size_t)BB * NN * INNER];
__device__ __half g_h1[(size_t)BB * NN * CC];

__device__ __forceinline__ void mma_f16(float c[4], const unsigned a[4], const unsigned b[2]) {
    asm volatile("mma.sync.aligned.m16n8k16.row.col.f32.f16.f16.f32 "
        "{%0,%1,%2,%3}, {%4,%5,%6,%7}, {%8,%9}, {%0,%1,%2,%3};"
        : "+f"(c[0]), "+f"(c[1]), "+f"(c[2]), "+f"(c[3])
        : "r"(a[0]), "r"(a[1]), "r"(a[2]), "r"(a[3]), "r"(b[0]), "r"(b[1]));
}
template <int STR>
__device__ __forceinline__ void lda16(unsigned a[4], const __half* S, int r, int kc) {
    a[0] = *(const unsigned*)&S[r * STR + kc];
    a[1] = *(const unsigned*)&S[(r + 8) * STR + kc];
    a[2] = *(const unsigned*)&S[r * STR + kc + 8];
    a[3] = *(const unsigned*)&S[(r + 8) * STR + kc + 8];
}
template <int STR>
__device__ __forceinline__ void ldb16(unsigned b[2], const __half* S, int n, int kc) {
    b[0] = *(const unsigned*)&S[n * STR + kc];
    b[1] = *(const unsigned*)&S[n * STR + kc + 8];
}
__device__ __forceinline__ void split_h(float f, __half& hi, __half& lo) {
    hi = __float2half_rn(f);
    lo = __float2half_rn(f - __half2float(hi));
}
__device__ __forceinline__ void cp16(void* dst, const void* src, bool valid) {
    unsigned saddr = (unsigned)__cvta_generic_to_shared(dst);
    int sz = valid ? 16 : 0;
    asm volatile("cp.async.ca.shared.global [%0], [%1], 16, %2;"
                 :: "r"(saddr), "l"(src), "r"(sz));
}
__device__ __forceinline__ void cp_commit() { asm volatile("cp.async.commit_group;"); }

// ---------------- prep ---------------------------------------------------------
__global__ void k_wprep(const float* __restrict__ conv_w) {
    int t = blockIdx.x * 256 + threadIdx.x;
    if (t >= INNER * KCONV) return;
    int o = t / KCONV, k = t - o * KCONV;
    g_wch[t] = __float2half_rn(conv_w[(size_t)(o * CC + (k & 255)) * 9 + (k >> 8)]);
}
__global__ void k_xprep(const float* __restrict__ x) {
    int t = blockIdx.x * 256 + threadIdx.x;
    float4 v = ((const float4*)x)[t];
    ((__half2*)g_xh)[t * 2]     = __floats2half2_rn(v.x, v.y);
    ((__half2*)g_xh)[t * 2 + 1] = __floats2half2_rn(v.z, v.w);
}
__global__ void k_wmlp(const float* __restrict__ W1, const float* __restrict__ W2) {
    int t = blockIdx.x * 256 + threadIdx.x;
    g_w1h[t] = __float2half_rn(W1[t]);
    if (t < CC * CC) g_w2h[t] = __float2half_rn(W2[t]);
}
__global__ void k_init() {
    int i = blockIdx.x * 256 + threadIdx.x;
    g_kv[i] = 0.f;
    if (i < BB * HEADS * KRR) g_colsum[i] = 0.f;
}

// ---------------- conv: fp16 m16n8k16 implicit GEMM, K-chunk 64, 3-stage -------
__global__ __launch_bounds__(256) void k_conv(const float* __restrict__ conv_b) {
    extern __shared__ __half sh[];
    const int tid = threadIdx.x, lane = tid & 31, wid = tid >> 5;
    const int wm = wid & 3, wn = wid >> 2;
    const int grp = lane >> 2, tig = lane & 3;
    const int otile = blockIdx.x * 128, mtile = blockIdx.y * 128;
    const int b = mtile >> 14;
    const int lrow = tid >> 1, lhalf = (tid & 1) * 32;
    const int prow = (mtile & (NN - 1)) + lrow;
    const int py = prow >> 7, px = prow & 127;
    const __half* xb = g_xh + (((size_t)b << 14)) * CC;
    const __half* wrow = g_wch + (size_t)(otile + lrow) * KCONV + lhalf;

    float acc[2][8][4] = {};

    auto issue = [&](int s) {
        const int buf = s % 3;
        const int g = s >> 2;
        const int dy = g / 3 - 1, dx = g % 3 - 1;
        const int cb = ((s & 3) << 6) + lhalf;
        const int yy = py + dy, xx = px + dx;
        const bool valid = ((unsigned)yy < 128u) && ((unsigned)xx < 128u);
        const __half* asrc = xb + (size_t)((yy << 7) + xx) * CC + cb;
        __half* adst = sh + buf * 9216 + lrow * 72 + lhalf;
        const __half* bsrc = wrow + (s << 6);
        __half* bdst = sh + 27648 + buf * 9216 + lrow * 72 + lhalf;
        #pragma unroll
        for (int j = 0; j < 4; j++) {
            cp16(adst + j * 8, asrc + j * 8, valid);
            cp16(bdst + j * 8, bsrc + j * 8, true);
        }
        cp_commit();
    };

    issue(0); issue(1);
    for (int s = 0; s < 36; s++) {
        if (s + 1 < 36) asm volatile("cp.async.wait_group 1;");
        else            asm volatile("cp.async.wait_group 0;");
        __syncthreads();
        if (s + 2 < 36) issue(s + 2);
        const __half* A  = sh + (s % 3) * 9216;
        const __half* Bm = sh + 27648 + (s % 3) * 9216;
        #pragma unroll
        for (int ks = 0; ks < 4; ks++) {
            const int kc = ks * 16 + tig * 2;
            unsigned a[2][4], bb[2];
            lda16<72>(a[0], A, wm * 32 + grp, kc);
            lda16<72>(a[1], A, wm * 32 + 16 + grp, kc);
            #pragma unroll
            for (int nt = 0; nt < 8; nt++) {
                ldb16<72>(bb, Bm, wn * 64 + nt * 8 + grp, kc);
                mma_f16(acc[0][nt], a[0], bb);
                mma_f16(acc[1][nt], a[1], bb);
            }
        }
    }
    #pragma unroll
    for (int mt = 0; mt < 2; mt++)
        #pragma unroll
        for (int nt = 0; nt < 8; nt++) {
            const int r = wm * 32 + mt * 16 + grp;
            const int c = wn * 64 + nt * 8 + tig * 2;
            const float b0 = conv_b[otile + c], b1 = conv_b[otile + c + 1];
            *(__half2*)(g_xc + (size_t)(mtile + r) * INNER + otile + c) =
                __floats2half2_rn(acc[mt][nt][0] + b0, acc[mt][nt][1] + b1);
            *(__half2*)(g_xc + (size_t)(mtile + r + 8) * INNER + otile + c) =
                __floats2half2_rn(acc[mt][nt][2] + b0, acc[mt][nt][3] + b1);
        }
}

// ---------------- MLP: fp16 m16n8k16, K-chunk 64, 3-stage ----------------------
template <int MODE>
__global__ __launch_bounds__(256) void k_mlp(const float* __restrict__ bias,
                                             float* __restrict__ out_ext) {
    constexpr int K = MODE ? CC : INNER;
    constexpr int NS = K / 64;
    const __half* A_g = MODE ? g_h1 : g_qkv;
    const __half* B_g = MODE ? g_w2h : g_w1h;

    extern __shared__ __half sh[];
    const int tid = threadIdx.x, lane = tid & 31, wid = tid >> 5;
    const int wm = wid & 3, wn = wid >> 2;
    const int grp = lane >> 2, tig = lane & 3;
    const int otile = blockIdx.x * 128, m0 = blockIdx.y * 128;
    const int lrow = tid >> 1, lhalf = (tid & 1) * 32;
    const __half* arow = A_g + (size_t)(m0 + lrow) * K + lhalf;
    const __half* brow = B_g + (size_t)(otile + lrow) * K + lhalf;

    float acc[2][8][4] = {};

    auto issue = [&](int s) {
        const int buf = s % 3;
        __half* adst = sh + buf * 9216 + lrow * 72 + lhalf;
        __half* bdst = sh + 27648 + buf * 9216 + lrow * 72 + lhalf;
        #pragma unroll
        for (int j = 0; j < 4; j++) {
            cp16(adst + j * 8, arow + (s << 6) + j * 8, true);
            cp16(bdst + j * 8, brow + (s << 6) + j * 8, true);
        }
        cp_commit();
    };

    issue(0); if (NS > 1) issue(1);
    for (int s = 0; s < NS; s++) {
        if (s + 1 < NS) asm volatile("cp.async.wait_group 1;");
        else            asm volatile("cp.async.wait_group 0;");
        __syncthreads();
        if (s + 2 < NS) issue(s + 2);
        const __half* A  = sh + (s % 3) * 9216;
        const __half* Bm = sh + 27648 + (s % 3) * 9216;
        #pragma unroll
        for (int ks = 0; ks < 4; ks++) {
            const int kc = ks * 16 + tig * 2;
            unsigned a[2][4], bb[2];
            lda16<72>(a[0], A, wm * 32 + grp, kc);
            lda16<72>(a[1], A, wm * 32 + 16 + grp, kc);
            #pragma unroll
            for (int nt = 0; nt < 8; nt++) {
                ldb16<72>(bb, Bm, wn * 64 + nt * 8 + grp, kc);
                mma_f16(acc[0][nt], a[0], bb);
                mma_f16(acc[1][nt], a[1], bb);
            }
        }
    }
    #pragma unroll
    for (int mt = 0; mt < 2; mt++)
        #pragma unroll
        for (int nt = 0; nt < 8; nt++) {
            const int r = wm * 32 + mt * 16 + grp;
            const int c = wn * 64 + nt * 8 + tig * 2;
            const float b0 = bias[otile + c], b1 = bias[otile + c + 1];
            float v[4] = {acc[mt][nt][0] + b0, acc[mt][nt][1] + b1,
                          acc[mt][nt][2] + b0, acc[mt][nt][3] + b1};
            if (MODE == 0) {
                #pragma unroll
                for (int j = 0; j < 4; j++)
                    v[j] = 0.5f * v[j] * (1.0f + erff(v[j] * 0.70710678118654752f));
                *(__half2*)(g_h1 + (size_t)(m0 + r) * CC + otile + c) =
                    __floats2half2_rn(v[0], v[1]);
                *(__half2*)(g_h1 + (size_t)(m0 + r + 8) * CC + otile + c) =
                    __floats2half2_rn(v[2], v[3]);
            } else {
                *(float2*)(out_ext + (size_t)(m0 + r) * CC + otile + c) =
                    make_float2(v[0], v[1]);
                *(float2*)(out_ext + (size_t)(m0 + r + 8) * CC + otile + c) =
                    make_float2(v[2], v[3]);
            }
        }
}

// ---------------- k_kv: fp16 split mma K,V proj + exp + K^T V ------------------
// grid (8, 64): block = (b,h) x 2048 rows, 32 chunks of 64.
__global__ __launch_bounds__(256) void k_kv(const float* __restrict__ Wk,
                                            const float* __restrict__ Wv) {
    extern __shared__ __half sh[];
    __half *Xs  = sh;                               // [64][72]
    __half *Wkh = sh + 4608,  *Wkl = sh + 9216;
    __half *Wvh = sh + 13824, *Wvl = sh + 18432;
    __half *Kth = sh + 23040, *Ktl = sh + 27648;    // [kr][seq]
    __half *Vth = sh + 32256, *Vtl = sh + 36864;    // [dh][seq]  (end 41472 halves)

    const int tid = threadIdx.x, lane = tid & 31, wid = tid >> 5;
    const int wm = wid & 3, wn = wid >> 2;
    const int grp = lane >> 2, tig = lane & 3;
    const int bh = blockIdx.y, b = bh >> 3, h = bh & 7;
    const int r = tid >> 2, c0 = (tid & 3) * 16;

    #pragma unroll
    for (int j = 0; j < 16; j++) {
        split_h(Wk[r * 64 + c0 + j], Wkh[r * 72 + c0 + j], Wkl[r * 72 + c0 + j]);
        split_h(Wv[r * 64 + c0 + j], Wvh[r * 72 + c0 + j], Wvl[r * 72 + c0 + j]);
    }

    float kvacc[4][4] = {};
    float csum[8] = {};
    const int mrow = wm * 16 + grp;

    for (int ch = 0; ch < 32; ch++) {
        const int n0 = blockIdx.x * 2048 + ch * 64;
        __syncthreads();
        {
            const __half* xsrc = g_xc + (size_t)(b * NN + n0 + r) * INNER + h * 64 + c0;
            *(uint4*)&Xs[r * 72 + c0]     = *(const uint4*)xsrc;
            *(uint4*)&Xs[r * 72 + c0 + 8] = *(const uint4*)(xsrc + 8);
        }
        __syncthreads();

        float ka[4][4] = {}, va[4][4] = {};
        #pragma unroll
        for (int ks = 0; ks < 4; ks++) {
            const int kc = ks * 16 + tig * 2;
            unsigned a[4], bh2[2], bl2[2];
            lda16<72>(a, Xs, mrow, kc);
            #pragma unroll
            for (int nt = 0; nt < 4; nt++) {
                const int n = wn * 32 + nt * 8 + grp;
                ldb16<72>(bh2, Wkh, n, kc); ldb16<72>(bl2, Wkl, n, kc);
                mma_f16(ka[nt], a, bh2); mma_f16(ka[nt], a, bl2);
                ldb16<72>(bh2, Wvh, n, kc); ldb16<72>(bl2, Wvl, n, kc);
                mma_f16(va[nt], a, bh2); mma_f16(va[nt], a, bl2);
            }
        }
        #pragma unroll
        for (int nt = 0; nt < 4; nt++) {
            const int c = wn * 32 + nt * 8 + tig * 2;
            float e;
            e = __expf(ka[nt][0]); csum[nt*2]   += e; split_h(e, Kth[c*72+mrow],       Ktl[c*72+mrow]);
            e = __expf(ka[nt][1]); csum[nt*2+1] += e; split_h(e, Kth[(c+1)*72+mrow],   Ktl[(c+1)*72+mrow]);
            e = __expf(ka[nt][2]); csum[nt*2]   += e; split_h(e, Kth[c*72+mrow+8],     Ktl[c*72+mrow+8]);
            e = __expf(ka[nt][3]); csum[nt*2+1] += e; split_h(e, Kth[(c+1)*72+mrow+8], Ktl[(c+1)*72+mrow+8]);
            split_h(va[nt][0], Vth[c*72+mrow],       Vtl[c*72+mrow]);
            split_h(va[nt][1], Vth[(c+1)*72+mrow],   Vtl[(c+1)*72+mrow]);
            split_h(va[nt][2], Vth[c*72+mrow+8],     Vtl[c*72+mrow+8]);
            split_h(va[nt][3], Vth[(c+1)*72+mrow+8], Vtl[(c+1)*72+mrow+8]);
        }
        __syncthreads();

        #pragma unroll
        for (int ks = 0; ks < 4; ks++) {
            const int kc = ks * 16 + tig * 2;
            unsigned ah[4], al[4], bh2[2], bl2[2];
            lda16<72>(ah, Kth, mrow, kc);
            lda16<72>(al, Ktl, mrow, kc);
            #pragma unroll
            for (int nt = 0; nt < 4; nt++) {
                const int n = wn * 32 + nt * 8 + grp;
                ldb16<72>(bh2, Vth, n, kc); ldb16<72>(bl2, Vtl, n, kc);
                mma_f16(kvacc[nt], ah, bh2);
                mma_f16(kvacc[nt], ah, bl2);
                mma_f16(kvacc[nt], al, bh2);
            }
        }
    }

    float* kvbase = g_kv + (size_t)bh * (KRR * DHH);
    #pragma unroll
    for (int nt = 0; nt < 4; nt++) {
        const int c = wn * 32 + nt * 8 + tig * 2;
        atomicAdd(kvbase + mrow * 64 + c,           kvacc[nt][0]);
        atomicAdd(kvbase + mrow * 64 + c + 1,       kvacc[nt][1]);
        atomicAdd(kvbase + (mrow + 8) * 64 + c,     kvacc[nt][2]);
        atomicAdd(kvbase + (mrow + 8) * 64 + c + 1, kvacc[nt][3]);
    }
    #pragma unroll
    for (int idx = 0; idx < 8; idx++) {
        const int c = wn * 32 + (idx >> 1) * 8 + tig * 2 + (idx & 1);
        atomicAdd(g_colsum + bh * 64 + c, csum[idx]);
    }
}

__global__ void k_kvnorm() {
    int i = blockIdx.x * 256 + threadIdx.x;
    g_kv[i] = g_kv[i] / g_colsum[i >> 6];
}

// ---------------- k_qkv: fp16 split mma, half output ----------------------------
// grid (128, 64): block = (b,h) x 128 rows.
__global__ __launch_bounds__(256) void k_qkv(const float* __restrict__ Wq) {
    extern __shared__ __half sh[];
    __half *Xs   = sh;                               // [128][72]
    __half *Qh   = sh + 9216,  *Ql  = sh + 18432;    // [128][72]
    __half *Wqh  = sh + 27648, *Wql = sh + 32256;    // [64][72]
    __half *kvth = sh + 36864, *kvtl = sh + 41472;   // [dh][kr]
    float  *rsum = (float*)(sh + 46080);             // [128]
    float  *inv  = rsum + 128;                       // [128]

    const int tid = threadIdx.x, lane = tid & 31, wid = tid >> 5;
    const int wm = wid & 3, wn = wid >> 2;
    const int grp = lane >> 2, tig = lane & 3;
    const int bh = blockIdx.y, b = bh >> 3, h = bh & 7;
    const int n0 = blockIdx.x * 128;

    if (tid < 128) rsum[tid] = 0.f;
    {
        const int r = tid >> 2, c0 = (tid & 3) * 16;
        const float* kvsrc = g_kv + (size_t)bh * (KRR * DHH) + r * 64 + c0;
        #pragma unroll
        for (int j = 0; j < 16; j++) {
            split_h(Wq[r * 64 + c0 + j], Wqh[r * 72 + c0 + j], Wql[r * 72 + c0 + j]);
            split_h(kvsrc[j], kvth[(c0 + j) * 72 + r], kvtl[(c0 + j) * 72 + r]);
        }
    }
    {
        const int xr = tid >> 1, xc0 = (tid & 1) * 32;
        const __half* xsrc = g_xc + (size_t)(b * NN + n0 + xr) * INNER + h * 64 + xc0;
        #pragma unroll
        for (int j = 0; j < 4; j++)
            *(uint4*)&Xs[xr * 72 + xc0 + j * 8] = *(const uint4*)(xsrc + j * 8);
    }
    __syncthreads();

    float qa[2][4][4] = {};
    #pragma unroll
    for (int ks = 0; ks < 4; ks++) {
        const int kc = ks * 16 + tig * 2;
        unsigned a[2][4], bh2[2], bl2[2];
        lda16<72>(a[0], Xs, wm * 32 + grp, kc);
        lda16<72>(a[1], Xs, wm * 32 + 16 + grp, kc);
        #pragma unroll
        for (int nt = 0; nt < 4; nt++) {
            const int n = wn * 32 + nt * 8 + grp;
            ldb16<72>(bh2, Wqh, n, kc); ldb16<72>(bl2, Wql, n, kc);
            #pragma unroll
            for (int mt = 0; mt < 2; mt++) {
                mma_f16(qa[mt][nt], a[mt], bh2);
                mma_f16(qa[mt][nt], a[mt], bl2);
            }
        }
    }
    float rp[2][2] = {};
    #pragma unroll
    for (int mt = 0; mt < 2; mt++)
        #pragma unroll
        for (int nt = 0; nt < 4; nt++) {
            const int r = wm * 32 + mt * 16 + grp;
            const int c = wn * 32 + nt * 8 + tig * 2;
            float e0 = __expf(qa[mt][nt][0]), e1 = __expf(qa[mt][nt][1]);
            float e2 = __expf(qa[mt][nt][2]), e3 = __expf(qa[mt][nt][3]);
            rp[mt][0] += e0 + e1; rp[mt][1] += e2 + e3;
            split_h(e0, Qh[r*72+c],       Ql[r*72+c]);
            split_h(e1, Qh[r*72+c+1],     Ql[r*72+c+1]);
            split_h(e2, Qh[(r+8)*72+c],   Ql[(r+8)*72+c]);
            split_h(e3, Qh[(r+8)*72+c+1], Ql[(r+8)*72+c+1]);
        }
    #pragma unroll
    for (int mt = 0; mt < 2; mt++)
        #pragma unroll
        for (int p = 0; p < 2; p++) {
            float v = rp[mt][p];
            v += __shfl_xor_sync(0xffffffffu, v, 1);
            v += __shfl_xor_sync(0xffffffffu, v, 2);
            if (tig == 0) atomicAdd(&rsum[wm * 32 + mt * 16 + grp + p * 8], v);
        }
    __syncthreads();
    if (tid < 128) inv[tid] = 1.f / rsum[tid];
    __syncthreads();

    float acc[2][4][4] = {};
    #pragma unroll
    for (int ks = 0; ks < 4; ks++) {
        const int kc = ks * 16 + tig * 2;
        unsigned ah[2][4], al[2][4], bh2[2], bl2[2];
        #pragma unroll
        for (int mt = 0; mt < 2; mt++) {
            lda16<72>(ah[mt], Qh, wm * 32 + mt * 16 + grp, kc);
            lda16<72>(al[mt], Ql, wm * 32 + mt * 16 + grp, kc);
        }
        #pragma unroll
        for (int nt = 0; nt < 4; nt++) {
            const int n = wn * 32 + nt * 8 + grp;
            ldb16<72>(bh2, kvth, n, kc); ldb16<72>(bl2, kvtl, n, kc);
            #pragma unroll
            for (int mt = 0; mt < 2; mt++) {
                mma_f16(acc[mt][nt], ah[mt], bh2);
                mma_f16(acc[mt][nt], ah[mt], bl2);
                mma_f16(acc[mt][nt], al[mt], bh2);
            }
        }
    }
    #pragma unroll
    for (int mt = 0; mt < 2; mt++)
        #pragma unroll
        for (int nt = 0; nt < 4; nt++) {
            const int r = wm * 32 + mt * 16 + grp;
            const int c = wn * 32 + nt * 8 + tig * 2;
            const float i0 = inv[r], i1 = inv[r + 8];
            __half* d0 = g_qkv + (size_t)(b * NN + n0 + r) * INNER + h * 64 + c;
            __half* d1 = g_qkv + (size_t)(b * NN + n0 + r + 8) * INNER + h * 64 + c;
            *(__half2*)d0 = __floats2half2_rn(acc[mt][nt][0] * i0, acc[mt][nt][1] * i0);
            *(__half2*)d1 = __floats2half2_rn(acc[mt][nt][2] * i1, acc[mt][nt][3] * i1);
        }
}

// ------------------------------------------------------------------------------
extern "C" void kernel_launch(void* const* d_in, const int* in_sizes, int n_in,
                              void* d_out, int out_size) {
    const float* x      = (const float*)d_in[0];
    const float* conv_w = (const float*)d_in[1];
    const float* conv_b = (const float*)d_in[2];
    const float* Wq     = (const float*)d_in[3];
    const float* Wk     = (const float*)d_in[4];
    const float* Wv     = (const float*)d_in[5];
    const float* W1     = (const float*)d_in[6];
    const float* b1     = (const float*)d_in[7];
    const float* W2     = (const float*)d_in[8];
    const float* b2     = (const float*)d_in[9];
    float* out = (float*)d_out;

    cudaFuncSetAttribute(k_conv, cudaFuncAttributeMaxDynamicSharedMemorySize, 110592);
    cudaFuncSetAttribute(k_mlp<0>, cudaFuncAttributeMaxDynamicSharedMemorySize, 110592);
    cudaFuncSetAttribute(k_mlp<1>, cudaFuncAttributeMaxDynamicSharedMemorySize, 110592);
    cudaFuncSetAttribute(k_kv,   cudaFuncAttributeMaxDynamicSharedMemorySize, 82944);
    cudaFuncSetAttribute(k_qkv,  cudaFuncAttributeMaxDynamicSharedMemorySize, 93184);

    k_wprep<<<(INNER * KCONV + 255) / 256, 256>>>(conv_w);
    k_xprep<<<((BB * NN * CC) / 4 + 255) / 256, 256>>>(x);
    k_wmlp<<<(CC * INNER + 255) / 256, 256>>>(W1, W2);
    k_init<<<(BB * HEADS * KRR * DHH) / 256, 256>>>();
    k_conv<<<dim3(INNER / 128, (BB * NN) / 128), 256, 110592>>>(conv_b);
    k_kv<<<dim3(8, BB * HEADS), 256, 82944>>>(Wk, Wv);
    k_kvnorm<<<(BB * HEADS * KRR * DHH) / 256, 256>>>();
    k_qkv<<<dim3(128, BB * HEADS), 256, 93184>>>(Wq);
    k_mlp<0><<<dim3(CC / 128, (BB * NN) / 128), 256, 110592>>>(b1, nullptr);
    k_mlp<1><<<dim3(CC / 128, (BB * NN) / 128), 256, 110592>>>(b2, out);
}

// round 9
// speedup vs baseline: 8.7472x; 1.2714x over previous
#include <cuda_runtime.h>
#include <cuda_fp16.h>
#include <math.h>

#define BB 8
#define CC 256
#define NN 16384
#define HEADS 8
#define INNER 512
#define KCONV 2304
#define KRR 64
#define DHH 64

__device__ __half g_wch[(size_t)INNER * KCONV];
__device__ __half g_xh[(size_t)BB * NN * CC];
__device__ __half g_w1h[CC * INNER];
__device__ __half g_w2h[CC * CC];
__device__ __half g_xc[(size_t)BB * NN * INNER];
__device__ float  g_colsum[BB * HEADS * KRR];
__device__ float  g_kv[BB * HEADS * KRR * DHH];
__device__ __half g_qkv[(size_t)BB * NN * INNER];
__device__ __half g_h1[(size_t)BB * NN * CC];

__device__ __forceinline__ void mma_f16(float c[4], const unsigned a[4], const unsigned b[2]) {
    asm volatile("mma.sync.aligned.m16n8k16.row.col.f32.f16.f16.f32 "
        "{%0,%1,%2,%3}, {%4,%5,%6,%7}, {%8,%9}, {%0,%1,%2,%3};"
        : "+f"(c[0]), "+f"(c[1]), "+f"(c[2]), "+f"(c[3])
        : "r"(a[0]), "r"(a[1]), "r"(a[2]), "r"(a[3]), "r"(b[0]), "r"(b[1]));
}
__device__ __forceinline__ void lm4(unsigned r[4], unsigned a) {
    asm volatile("ldmatrix.sync.aligned.m8n8.x4.shared.b16 {%0,%1,%2,%3}, [%4];"
        : "=r"(r[0]), "=r"(r[1]), "=r"(r[2]), "=r"(r[3]) : "r"(a));
}
template <int STR>
__device__ __forceinline__ void lda16(unsigned a[4], const __half* S, int r, int kc) {
    a[0] = *(const unsigned*)&S[r * STR + kc];
    a[1] = *(const unsigned*)&S[(r + 8) * STR + kc];
    a[2] = *(const unsigned*)&S[r * STR + kc + 8];
    a[3] = *(const unsigned*)&S[(r + 8) * STR + kc + 8];
}
template <int STR>
__device__ __forceinline__ void ldb16(unsigned b[2], const __half* S, int n, int kc) {
    b[0] = *(const unsigned*)&S[n * STR + kc];
    b[1] = *(const unsigned*)&S[n * STR + kc + 8];
}
__device__ __forceinline__ void split_h(float f, __half& hi, __half& lo) {
    hi = __float2half_rn(f);
    lo = __float2half_rn(f - __half2float(hi));
}
__device__ __forceinline__ unsigned smem_u32(const void* p) {
    return (unsigned)__cvta_generic_to_shared(p);
}
__device__ __forceinline__ void cp16(void* dst, const void* src, bool valid) {
    unsigned saddr = smem_u32(dst);
    int sz = valid ? 16 : 0;
    asm volatile("cp.async.ca.shared.global [%0], [%1], 16, %2;"
                 :: "r"(saddr), "l"(src), "r"(sz));
}
__device__ __forceinline__ void cp_commit() { asm volatile("cp.async.commit_group;"); }

// ---------------- prep ---------------------------------------------------------
__global__ void k_wprep(const float* __restrict__ conv_w) {
    int t = blockIdx.x * 256 + threadIdx.x;
    if (t >= INNER * KCONV) return;
    int o = t / KCONV, k = t - o * KCONV;
    g_wch[t] = __float2half_rn(conv_w[(size_t)(o * CC + (k & 255)) * 9 + (k >> 8)]);
}
__global__ void k_xprep(const float* __restrict__ x) {
    int t = blockIdx.x * 256 + threadIdx.x;
    float4 v = ((const float4*)x)[t];
    ((__half2*)g_xh)[t * 2]     = __floats2half2_rn(v.x, v.y);
    ((__half2*)g_xh)[t * 2 + 1] = __floats2half2_rn(v.z, v.w);
}
__global__ void k_wmlp(const float* __restrict__ W1, const float* __restrict__ W2) {
    int t = blockIdx.x * 256 + threadIdx.x;
    g_w1h[t] = __float2half_rn(W1[t]);
    if (t < CC * CC) g_w2h[t] = __float2half_rn(W2[t]);
}
__global__ void k_init() {
    int i = blockIdx.x * 256 + threadIdx.x;
    g_kv[i] = 0.f;
    if (i < BB * HEADS * KRR) g_colsum[i] = 0.f;
}

// ---------------- conv: fp16 mma + ldmatrix, 2-buf cp.async (2 CTA/SM) ---------
// smem halves: A bufs @0,9216; B bufs @18432,27648  (73728 bytes total)
__global__ __launch_bounds__(256) void k_conv(const float* __restrict__ conv_b) {
    extern __shared__ __half sh[];
    const int tid = threadIdx.x, lane = tid & 31, wid = tid >> 5;
    const int wm = wid & 3, wn = wid >> 2;
    const int grp = lane >> 2, tig = lane & 3;
    const int otile = blockIdx.x * 128, mtile = blockIdx.y * 128;
    const int b = mtile >> 14;
    const int lrow = tid >> 1, lhalf = (tid & 1) * 32;
    const int prow = (mtile & (NN - 1)) + lrow;
    const int py = prow >> 7, px = prow & 127;
    const __half* xb = g_xh + (((size_t)b << 14)) * CC;
    const __half* wrow = g_wch + (size_t)(otile + lrow) * KCONV + lhalf;

    // ldmatrix per-lane base addresses (bytes)
    const int a_row = ((lane >> 3) & 1) * 8 + (lane & 7);
    const int a_col = (lane >> 4) * 8;
    const int b_row = (lane >> 4) * 8 + (lane & 7);
    const int b_col = ((lane >> 3) & 1) * 8;
    const unsigned aBase = smem_u32(sh) + ((wm * 32 + a_row) * 72 + a_col) * 2;
    const unsigned bBase = smem_u32(sh) + 36864 + ((wn * 64 + b_row) * 72 + b_col) * 2;

    float acc[2][8][4] = {};

    auto issue = [&](int s) {
        const int buf = s & 1;
        const int g = s >> 2;
        const int dy = g / 3 - 1, dx = g % 3 - 1;
        const int cb = ((s & 3) << 6) + lhalf;
        const int yy = py + dy, xx = px + dx;
        const bool valid = ((unsigned)yy < 128u) && ((unsigned)xx < 128u);
        const __half* asrc = xb + (size_t)((yy << 7) + xx) * CC + cb;
        __half* adst = sh + buf * 9216 + lrow * 72 + lhalf;
        const __half* bsrc = wrow + (s << 6);
        __half* bdst = sh + 18432 + buf * 9216 + lrow * 72 + lhalf;
        #pragma unroll
        for (int j = 0; j < 4; j++) {
            cp16(adst + j * 8, asrc + j * 8, valid);
            cp16(bdst + j * 8, bsrc + j * 8, true);
        }
        cp_commit();
    };

    issue(0);
    for (int s = 0; s < 36; s++) {
        if (s + 1 < 36) { issue(s + 1); asm volatile("cp.async.wait_group 1;"); }
        else            asm volatile("cp.async.wait_group 0;");
        __syncthreads();
        const unsigned bufA = aBase + (s & 1) * 18432;
        const unsigned bufB = bBase + (s & 1) * 18432;
        #pragma unroll
        for (int ks = 0; ks < 4; ks++) {
            const unsigned kcB = ks * 32;
            unsigned a0[4], a1[4];
            lm4(a0, bufA + kcB);
            lm4(a1, bufA + 2304 + kcB);          // +16 rows * 144B
            #pragma unroll
            for (int np = 0; np < 4; np++) {
                unsigned bb[4];
                lm4(bb, bufB + np * 2304 + kcB);
                mma_f16(acc[0][np * 2],     a0, bb);
                mma_f16(acc[1][np * 2],     a1, bb);
                mma_f16(acc[0][np * 2 + 1], a0, bb + 2);
                mma_f16(acc[1][np * 2 + 1], a1, bb + 2);
            }
        }
        __syncthreads();
    }
    #pragma unroll
    for (int mt = 0; mt < 2; mt++)
        #pragma unroll
        for (int nt = 0; nt < 8; nt++) {
            const int r = wm * 32 + mt * 16 + grp;
            const int c = wn * 64 + nt * 8 + tig * 2;
            const float b0 = conv_b[otile + c], b1 = conv_b[otile + c + 1];
            *(__half2*)(g_xc + (size_t)(mtile + r) * INNER + otile + c) =
                __floats2half2_rn(acc[mt][nt][0] + b0, acc[mt][nt][1] + b1);
            *(__half2*)(g_xc + (size_t)(mtile + r + 8) * INNER + otile + c) =
                __floats2half2_rn(acc[mt][nt][2] + b0, acc[mt][nt][3] + b1);
        }
}

// ---------------- MLP: fp16 mma + ldmatrix, 2-buf ------------------------------
template <int MODE>
__global__ __launch_bounds__(256) void k_mlp(const float* __restrict__ bias,
                                             float* __restrict__ out_ext) {
    constexpr int K = MODE ? CC : INNER;
    constexpr int NS = K / 64;
    const __half* A_g = MODE ? g_h1 : g_qkv;
    const __half* B_g = MODE ? g_w2h : g_w1h;

    extern __shared__ __half sh[];
    const int tid = threadIdx.x, lane = tid & 31, wid = tid >> 5;
    const int wm = wid & 3, wn = wid >> 2;
    const int grp = lane >> 2, tig = lane & 3;
    const int otile = blockIdx.x * 128, m0 = blockIdx.y * 128;
    const int lrow = tid >> 1, lhalf = (tid & 1) * 32;
    const __half* arow = A_g + (size_t)(m0 + lrow) * K + lhalf;
    const __half* brow = B_g + (size_t)(otile + lrow) * K + lhalf;

    const int a_row = ((lane >> 3) & 1) * 8 + (lane & 7);
    const int a_col = (lane >> 4) * 8;
    const int b_row = (lane >> 4) * 8 + (lane & 7);
    const int b_col = ((lane >> 3) & 1) * 8;
    const unsigned aBase = smem_u32(sh) + ((wm * 32 + a_row) * 72 + a_col) * 2;
    const unsigned bBase = smem_u32(sh) + 36864 + ((wn * 64 + b_row) * 72 + b_col) * 2;

    float acc[2][8][4] = {};

    auto issue = [&](int s) {
        const int buf = s & 1;
        __half* adst = sh + buf * 9216 + lrow * 72 + lhalf;
        __half* bdst = sh + 18432 + buf * 9216 + lrow * 72 + lhalf;
        #pragma unroll
        for (int j = 0; j < 4; j++) {
            cp16(adst + j * 8, arow + (s << 6) + j * 8, true);
            cp16(bdst + j * 8, brow + (s << 6) + j * 8, true);
        }
        cp_commit();
    };

    issue(0);
    for (int s = 0; s < NS; s++) {
        if (s + 1 < NS) { issue(s + 1); asm volatile("cp.async.wait_group 1;"); }
        else            asm volatile("cp.async.wait_group 0;");
        __syncthreads();
        const unsigned bufA = aBase + (s & 1) * 18432;
        const unsigned bufB = bBase + (s & 1) * 18432;
        #pragma unroll
        for (int ks = 0; ks < 4; ks++) {
            const unsigned kcB = ks * 32;
            unsigned a0[4], a1[4];
            lm4(a0, bufA + kcB);
            lm4(a1, bufA + 2304 + kcB);
            #pragma unroll
            for (int np = 0; np < 4; np++) {
                unsigned bb[4];
                lm4(bb, bufB + np * 2304 + kcB);
                mma_f16(acc[0][np * 2],     a0, bb);
                mma_f16(acc[1][np * 2],     a1, bb);
                mma_f16(acc[0][np * 2 + 1], a0, bb + 2);
                mma_f16(acc[1][np * 2 + 1], a1, bb + 2);
            }
        }
        __syncthreads();
    }
    #pragma unroll
    for (int mt = 0; mt < 2; mt++)
        #pragma unroll
        for (int nt = 0; nt < 8; nt++) {
            const int r = wm * 32 + mt * 16 + grp;
            const int c = wn * 64 + nt * 8 + tig * 2;
            const float b0 = bias[otile + c], b1 = bias[otile + c + 1];
            float v[4] = {acc[mt][nt][0] + b0, acc[mt][nt][1] + b1,
                          acc[mt][nt][2] + b0, acc[mt][nt][3] + b1};
            if (MODE == 0) {
                #pragma unroll
                for (int j = 0; j < 4; j++)
                    v[j] = 0.5f * v[j] * (1.0f + erff(v[j] * 0.70710678118654752f));
                *(__half2*)(g_h1 + (size_t)(m0 + r) * CC + otile + c) =
                    __floats2half2_rn(v[0], v[1]);
                *(__half2*)(g_h1 + (size_t)(m0 + r + 8) * CC + otile + c) =
                    __floats2half2_rn(v[2], v[3]);
            } else {
                *(float2*)(out_ext + (size_t)(m0 + r) * CC + otile + c) =
                    make_float2(v[0], v[1]);
                *(float2*)(out_ext + (size_t)(m0 + r + 8) * CC + otile + c) =
                    make_float2(v[2], v[3]);
            }
        }
}

// ---------------- k_kv: fp16 split mma K,V proj + exp + K^T V ------------------
__global__ __launch_bounds__(256) void k_kv(const float* __restrict__ Wk,
                                            const float* __restrict__ Wv) {
    extern __shared__ __half sh[];
    __half *Xs  = sh;
    __half *Wkh = sh + 4608,  *Wkl = sh + 9216;
    __half *Wvh = sh + 13824, *Wvl = sh + 18432;
    __half *Kth = sh + 23040, *Ktl = sh + 27648;
    __half *Vth = sh + 32256, *Vtl = sh + 36864;

    const int tid = threadIdx.x, lane = tid & 31, wid = tid >> 5;
    const int wm = wid & 3, wn = wid >> 2;
    const int grp = lane >> 2, tig = lane & 3;
    const int bh = blockIdx.y, b = bh >> 3, h = bh & 7;
    const int r = tid >> 2, c0 = (tid & 3) * 16;

    #pragma unroll
    for (int j = 0; j < 16; j++) {
        split_h(Wk[r * 64 + c0 + j], Wkh[r * 72 + c0 + j], Wkl[r * 72 + c0 + j]);
        split_h(Wv[r * 64 + c0 + j], Wvh[r * 72 + c0 + j], Wvl[r * 72 + c0 + j]);
    }

    float kvacc[4][4] = {};
    float csum[8] = {};
    const int mrow = wm * 16 + grp;

    for (int ch = 0; ch < 32; ch++) {
        const int n0 = blockIdx.x * 2048 + ch * 64;
        __syncthreads();
        {
            const __half* xsrc = g_xc + (size_t)(b * NN + n0 + r) * INNER + h * 64 + c0;
            *(uint4*)&Xs[r * 72 + c0]     = *(const uint4*)xsrc;
            *(uint4*)&Xs[r * 72 + c0 + 8] = *(const uint4*)(xsrc + 8);
        }
        __syncthreads();

        float ka[4][4] = {}, va[4][4] = {};
        #pragma unroll
        for (int ks = 0; ks < 4; ks++) {
            const int kc = ks * 16 + tig * 2;
            unsigned a[4], bh2[2], bl2[2];
            lda16<72>(a, Xs, mrow, kc);
            #pragma unroll
            for (int nt = 0; nt < 4; nt++) {
                const int n = wn * 32 + nt * 8 + grp;
                ldb16<72>(bh2, Wkh, n, kc); ldb16<72>(bl2, Wkl, n, kc);
                mma_f16(ka[nt], a, bh2); mma_f16(ka[nt], a, bl2);
                ldb16<72>(bh2, Wvh, n, kc); ldb16<72>(bl2, Wvl, n, kc);
                mma_f16(va[nt], a, bh2); mma_f16(va[nt], a, bl2);
            }
        }
        #pragma unroll
        for (int nt = 0; nt < 4; nt++) {
            const int c = wn * 32 + nt * 8 + tig * 2;
            float e;
            e = __expf(ka[nt][0]); csum[nt*2]   += e; split_h(e, Kth[c*72+mrow],       Ktl[c*72+mrow]);
            e = __expf(ka[nt][1]); csum[nt*2+1] += e; split_h(e, Kth[(c+1)*72+mrow],   Ktl[(c+1)*72+mrow]);
            e = __expf(ka[nt][2]); csum[nt*2]   += e; split_h(e, Kth[c*72+mrow+8],     Ktl[c*72+mrow+8]);
            e = __expf(ka[nt][3]); csum[nt*2+1] += e; split_h(e, Kth[(c+1)*72+mrow+8], Ktl[(c+1)*72+mrow+8]);
            split_h(va[nt][0], Vth[c*72+mrow],       Vtl[c*72+mrow]);
            split_h(va[nt][1], Vth[(c+1)*72+mrow],   Vtl[(c+1)*72+mrow]);
            split_h(va[nt][2], Vth[c*72+mrow+8],     Vtl[c*72+mrow+8]);
            split_h(va[nt][3], Vth[(c+1)*72+mrow+8], Vtl[(c+1)*72+mrow+8]);
        }
        __syncthreads();

        #pragma unroll
        for (int ks = 0; ks < 4; ks++) {
            const int kc = ks * 16 + tig * 2;
            unsigned ah[4], al[4], bh2[2], bl2[2];
            lda16<72>(ah, Kth, mrow, kc);
            lda16<72>(al, Ktl, mrow, kc);
            #pragma unroll
            for (int nt = 0; nt < 4; nt++) {
                const int n = wn * 32 + nt * 8 + grp;
                ldb16<72>(bh2, Vth, n, kc); ldb16<72>(bl2, Vtl, n, kc);
                mma_f16(kvacc[nt], ah, bh2);
                mma_f16(kvacc[nt], ah, bl2);
                mma_f16(kvacc[nt], al, bh2);
            }
        }
    }

    float* kvbase = g_kv + (size_t)bh * (KRR * DHH);
    #pragma unroll
    for (int nt = 0; nt < 4; nt++) {
        const int c = wn * 32 + nt * 8 + tig * 2;
        atomicAdd(kvbase + mrow * 64 + c,           kvacc[nt][0]);
        atomicAdd(kvbase + mrow * 64 + c + 1,       kvacc[nt][1]);
        atomicAdd(kvbase + (mrow + 8) * 64 + c,     kvacc[nt][2]);
        atomicAdd(kvbase + (mrow + 8) * 64 + c + 1, kvacc[nt][3]);
    }
    #pragma unroll
    for (int idx = 0; idx < 8; idx++) {
        const int c = wn * 32 + (idx >> 1) * 8 + tig * 2 + (idx & 1);
        atomicAdd(g_colsum + bh * 64 + c, csum[idx]);
    }
}

__global__ void k_kvnorm() {
    int i = blockIdx.x * 256 + threadIdx.x;
    g_kv[i] = g_kv[i] / g_colsum[i >> 6];
}

// ---------------- k_qkv: fp16 split mma, half output ----------------------------
__global__ __launch_bounds__(256) void k_qkv(const float* __restrict__ Wq) {
    extern __shared__ __half sh[];
    __half *Xs   = sh;
    __half *Qh   = sh + 9216,  *Ql  = sh + 18432;
    __half *Wqh  = sh + 27648, *Wql = sh + 32256;
    __half *kvth = sh + 36864, *kvtl = sh + 41472;
    float  *rsum = (float*)(sh + 46080);
    float  *inv  = rsum + 128;

    const int tid = threadIdx.x, lane = tid & 31, wid = tid >> 5;
    const int wm = wid & 3, wn = wid >> 2;
    const int grp = lane >> 2, tig = lane & 3;
    const int bh = blockIdx.y, b = bh >> 3, h = bh & 7;
    const int n0 = blockIdx.x * 128;

    if (tid < 128) rsum[tid] = 0.f;
    {
        const int r = tid >> 2, c0 = (tid & 3) * 16;
        const float* kvsrc = g_kv + (size_t)bh * (KRR * DHH) + r * 64 + c0;
        #pragma unroll
        for (int j = 0; j < 16; j++) {
            split_h(Wq[r * 64 + c0 + j], Wqh[r * 72 + c0 + j], Wql[r * 72 + c0 + j]);
            split_h(kvsrc[j], kvth[(c0 + j) * 72 + r], kvtl[(c0 + j) * 72 + r]);
        }
    }
    {
        const int xr = tid >> 1, xc0 = (tid & 1) * 32;
        const __half* xsrc = g_xc + (size_t)(b * NN + n0 + xr) * INNER + h * 64 + xc0;
        #pragma unroll
        for (int j = 0; j < 4; j++)
            *(uint4*)&Xs[xr * 72 + xc0 + j * 8] = *(const uint4*)(xsrc + j * 8);
    }
    __syncthreads();

    float qa[2][4][4] = {};
    #pragma unroll
    for (int ks = 0; ks < 4; ks++) {
        const int kc = ks * 16 + tig * 2;
        unsigned a[2][4], bh2[2], bl2[2];
        lda16<72>(a[0], Xs, wm * 32 + grp, kc);
        lda16<72>(a[1], Xs, wm * 32 + 16 + grp, kc);
        #pragma unroll
        for (int nt = 0; nt < 4; nt++) {
            const int n = wn * 32 + nt * 8 + grp;
            ldb16<72>(bh2, Wqh, n, kc); ldb16<72>(bl2, Wql, n, kc);
            #pragma unroll
            for (int mt = 0; mt < 2; mt++) {
                mma_f16(qa[mt][nt], a[mt], bh2);
                mma_f16(qa[mt][nt], a[mt], bl2);
            }
        }
    }
    float rp[2][2] = {};
    #pragma unroll
    for (int mt = 0; mt < 2; mt++)
        #pragma unroll
        for (int nt = 0; nt < 4; nt++) {
            const int r = wm * 32 + mt * 16 + grp;
            const int c = wn * 32 + nt * 8 + tig * 2;
            float e0 = __expf(qa[mt][nt][0]), e1 = __expf(qa[mt][nt][1]);
            float e2 = __expf(qa[mt][nt][2]), e3 = __expf(qa[mt][nt][3]);
            rp[mt][0] += e0 + e1; rp[mt][1] += e2 + e3;
            split_h(e0, Qh[r*72+c],       Ql[r*72+c]);
            split_h(e1, Qh[r*72+c+1],     Ql[r*72+c+1]);
            split_h(e2, Qh[(r+8)*72+c],   Ql[(r+8)*72+c]);
            split_h(e3, Qh[(r+8)*72+c+1], Ql[(r+8)*72+c+1]);
        }
    #pragma unroll
    for (int mt = 0; mt < 2; mt++)
        #pragma unroll
        for (int p = 0; p < 2; p++) {
            float v = rp[mt][p];
            v += __shfl_xor_sync(0xffffffffu, v, 1);
            v += __shfl_xor_sync(0xffffffffu, v, 2);
            if (tig == 0) atomicAdd(&rsum[wm * 32 + mt * 16 + grp + p * 8], v);
        }
    __syncthreads();
    if (tid < 128) inv[tid] = 1.f / rsum[tid];
    __syncthreads();

    float acc[2][4][4] = {};
    #pragma unroll
    for (int ks = 0; ks < 4; ks++) {
        const int kc = ks * 16 + tig * 2;
        unsigned ah[2][4], al[2][4], bh2[2], bl2[2];
        #pragma unroll
        for (int mt = 0; mt < 2; mt++) {
            lda16<72>(ah[mt], Qh, wm * 32 + mt * 16 + grp, kc);
            lda16<72>(al[mt], Ql, wm * 32 + mt * 16 + grp, kc);
        }
        #pragma unroll
        for (int nt = 0; nt < 4; nt++) {
            const int n = wn * 32 + nt * 8 + grp;
            ldb16<72>(bh2, kvth, n, kc); ldb16<72>(bl2, kvtl, n, kc);
            #pragma unroll
            for (int mt = 0; mt < 2; mt++) {
                mma_f16(acc[mt][nt], ah[mt], bh2);
                mma_f16(acc[mt][nt], ah[mt], bl2);
                mma_f16(acc[mt][nt], al[mt], bh2);
            }
        }
    }
    #pragma unroll
    for (int mt = 0; mt < 2; mt++)
        #pragma unroll
        for (int nt = 0; nt < 4; nt++) {
            const int r = wm * 32 + mt * 16 + grp;
            const int c = wn * 32 + nt * 8 + tig * 2;
            const float i0 = inv[r], i1 = inv[r + 8];
            __half* d0 = g_qkv + (size_t)(b * NN + n0 + r) * INNER + h * 64 + c;
            __half* d1 = g_qkv + (size_t)(b * NN + n0 + r + 8) * INNER + h * 64 + c;
            *(__half2*)d0 = __floats2half2_rn(acc[mt][nt][0] * i0, acc[mt][nt][1] * i0);
            *(__half2*)d1 = __floats2half2_rn(acc[mt][nt][2] * i1, acc[mt][nt][3] * i1);
        }
}

// ------------------------------------------------------------------------------
extern "C" void kernel_launch(void* const* d_in, const int* in_sizes, int n_in,
                              void* d_out, int out_size) {
    const float* x      = (const float*)d_in[0];
    const float* conv_w = (const float*)d_in[1];
    const float* conv_b = (const float*)d_in[2];
    const float* Wq     = (const float*)d_in[3];
    const float* Wk     = (const float*)d_in[4];
    const float* Wv     = (const float*)d_in[5];
    const float* W1     = (const float*)d_in[6];
    const float* b1     = (const float*)d_in[7];
    const float* W2     = (const float*)d_in[8];
    const float* b2     = (const float*)d_in[9];
    float* out = (float*)d_out;

    cudaFuncSetAttribute(k_conv, cudaFuncAttributeMaxDynamicSharedMemorySize, 73728);
    cudaFuncSetAttribute(k_mlp<0>, cudaFuncAttributeMaxDynamicSharedMemorySize, 73728);
    cudaFuncSetAttribute(k_mlp<1>, cudaFuncAttributeMaxDynamicSharedMemorySize, 73728);
    cudaFuncSetAttribute(k_kv,   cudaFuncAttributeMaxDynamicSharedMemorySize, 82944);
    cudaFuncSetAttribute(k_qkv,  cudaFuncAttributeMaxDynamicSharedMemorySize, 93184);

    k_wprep<<<(INNER * KCONV + 255) / 256, 256>>>(conv_w);
    k_xprep<<<((BB * NN * CC) / 4 + 255) / 256, 256>>>(x);
    k_wmlp<<<(CC * INNER + 255) / 256, 256>>>(W1, W2);
    k_init<<<(BB * HEADS * KRR * DHH) / 256, 256>>>();
    k_conv<<<dim3(INNER / 128, (BB * NN) / 128), 256, 73728>>>(conv_b);
    k_kv<<<dim3(8, BB * HEADS), 256, 82944>>>(Wk, Wv);
    k_kvnorm<<<(BB * HEADS * KRR * DHH) / 256, 256>>>();
    k_qkv<<<dim3(128, BB * HEADS), 256, 93184>>>(Wq);
    k_mlp<0><<<dim3(CC / 128, (BB * NN) / 128), 256, 73728>>>(b1, nullptr);
    k_mlp<1><<<dim3(CC / 128, (BB * NN) / 128), 256, 73728>>>(b2, out);
}

// round 10
// speedup vs baseline: 12.3914x; 1.4166x over previous
#include <cuda_runtime.h>
#include <cuda.h>
#include <cuda_fp16.h>
#include <math.h>

#define BB 8
#define CC 256
#define NN 16384
#define HEADS 8
#define INNER 512
#define KCONV 2304
#define KRR 64
#define DHH 64

__device__ __half g_wch[(size_t)INNER * KCONV];
__device__ __half g_xh[(size_t)BB * NN * CC];
__device__ __half g_w1h[CC * INNER];
__device__ __half g_w2h[CC * CC];
__device__ __half g_xc[(size_t)BB * NN * INNER];
__device__ float  g_colsum[BB * HEADS * KRR];
__device__ float  g_kv[BB * HEADS * KRR * DHH];
__device__ __half g_qkv[(size_t)BB * NN * INNER];
__device__ __half g_h1[(size_t)BB * NN * CC];

__device__ __forceinline__ void mma_f16(float c[4], const unsigned a[4], const unsigned b[2]) {
    asm volatile("mma.sync.aligned.m16n8k16.row.col.f32.f16.f16.f32 "
        "{%0,%1,%2,%3}, {%4,%5,%6,%7}, {%8,%9}, {%0,%1,%2,%3};"
        : "+f"(c[0]), "+f"(c[1]), "+f"(c[2]), "+f"(c[3])
        : "r"(a[0]), "r"(a[1]), "r"(a[2]), "r"(a[3]), "r"(b[0]), "r"(b[1]));
}
__device__ __forceinline__ void lm4(unsigned r[4], unsigned a) {
    asm volatile("ldmatrix.sync.aligned.m8n8.x4.shared.b16 {%0,%1,%2,%3}, [%4];"
        : "=r"(r[0]), "=r"(r[1]), "=r"(r[2]), "=r"(r[3]) : "r"(a));
}
template <int STR>
__device__ __forceinline__ void lda16(unsigned a[4], const __half* S, int r, int kc) {
    a[0] = *(const unsigned*)&S[r * STR + kc];
    a[1] = *(const unsigned*)&S[(r + 8) * STR + kc];
    a[2] = *(const unsigned*)&S[r * STR + kc + 8];
    a[3] = *(const unsigned*)&S[(r + 8) * STR + kc + 8];
}
template <int STR>
__device__ __forceinline__ void ldb16(unsigned b[2], const __half* S, int n, int kc) {
    b[0] = *(const unsigned*)&S[n * STR + kc];
    b[1] = *(const unsigned*)&S[n * STR + kc + 8];
}
__device__ __forceinline__ void split_h(float f, __half& hi, __half& lo) {
    hi = __float2half_rn(f);
    lo = __float2half_rn(f - __half2float(hi));
}
__device__ __forceinline__ unsigned smem_u32(const void* p) {
    return (unsigned)__cvta_generic_to_shared(p);
}
__device__ __forceinline__ void mb_init(unsigned a, unsigned n) {
    asm volatile("mbarrier.init.shared.b64 [%0], %1;" :: "r"(a), "r"(n) : "memory");
}
__device__ __forceinline__ void mb_expect(unsigned a, unsigned bytes) {
    asm volatile("mbarrier.arrive.expect_tx.shared.b64 _, [%0], %1;"
                 :: "r"(a), "r"(bytes) : "memory");
}
__device__ __forceinline__ void mb_wait(unsigned a, unsigned ph) {
    asm volatile("{\n\t.reg .pred P;\n\tW%=:\n\t"
                 "mbarrier.try_wait.parity.shared.b64 P, [%0], %1;\n\t"
                 "@!P bra W%=;\n\t}" :: "r"(a), "r"(ph) : "memory");
}
__device__ __forceinline__ void tma4d(unsigned dst, const CUtensorMap* m,
                                      int c0, int c1, int c2, int c3, unsigned mb) {
    asm volatile("cp.async.bulk.tensor.4d.shared::cta.global.tile.mbarrier::complete_tx::bytes"
                 " [%0], [%1, {%2,%3,%4,%5}], [%6];"
                 :: "r"(dst), "l"(m), "r"(c0), "r"(c1), "r"(c2), "r"(c3), "r"(mb) : "memory");
}
__device__ __forceinline__ void tma2d(unsigned dst, const CUtensorMap* m,
                                      int c0, int c1, unsigned mb) {
    asm volatile("cp.async.bulk.tensor.2d.shared::cta.global.tile.mbarrier::complete_tx::bytes"
                 " [%0], [%1, {%2,%3}], [%4];"
                 :: "r"(dst), "l"(m), "r"(c0), "r"(c1), "r"(mb) : "memory");
}

// ---------------- prep ---------------------------------------------------------
__global__ void k_wprep(const float* __restrict__ conv_w) {
    int t = blockIdx.x * 256 + threadIdx.x;
    if (t >= INNER * KCONV) return;
    int o = t / KCONV, k = t - o * KCONV;
    g_wch[t] = __float2half_rn(conv_w[(size_t)(o * CC + (k & 255)) * 9 + (k >> 8)]);
}
__global__ void k_xprep(const float* __restrict__ x) {
    int t = blockIdx.x * 256 + threadIdx.x;
    float4 v = ((const float4*)x)[t];
    ((__half2*)g_xh)[t * 2]     = __floats2half2_rn(v.x, v.y);
    ((__half2*)g_xh)[t * 2 + 1] = __floats2half2_rn(v.z, v.w);
}
__global__ void k_wmlp(const float* __restrict__ W1, const float* __restrict__ W2) {
    int t = blockIdx.x * 256 + threadIdx.x;
    g_w1h[t] = __float2half_rn(W1[t]);
    if (t < CC * CC) g_w2h[t] = __float2half_rn(W2[t]);
}
__global__ void k_init() {
    int i = blockIdx.x * 256 + threadIdx.x;
    g_kv[i] = 0.f;
    if (i < BB * HEADS * KRR) g_colsum[i] = 0.f;
}

// ---------------- conv: fp16 mma + ldmatrix, TMA double-buffered ---------------
// smem: [0..1024) mbarriers; A bufs @1024,17408; B bufs @33792,50176 (66560 B)
__global__ __launch_bounds__(256) void k_conv(
    const __grid_constant__ CUtensorMap mA,
    const __grid_constant__ CUtensorMap mB,
    const float* __restrict__ conv_b) {
    extern __shared__ __align__(1024) char smc[];
    const unsigned sbase = smem_u32(smc);
    const int tid = threadIdx.x, lane = tid & 31, wid = tid >> 5;
    const int wm = wid & 3, wn = wid >> 2;
    const int grp = lane >> 2, tig = lane & 3;
    const int otile = blockIdx.x * 128, mtile = blockIdx.y * 128;
    const int b = mtile >> 14;
    const int py = (mtile & (NN - 1)) >> 7;

    if (tid == 0) { mb_init(sbase, 1); mb_init(sbase + 8, 1); }
    __syncthreads();

    // ldmatrix per-lane swizzled addressing
    const int a_r = (lane & 7) + ((lane >> 3) & 1) * 8;     // 0..15
    const unsigned a_kb = (lane >> 4) * 16;                 // 0 or 16 bytes
    const unsigned axor = (unsigned)(a_r & 7) << 4;
    const int b_r = (lane & 7) + (lane >> 4) * 8;           // 0..15
    const unsigned b_kb = ((lane >> 3) & 1) * 16;
    const unsigned bxor = (unsigned)(b_r & 7) << 4;
    const unsigned Abase0 = sbase + 1024;
    const unsigned Bbase0 = sbase + 33792;

    float acc[2][8][4] = {};

    auto issue = [&](int s) {
        const int p = s & 1;
        const int g = s >> 2;
        const int dy = g / 3 - 1, dx = g % 3 - 1;
        const int cb = (s & 3) * 64;
        mb_expect(sbase + p * 8, 32768);
        tma4d(Abase0 + p * 16384, &mA, cb, dx, py + dy, b, sbase + p * 8);
        tma2d(Bbase0 + p * 16384, &mB, g * 256 + cb, otile, sbase + p * 8);
    };

    if (tid == 0) issue(0);
    for (int s = 0; s < 36; s++) {
        const int p = s & 1;
        if (s + 1 < 36 && tid == 0) issue(s + 1);
        mb_wait(sbase + p * 8, (s >> 1) & 1);
        const unsigned Ab = Abase0 + p * 16384;
        const unsigned Bb = Bbase0 + p * 16384;
        #pragma unroll
        for (int ks = 0; ks < 4; ks++) {
            const unsigned ak = ((unsigned)(ks * 32) + a_kb) ^ axor;
            const unsigned bk = ((unsigned)(ks * 32) + b_kb) ^ bxor;
            unsigned a0[4], a1[4];
            lm4(a0, Ab + (unsigned)(wm * 32 + a_r) * 128 + ak);
            lm4(a1, Ab + (unsigned)(wm * 32 + 16 + a_r) * 128 + ak);
            #pragma unroll
            for (int np = 0; np < 4; np++) {
                unsigned bb[4];
                lm4(bb, Bb + (unsigned)(wn * 64 + np * 16 + b_r) * 128 + bk);
                mma_f16(acc[0][np * 2],     a0, bb);
                mma_f16(acc[1][np * 2],     a1, bb);
                mma_f16(acc[0][np * 2 + 1], a0, bb + 2);
                mma_f16(acc[1][np * 2 + 1], a1, bb + 2);
            }
        }
        __syncthreads();
    }
    #pragma unroll
    for (int mt = 0; mt < 2; mt++)
        #pragma unroll
        for (int nt = 0; nt < 8; nt++) {
            const int r = wm * 32 + mt * 16 + grp;
            const int c = wn * 64 + nt * 8 + tig * 2;
            const float b0 = conv_b[otile + c], b1 = conv_b[otile + c + 1];
            *(__half2*)(g_xc + (size_t)(mtile + r) * INNER + otile + c) =
                __floats2half2_rn(acc[mt][nt][0] + b0, acc[mt][nt][1] + b1);
            *(__half2*)(g_xc + (size_t)(mtile + r + 8) * INNER + otile + c) =
                __floats2half2_rn(acc[mt][nt][2] + b0, acc[mt][nt][3] + b1);
        }
}

// ---------------- MLP: fp16 mma + ldmatrix, TMA double-buffered ----------------
template <int MODE>
__global__ __launch_bounds__(256) void k_mlp(
    const __grid_constant__ CUtensorMap mA,
    const __grid_constant__ CUtensorMap mB,
    const float* __restrict__ bias,
    float* __restrict__ out_ext) {
    constexpr int K = MODE ? CC : INNER;
    constexpr int NS = K / 64;
    extern __shared__ __align__(1024) char smc[];
    const unsigned sbase = smem_u32(smc);
    const int tid = threadIdx.x, lane = tid & 31, wid = tid >> 5;
    const int wm = wid & 3, wn = wid >> 2;
    const int grp = lane >> 2, tig = lane & 3;
    const int otile = blockIdx.x * 128, m0 = blockIdx.y * 128;

    if (tid == 0) { mb_init(sbase, 1); mb_init(sbase + 8, 1); }
    __syncthreads();

    const int a_r = (lane & 7) + ((lane >> 3) & 1) * 8;
    const unsigned a_kb = (lane >> 4) * 16;
    const unsigned axor = (unsigned)(a_r & 7) << 4;
    const int b_r = (lane & 7) + (lane >> 4) * 8;
    const unsigned b_kb = ((lane >> 3) & 1) * 16;
    const unsigned bxor = (unsigned)(b_r & 7) << 4;
    const unsigned Abase0 = sbase + 1024;
    const unsigned Bbase0 = sbase + 33792;

    float acc[2][8][4] = {};

    auto issue = [&](int s) {
        const int p = s & 1;
        mb_expect(sbase + p * 8, 32768);
        tma2d(Abase0 + p * 16384, &mA, s * 64, m0, sbase + p * 8);
        tma2d(Bbase0 + p * 16384, &mB, s * 64, otile, sbase + p * 8);
    };

    if (tid == 0) issue(0);
    for (int s = 0; s < NS; s++) {
        const int p = s & 1;
        if (s + 1 < NS && tid == 0) issue(s + 1);
        mb_wait(sbase + p * 8, (s >> 1) & 1);
        const unsigned Ab = Abase0 + p * 16384;
        const unsigned Bb = Bbase0 + p * 16384;
        #pragma unroll
        for (int ks = 0; ks < 4; ks++) {
            const unsigned ak = ((unsigned)(ks * 32) + a_kb) ^ axor;
            const unsigned bk = ((unsigned)(ks * 32) + b_kb) ^ bxor;
            unsigned a0[4], a1[4];
            lm4(a0, Ab + (unsigned)(wm * 32 + a_r) * 128 + ak);
            lm4(a1, Ab + (unsigned)(wm * 32 + 16 + a_r) * 128 + ak);
            #pragma unroll
            for (int np = 0; np < 4; np++) {
                unsigned bb[4];
                lm4(bb, Bb + (unsigned)(wn * 64 + np * 16 + b_r) * 128 + bk);
                mma_f16(acc[0][np * 2],     a0, bb);
                mma_f16(acc[1][np * 2],     a1, bb);
                mma_f16(acc[0][np * 2 + 1], a0, bb + 2);
                mma_f16(acc[1][np * 2 + 1], a1, bb + 2);
            }
        }
        __syncthreads();
    }
    #pragma unroll
    for (int mt = 0; mt < 2; mt++)
        #pragma unroll
        for (int nt = 0; nt < 8; nt++) {
            const int r = wm * 32 + mt * 16 + grp;
            const int c = wn * 64 + nt * 8 + tig * 2;
            const float b0 = bias[otile + c], b1 = bias[otile + c + 1];
            float v[4] = {acc[mt][nt][0] + b0, acc[mt][nt][1] + b1,
                          acc[mt][nt][2] + b0, acc[mt][nt][3] + b1};
            if (MODE == 0) {
                #pragma unroll
                for (int j = 0; j < 4; j++)
                    v[j] = 0.5f * v[j] * (1.0f + erff(v[j] * 0.70710678118654752f));
                *(__half2*)(g_h1 + (size_t)(m0 + r) * CC + otile + c) =
                    __floats2half2_rn(v[0], v[1]);
                *(__half2*)(g_h1 + (size_t)(m0 + r + 8) * CC + otile + c) =
                    __floats2half2_rn(v[2], v[3]);
            } else {
                *(float2*)(out_ext + (size_t)(m0 + r) * CC + otile + c) =
                    make_float2(v[0], v[1]);
                *(float2*)(out_ext + (size_t)(m0 + r + 8) * CC + otile + c) =
                    make_float2(v[2], v[3]);
            }
        }
}

// ---------------- k_kv: fp16 split mma K,V proj + exp + K^T V (unchanged) ------
__global__ __launch_bounds__(256) void k_kv(const float* __restrict__ Wk,
                                            const float* __restrict__ Wv) {
    extern __shared__ __half sh[];
    __half *Xs  = sh;
    __half *Wkh = sh + 4608,  *Wkl = sh + 9216;
    __half *Wvh = sh + 13824, *Wvl = sh + 18432;
    __half *Kth = sh + 23040, *Ktl = sh + 27648;
    __half *Vth = sh + 32256, *Vtl = sh + 36864;

    const int tid = threadIdx.x, lane = tid & 31, wid = tid >> 5;
    const int wm = wid & 3, wn = wid >> 2;
    const int grp = lane >> 2, tig = lane & 3;
    const int bh = blockIdx.y, b = bh >> 3, h = bh & 7;
    const int r = tid >> 2, c0 = (tid & 3) * 16;

    #pragma unroll
    for (int j = 0; j < 16; j++) {
        split_h(Wk[r * 64 + c0 + j], Wkh[r * 72 + c0 + j], Wkl[r * 72 + c0 + j]);
        split_h(Wv[r * 64 + c0 + j], Wvh[r * 72 + c0 + j], Wvl[r * 72 + c0 + j]);
    }

    float kvacc[4][4] = {};
    float csum[8] = {};
    const int mrow = wm * 16 + grp;

    for (int ch = 0; ch < 32; ch++) {
        const int n0 = blockIdx.x * 2048 + ch * 64;
        __syncthreads();
        {
            const __half* xsrc = g_xc + (size_t)(b * NN + n0 + r) * INNER + h * 64 + c0;
            *(uint4*)&Xs[r * 72 + c0]     = *(const uint4*)xsrc;
            *(uint4*)&Xs[r * 72 + c0 + 8] = *(const uint4*)(xsrc + 8);
        }
        __syncthreads();

        float ka[4][4] = {}, va[4][4] = {};
        #pragma unroll
        for (int ks = 0; ks < 4; ks++) {
            const int kc = ks * 16 + tig * 2;
            unsigned a[4], bh2[2], bl2[2];
            lda16<72>(a, Xs, mrow, kc);
            #pragma unroll
            for (int nt = 0; nt < 4; nt++) {
                const int n = wn * 32 + nt * 8 + grp;
                ldb16<72>(bh2, Wkh, n, kc); ldb16<72>(bl2, Wkl, n, kc);
                mma_f16(ka[nt], a, bh2); mma_f16(ka[nt], a, bl2);
                ldb16<72>(bh2, Wvh, n, kc); ldb16<72>(bl2, Wvl, n, kc);
                mma_f16(va[nt], a, bh2); mma_f16(va[nt], a, bl2);
            }
        }
        #pragma unroll
        for (int nt = 0; nt < 4; nt++) {
            const int c = wn * 32 + nt * 8 + tig * 2;
            float e;
            e = __expf(ka[nt][0]); csum[nt*2]   += e; split_h(e, Kth[c*72+mrow],       Ktl[c*72+mrow]);
            e = __expf(ka[nt][1]); csum[nt*2+1] += e; split_h(e, Kth[(c+1)*72+mrow],   Ktl[(c+1)*72+mrow]);
            e = __expf(ka[nt][2]); csum[nt*2]   += e; split_h(e, Kth[c*72+mrow+8],     Ktl[c*72+mrow+8]);
            e = __expf(ka[nt][3]); csum[nt*2+1] += e; split_h(e, Kth[(c+1)*72+mrow+8], Ktl[(c+1)*72+mrow+8]);
            split_h(va[nt][0], Vth[c*72+mrow],       Vtl[c*72+mrow]);
            split_h(va[nt][1], Vth[(c+1)*72+mrow],   Vtl[(c+1)*72+mrow]);
            split_h(va[nt][2], Vth[c*72+mrow+8],     Vtl[c*72+mrow+8]);
            split_h(va[nt][3], Vth[(c+1)*72+mrow+8], Vtl[(c+1)*72+mrow+8]);
        }
        __syncthreads();

        #pragma unroll
        for (int ks = 0; ks < 4; ks++) {
            const int kc = ks * 16 + tig * 2;
            unsigned ah[4], al[4], bh2[2], bl2[2];
            lda16<72>(ah, Kth, mrow, kc);
            lda16<72>(al, Ktl, mrow, kc);
            #pragma unroll
            for (int nt = 0; nt < 4; nt++) {
                const int n = wn * 32 + nt * 8 + grp;
                ldb16<72>(bh2, Vth, n, kc); ldb16<72>(bl2, Vtl, n, kc);
                mma_f16(kvacc[nt], ah, bh2);
                mma_f16(kvacc[nt], ah, bl2);
                mma_f16(kvacc[nt], al, bh2);
            }
        }
    }

    float* kvbase = g_kv + (size_t)bh * (KRR * DHH);
    #pragma unroll
    for (int nt = 0; nt < 4; nt++) {
        const int c = wn * 32 + nt * 8 + tig * 2;
        atomicAdd(kvbase + mrow * 64 + c,           kvacc[nt][0]);
        atomicAdd(kvbase + mrow * 64 + c + 1,       kvacc[nt][1]);
        atomicAdd(kvbase + (mrow + 8) * 64 + c,     kvacc[nt][2]);
        atomicAdd(kvbase + (mrow + 8) * 64 + c + 1, kvacc[nt][3]);
    }
    #pragma unroll
    for (int idx = 0; idx < 8; idx++) {
        const int c = wn * 32 + (idx >> 1) * 8 + tig * 2 + (idx & 1);
        atomicAdd(g_colsum + bh * 64 + c, csum[idx]);
    }
}

__global__ void k_kvnorm() {
    int i = blockIdx.x * 256 + threadIdx.x;
    g_kv[i] = g_kv[i] / g_colsum[i >> 6];
}

// ---------------- k_qkv: fp16 split mma, half output (unchanged) ---------------
__global__ __launch_bounds__(256) void k_qkv(const float* __restrict__ Wq) {
    extern __shared__ __half sh[];
    __half *Xs   = sh;
    __half *Qh   = sh + 9216,  *Ql  = sh + 18432;
    __half *Wqh  = sh + 27648, *Wql = sh + 32256;
    __half *kvth = sh + 36864, *kvtl = sh + 41472;
    float  *rsum = (float*)(sh + 46080);
    float  *inv  = rsum + 128;

    const int tid = threadIdx.x, lane = tid & 31, wid = tid >> 5;
    const int wm = wid & 3, wn = wid >> 2;
    const int grp = lane >> 2, tig = lane & 3;
    const int bh = blockIdx.y, b = bh >> 3, h = bh & 7;
    const int n0 = blockIdx.x * 128;

    if (tid < 128) rsum[tid] = 0.f;
    {
        const int r = tid >> 2, c0 = (tid & 3) * 16;
        const float* kvsrc = g_kv + (size_t)bh * (KRR * DHH) + r * 64 + c0;
        #pragma unroll
        for (int j = 0; j < 16; j++) {
            split_h(Wq[r * 64 + c0 + j], Wqh[r * 72 + c0 + j], Wql[r * 72 + c0 + j]);
            split_h(kvsrc[j], kvth[(c0 + j) * 72 + r], kvtl[(c0 + j) * 72 + r]);
        }
    }
    {
        const int xr = tid >> 1, xc0 = (tid & 1) * 32;
        const __half* xsrc = g_xc + (size_t)(b * NN + n0 + xr) * INNER + h * 64 + xc0;
        #pragma unroll
        for (int j = 0; j < 4; j++)
            *(uint4*)&Xs[xr * 72 + xc0 + j * 8] = *(const uint4*)(xsrc + j * 8);
    }
    __syncthreads();

    float qa[2][4][4] = {};
    #pragma unroll
    for (int ks = 0; ks < 4; ks++) {
        const int kc = ks * 16 + tig * 2;
        unsigned a[2][4], bh2[2], bl2[2];
        lda16<72>(a[0], Xs, wm * 32 + grp, kc);
        lda16<72>(a[1], Xs, wm * 32 + 16 + grp, kc);
        #pragma unroll
        for (int nt = 0; nt < 4; nt++) {
            const int n = wn * 32 + nt * 8 + grp;
            ldb16<72>(bh2, Wqh, n, kc); ldb16<72>(bl2, Wql, n, kc);
            #pragma unroll
            for (int mt = 0; mt < 2; mt++) {
                mma_f16(qa[mt][nt], a[mt], bh2);
                mma_f16(qa[mt][nt], a[mt], bl2);
            }
        }
    }
    float rp[2][2] = {};
    #pragma unroll
    for (int mt = 0; mt < 2; mt++)
        #pragma unroll
        for (int nt = 0; nt < 4; nt++) {
            const int r = wm * 32 + mt * 16 + grp;
            const int c = wn * 32 + nt * 8 + tig * 2;
            float e0 = __expf(qa[mt][nt][0]), e1 = __expf(qa[mt][nt][1]);
            float e2 = __expf(qa[mt][nt][2]), e3 = __expf(qa[mt][nt][3]);
            rp[mt][0] += e0 + e1; rp[mt][1] += e2 + e3;
            split_h(e0, Qh[r*72+c],       Ql[r*72+c]);
            split_h(e1, Qh[r*72+c+1],     Ql[r*72+c+1]);
            split_h(e2, Qh[(r+8)*72+c],   Ql[(r+8)*72+c]);
            split_h(e3, Qh[(r+8)*72+c+1], Ql[(r+8)*72+c+1]);
        }
    #pragma unroll
    for (int mt = 0; mt < 2; mt++)
        #pragma unroll
        for (int p = 0; p < 2; p++) {
            float v = rp[mt][p];
            v += __shfl_xor_sync(0xffffffffu, v, 1);
            v += __shfl_xor_sync(0xffffffffu, v, 2);
            if (tig == 0) atomicAdd(&rsum[wm * 32 + mt * 16 + grp + p * 8], v);
        }
    __syncthreads();
    if (tid < 128) inv[tid] = 1.f / rsum[tid];
    __syncthreads();

    float acc[2][4][4] = {};
    #pragma unroll
    for (int ks = 0; ks < 4; ks++) {
        const int kc = ks * 16 + tig * 2;
        unsigned ah[2][4], al[2][4], bh2[2], bl2[2];
        #pragma unroll
        for (int mt = 0; mt < 2; mt++) {
            lda16<72>(ah[mt], Qh, wm * 32 + mt * 16 + grp, kc);
            lda16<72>(al[mt], Ql, wm * 32 + mt * 16 + grp, kc);
        }
        #pragma unroll
        for (int nt = 0; nt < 4; nt++) {
            const int n = wn * 32 + nt * 8 + grp;
            ldb16<72>(bh2, kvth, n, kc); ldb16<72>(bl2, kvtl, n, kc);
            #pragma unroll
            for (int mt = 0; mt < 2; mt++) {
                mma_f16(acc[mt][nt], ah[mt], bh2);
                mma_f16(acc[mt][nt], ah[mt], bl2);
                mma_f16(acc[mt][nt], al[mt], bh2);
            }
        }
    }
    #pragma unroll
    for (int mt = 0; mt < 2; mt++)
        #pragma unroll
        for (int nt = 0; nt < 4; nt++) {
            const int r = wm * 32 + mt * 16 + grp;
            const int c = wn * 32 + nt * 8 + tig * 2;
            const float i0 = inv[r], i1 = inv[r + 8];
            __half* d0 = g_qkv + (size_t)(b * NN + n0 + r) * INNER + h * 64 + c;
            __half* d1 = g_qkv + (size_t)(b * NN + n0 + r + 8) * INNER + h * 64 + c;
            *(__half2*)d0 = __floats2half2_rn(acc[mt][nt][0] * i0, acc[mt][nt][1] * i0);
            *(__half2*)d1 = __floats2half2_rn(acc[mt][nt][2] * i1, acc[mt][nt][3] * i1);
        }
}

// ------------------------------------------------------------------------------
extern "C" void kernel_launch(void* const* d_in, const int* in_sizes, int n_in,
                              void* d_out, int out_size) {
    const float* x      = (const float*)d_in[0];
    const float* conv_w = (const float*)d_in[1];
    const float* conv_b = (const float*)d_in[2];
    const float* Wq     = (const float*)d_in[3];
    const float* Wk     = (const float*)d_in[4];
    const float* Wv     = (const float*)d_in[5];
    const float* W1     = (const float*)d_in[6];
    const float* b1     = (const float*)d_in[7];
    const float* W2     = (const float*)d_in[8];
    const float* b2     = (const float*)d_in[9];
    float* out = (float*)d_out;

    using EncFn = decltype(&cuTensorMapEncodeTiled);
    static EncFn enc = nullptr;
    if (!enc) {
        void* fp = nullptr;
        cudaDriverEntryPointQueryResult qr;
        cudaGetDriverEntryPointByVersion("cuTensorMapEncodeTiled", &fp, 12000,
                                         cudaEnableDefault, &qr);
        enc = (EncFn)fp;
    }
    static CUtensorMap mCA, mCB, mA0, mB0, mA1, mB1;
    {
        void *xp, *wp, *qkvp, *w1p, *h1p, *w2p;
        cudaGetSymbolAddress(&xp, g_xh);
        cudaGetSymbolAddress(&wp, g_wch);
        cudaGetSymbolAddress(&qkvp, g_qkv);
        cudaGetSymbolAddress(&w1p, g_w1h);
        cudaGetSymbolAddress(&h1p, g_h1);
        cudaGetSymbolAddress(&w2p, g_w2h);
        cuuint32_t e4[4] = {1, 1, 1, 1};
        // conv A: g_xh [b][py][px][ch]
        cuuint64_t dA[4] = {256, 128, 128, 8};
        cuuint64_t sA[3] = {512, 65536, 8388608};
        cuuint32_t bA[4] = {64, 128, 1, 1};
        enc(&mCA, CU_TENSOR_MAP_DATA_TYPE_FLOAT16, 4, xp, dA, sA, bA, e4,
            CU_TENSOR_MAP_INTERLEAVE_NONE, CU_TENSOR_MAP_SWIZZLE_128B,
            CU_TENSOR_MAP_L2_PROMOTION_L2_128B, CU_TENSOR_MAP_FLOAT_OOB_FILL_NONE);
        // conv B: g_wch [o][k]
        cuuint64_t dB[2] = {KCONV, INNER};
        cuuint64_t sB[1] = {KCONV * 2};
        cuuint32_t bB[2] = {64, 128};
        enc(&mCB, CU_TENSOR_MAP_DATA_TYPE_FLOAT16, 2, wp, dB, sB, bB, e4,
            CU_TENSOR_MAP_INTERLEAVE_NONE, CU_TENSOR_MAP_SWIZZLE_128B,
            CU_TENSOR_MAP_L2_PROMOTION_L2_128B, CU_TENSOR_MAP_FLOAT_OOB_FILL_NONE);
        // mlp0: A=g_qkv [131072][512], B=g_w1h [256][512]
        cuuint64_t dA0[2] = {512, 131072}; cuuint64_t sA0[1] = {1024};
        enc(&mA0, CU_TENSOR_MAP_DATA_TYPE_FLOAT16, 2, qkvp, dA0, sA0, bB, e4,
            CU_TENSOR_MAP_INTERLEAVE_NONE, CU_TENSOR_MAP_SWIZZLE_128B,
            CU_TENSOR_MAP_L2_PROMOTION_L2_128B, CU_TENSOR_MAP_FLOAT_OOB_FILL_NONE);
        cuuint64_t dB0[2] = {512, 256}; cuuint64_t sB0[1] = {1024};
        enc(&mB0, CU_TENSOR_MAP_DATA_TYPE_FLOAT16, 2, w1p, dB0, sB0, bB, e4,
            CU_TENSOR_MAP_INTERLEAVE_NONE, CU_TENSOR_MAP_SWIZZLE_128B,
            CU_TENSOR_MAP_L2_PROMOTION_L2_128B, CU_TENSOR_MAP_FLOAT_OOB_FILL_NONE);
        // mlp1: A=g_h1 [131072][256], B=g_w2h [256][256]
        cuuint64_t dA1[2] = {256, 131072}; cuuint64_t sA1[1] = {512};
        enc(&mA1, CU_TENSOR_MAP_DATA_TYPE_FLOAT16, 2, h1p, dA1, sA1, bB, e4,
            CU_TENSOR_MAP_INTERLEAVE_NONE, CU_TENSOR_MAP_SWIZZLE_128B,
            CU_TENSOR_MAP_L2_PROMOTION_L2_128B, CU_TENSOR_MAP_FLOAT_OOB_FILL_NONE);
        cuuint64_t dB1[2] = {256, 256}; cuuint64_t sB1[1] = {512};
        enc(&mB1, CU_TENSOR_MAP_DATA_TYPE_FLOAT16, 2, w2p, dB1, sB1, bB, e4,
            CU_TENSOR_MAP_INTERLEAVE_NONE, CU_TENSOR_MAP_SWIZZLE_128B,
            CU_TENSOR_MAP_L2_PROMOTION_L2_128B, CU_TENSOR_MAP_FLOAT_OOB_FILL_NONE);
    }

    cudaFuncSetAttribute(k_conv, cudaFuncAttributeMaxDynamicSharedMemorySize, 66560);
    cudaFuncSetAttribute(k_mlp<0>, cudaFuncAttributeMaxDynamicSharedMemorySize, 66560);
    cudaFuncSetAttribute(k_mlp<1>, cudaFuncAttributeMaxDynamicSharedMemorySize, 66560);
    cudaFuncSetAttribute(k_kv,   cudaFuncAttributeMaxDynamicSharedMemorySize, 82944);
    cudaFuncSetAttribute(k_qkv,  cudaFuncAttributeMaxDynamicSharedMemorySize, 93184);

    k_wprep<<<(INNER * KCONV + 255) / 256, 256>>>(conv_w);
    k_xprep<<<((BB * NN * CC) / 4 + 255) / 256, 256>>>(x);
    k_wmlp<<<(CC * INNER + 255) / 256, 256>>>(W1, W2);
    k_init<<<(BB * HEADS * KRR * DHH) / 256, 256>>>();
    k_conv<<<dim3(INNER / 128, (BB * NN) / 128), 256, 66560>>>(mCA, mCB, conv_b);
    k_kv<<<dim3(8, BB * HEADS), 256, 82944>>>(Wk, Wv);
    k_kvnorm<<<(BB * HEADS * KRR * DHH) / 256, 256>>>();
    k_qkv<<<dim3(128, BB * HEADS), 256, 93184>>>(Wq);
    k_mlp<0><<<dim3(CC / 128, (BB * NN) / 128), 256, 66560>>>(mA0, mB0, b1, nullptr);
    k_mlp<1><<<dim3(CC / 128, (BB * NN) / 128), 256, 66560>>>(mA1, mB1, b2, out);
}

// round 11
// speedup vs baseline: 14.0605x; 1.1347x over previous
#include <cuda_runtime.h>
#include <cuda.h>
#include <cuda_fp16.h>
#include <math.h>

#define BB 8
#define CC 256
#define NN 16384
#define HEADS 8
#define INNER 512
#define KCONV 2304
#define KRR 64
#define DHH 64

__device__ __half g_wch[(size_t)INNER * KCONV];
__device__ __half g_xh[(size_t)BB * NN * CC];
__device__ __half g_w1h[CC * INNER];
__device__ __half g_w2h[CC * CC];
__device__ __half g_xc[(size_t)BB * NN * INNER];
__device__ float  g_colsum[BB * HEADS * KRR];
__device__ float  g_kv[BB * HEADS * KRR * DHH];
__device__ __half g_qkv[(size_t)BB * NN * INNER];
__device__ __half g_h1[(size_t)BB * NN * CC];
// precomputed hi/lo splits
__device__ __half g_wqh[4096], g_wql[4096], g_wkh[4096], g_wkl[4096];
__device__ __half g_wvh[4096], g_wvl[4096];
__device__ __half g_kvth[64 * 4096], g_kvtl[64 * 4096];   // [bh][dh][kr]

__device__ __forceinline__ void mma_f16(float c[4], const unsigned a[4], const unsigned b[2]) {
    asm volatile("mma.sync.aligned.m16n8k16.row.col.f32.f16.f16.f32 "
        "{%0,%1,%2,%3}, {%4,%5,%6,%7}, {%8,%9}, {%0,%1,%2,%3};"
        : "+f"(c[0]), "+f"(c[1]), "+f"(c[2]), "+f"(c[3])
        : "r"(a[0]), "r"(a[1]), "r"(a[2]), "r"(a[3]), "r"(b[0]), "r"(b[1]));
}
__device__ __forceinline__ void lm4(unsigned r[4], unsigned a) {
    asm volatile("ldmatrix.sync.aligned.m8n8.x4.shared.b16 {%0,%1,%2,%3}, [%4];"
        : "=r"(r[0]), "=r"(r[1]), "=r"(r[2]), "=r"(r[3]) : "r"(a));
}
__device__ __forceinline__ void split_h(float f, __half& hi, __half& lo) {
    hi = __float2half_rn(f);
    lo = __float2half_rn(f - __half2float(hi));
}
__device__ __forceinline__ unsigned smem_u32(const void* p) {
    return (unsigned)__cvta_generic_to_shared(p);
}
__device__ __forceinline__ void mb_init(unsigned a, unsigned n) {
    asm volatile("mbarrier.init.shared.b64 [%0], %1;" :: "r"(a), "r"(n) : "memory");
}
__device__ __forceinline__ void mb_expect(unsigned a, unsigned bytes) {
    asm volatile("mbarrier.arrive.expect_tx.shared.b64 _, [%0], %1;"
                 :: "r"(a), "r"(bytes) : "memory");
}
__device__ __forceinline__ void mb_wait(unsigned a, unsigned ph) {
    asm volatile("{\n\t.reg .pred P;\n\tW%=:\n\t"
                 "mbarrier.try_wait.parity.shared.b64 P, [%0], %1;\n\t"
                 "@!P bra W%=;\n\t}" :: "r"(a), "r"(ph) : "memory");
}
__device__ __forceinline__ void tma4d(unsigned dst, const CUtensorMap* m,
                                      int c0, int c1, int c2, int c3, unsigned mb) {
    asm volatile("cp.async.bulk.tensor.4d.shared::cta.global.tile.mbarrier::complete_tx::bytes"
                 " [%0], [%1, {%2,%3,%4,%5}], [%6];"
                 :: "r"(dst), "l"(m), "r"(c0), "r"(c1), "r"(c2), "r"(c3), "r"(mb) : "memory");
}
__device__ __forceinline__ void tma2d(unsigned dst, const CUtensorMap* m,
                                      int c0, int c1, unsigned mb) {
    asm volatile("cp.async.bulk.tensor.2d.shared::cta.global.tile.mbarrier::complete_tx::bytes"
                 " [%0], [%1, {%2,%3}], [%4];"
                 :: "r"(dst), "l"(m), "r"(c0), "r"(c1), "r"(mb) : "memory");
}

// ---------------- prep ---------------------------------------------------------
__global__ void k_wprep(const float* __restrict__ conv_w) {
    int t = blockIdx.x * 256 + threadIdx.x;
    if (t >= INNER * KCONV) return;
    int o = t / KCONV, k = t - o * KCONV;
    g_wch[t] = __float2half_rn(conv_w[(size_t)(o * CC + (k & 255)) * 9 + (k >> 8)]);
}
__global__ void k_xprep(const float* __restrict__ x) {
    int t = blockIdx.x * 256 + threadIdx.x;
    float4 v = ((const float4*)x)[t];
    ((__half2*)g_xh)[t * 2]     = __floats2half2_rn(v.x, v.y);
    ((__half2*)g_xh)[t * 2 + 1] = __floats2half2_rn(v.z, v.w);
}
__global__ void k_wmlp(const float* __restrict__ W1, const float* __restrict__ W2) {
    int t = blockIdx.x * 256 + threadIdx.x;
    g_w1h[t] = __float2half_rn(W1[t]);
    if (t < CC * CC) g_w2h[t] = __float2half_rn(W2[t]);
}
__global__ void k_wsplit(const float* __restrict__ Wq, const float* __restrict__ Wk,
                         const float* __restrict__ Wv) {
    int t = blockIdx.x * 256 + threadIdx.x;            // 4096
    split_h(Wq[t], g_wqh[t], g_wql[t]);
    split_h(Wk[t], g_wkh[t], g_wkl[t]);
    split_h(Wv[t], g_wvh[t], g_wvl[t]);
}
__global__ void k_init() {
    int i = blockIdx.x * 256 + threadIdx.x;
    g_kv[i] = 0.f;
    if (i < BB * HEADS * KRR) g_colsum[i] = 0.f;
}

// ---------------- conv: fp16 mma + ldmatrix, TMA double-buffered ---------------
__global__ __launch_bounds__(256) void k_conv(
    const __grid_constant__ CUtensorMap mA,
    const __grid_constant__ CUtensorMap mB,
    const float* __restrict__ conv_b) {
    extern __shared__ __align__(1024) char smc[];
    const unsigned sbase = smem_u32(smc);
    const int tid = threadIdx.x, lane = tid & 31, wid = tid >> 5;
    const int wm = wid & 3, wn = wid >> 2;
    const int grp = lane >> 2, tig = lane & 3;
    const int otile = blockIdx.x * 128, mtile = blockIdx.y * 128;
    const int b = mtile >> 14;
    const int py = (mtile & (NN - 1)) >> 7;

    if (tid == 0) { mb_init(sbase, 1); mb_init(sbase + 8, 1); }
    __syncthreads();

    const int a_r = (lane & 7) + ((lane >> 3) & 1) * 8;
    const unsigned a_kb = (lane >> 4) * 16;
    const unsigned axor = (unsigned)(a_r & 7) << 4;
    const int b_r = (lane & 7) + (lane >> 4) * 8;
    const unsigned b_kb = ((lane >> 3) & 1) * 16;
    const unsigned bxor = (unsigned)(b_r & 7) << 4;
    const unsigned Abase0 = sbase + 1024;
    const unsigned Bbase0 = sbase + 33792;

    float acc[2][8][4] = {};

    auto issue = [&](int s) {
        const int p = s & 1;
        const int g = s >> 2;
        const int dy = g / 3 - 1, dx = g % 3 - 1;
        const int cb = (s & 3) * 64;
        mb_expect(sbase + p * 8, 32768);
        tma4d(Abase0 + p * 16384, &mA, cb, dx, py + dy, b, sbase + p * 8);
        tma2d(Bbase0 + p * 16384, &mB, g * 256 + cb, otile, sbase + p * 8);
    };

    if (tid == 0) issue(0);
    for (int s = 0; s < 36; s++) {
        const int p = s & 1;
        if (s + 1 < 36 && tid == 0) issue(s + 1);
        mb_wait(sbase + p * 8, (s >> 1) & 1);
        const unsigned Ab = Abase0 + p * 16384;
        const unsigned Bb = Bbase0 + p * 16384;
        #pragma unroll
        for (int ks = 0; ks < 4; ks++) {
            const unsigned ak = ((unsigned)(ks * 32) + a_kb) ^ axor;
            const unsigned bk = ((unsigned)(ks * 32) + b_kb) ^ bxor;
            unsigned a0[4], a1[4];
            lm4(a0, Ab + (unsigned)(wm * 32 + a_r) * 128 + ak);
            lm4(a1, Ab + (unsigned)(wm * 32 + 16 + a_r) * 128 + ak);
            #pragma unroll
            for (int np = 0; np < 4; np++) {
                unsigned bb[4];
                lm4(bb, Bb + (unsigned)(wn * 64 + np * 16 + b_r) * 128 + bk);
                mma_f16(acc[0][np * 2],     a0, bb);
                mma_f16(acc[1][np * 2],     a1, bb);
                mma_f16(acc[0][np * 2 + 1], a0, bb + 2);
                mma_f16(acc[1][np * 2 + 1], a1, bb + 2);
            }
        }
        __syncthreads();
    }
    #pragma unroll
    for (int mt = 0; mt < 2; mt++)
        #pragma unroll
        for (int nt = 0; nt < 8; nt++) {
            const int r = wm * 32 + mt * 16 + grp;
            const int c = wn * 64 + nt * 8 + tig * 2;
            const float b0 = conv_b[otile + c], b1 = conv_b[otile + c + 1];
            *(__half2*)(g_xc + (size_t)(mtile + r) * INNER + otile + c) =
                __floats2half2_rn(acc[mt][nt][0] + b0, acc[mt][nt][1] + b1);
            *(__half2*)(g_xc + (size_t)(mtile + r + 8) * INNER + otile + c) =
                __floats2half2_rn(acc[mt][nt][2] + b0, acc[mt][nt][3] + b1);
        }
}

// ---------------- MLP: fp16 mma + ldmatrix, TMA double-buffered ----------------
template <int MODE>
__global__ __launch_bounds__(256) void k_mlp(
    const __grid_constant__ CUtensorMap mA,
    const __grid_constant__ CUtensorMap mB,
    const float* __restrict__ bias,
    float* __restrict__ out_ext) {
    constexpr int K = MODE ? CC : INNER;
    constexpr int NS = K / 64;
    extern __shared__ __align__(1024) char smc[];
    const unsigned sbase = smem_u32(smc);
    const int tid = threadIdx.x, lane = tid & 31, wid = tid >> 5;
    const int wm = wid & 3, wn = wid >> 2;
    const int grp = lane >> 2, tig = lane & 3;
    const int otile = blockIdx.x * 128, m0 = blockIdx.y * 128;

    if (tid == 0) { mb_init(sbase, 1); mb_init(sbase + 8, 1); }
    __syncthreads();

    const int a_r = (lane & 7) + ((lane >> 3) & 1) * 8;
    const unsigned a_kb = (lane >> 4) * 16;
    const unsigned axor = (unsigned)(a_r & 7) << 4;
    const int b_r = (lane & 7) + (lane >> 4) * 8;
    const unsigned b_kb = ((lane >> 3) & 1) * 16;
    const unsigned bxor = (unsigned)(b_r & 7) << 4;
    const unsigned Abase0 = sbase + 1024;
    const unsigned Bbase0 = sbase + 33792;

    float acc[2][8][4] = {};

    auto issue = [&](int s) {
        const int p = s & 1;
        mb_expect(sbase + p * 8, 32768);
        tma2d(Abase0 + p * 16384, &mA, s * 64, m0, sbase + p * 8);
        tma2d(Bbase0 + p * 16384, &mB, s * 64, otile, sbase + p * 8);
    };

    if (tid == 0) issue(0);
    for (int s = 0; s < NS; s++) {
        const int p = s & 1;
        if (s + 1 < NS && tid == 0) issue(s + 1);
        mb_wait(sbase + p * 8, (s >> 1) & 1);
        const unsigned Ab = Abase0 + p * 16384;
        const unsigned Bb = Bbase0 + p * 16384;
        #pragma unroll
        for (int ks = 0; ks < 4; ks++) {
            const unsigned ak = ((unsigned)(ks * 32) + a_kb) ^ axor;
            const unsigned bk = ((unsigned)(ks * 32) + b_kb) ^ bxor;
            unsigned a0[4], a1[4];
            lm4(a0, Ab + (unsigned)(wm * 32 + a_r) * 128 + ak);
            lm4(a1, Ab + (unsigned)(wm * 32 + 16 + a_r) * 128 + ak);
            #pragma unroll
            for (int np = 0; np < 4; np++) {
                unsigned bb[4];
                lm4(bb, Bb + (unsigned)(wn * 64 + np * 16 + b_r) * 128 + bk);
                mma_f16(acc[0][np * 2],     a0, bb);
                mma_f16(acc[1][np * 2],     a1, bb);
                mma_f16(acc[0][np * 2 + 1], a0, bb + 2);
                mma_f16(acc[1][np * 2 + 1], a1, bb + 2);
            }
        }
        __syncthreads();
    }
    #pragma unroll
    for (int mt = 0; mt < 2; mt++)
        #pragma unroll
        for (int nt = 0; nt < 8; nt++) {
            const int r = wm * 32 + mt * 16 + grp;
            const int c = wn * 64 + nt * 8 + tig * 2;
            const float b0 = bias[otile + c], b1 = bias[otile + c + 1];
            float v[4] = {acc[mt][nt][0] + b0, acc[mt][nt][1] + b1,
                          acc[mt][nt][2] + b0, acc[mt][nt][3] + b1};
            if (MODE == 0) {
                #pragma unroll
                for (int j = 0; j < 4; j++)
                    v[j] = 0.5f * v[j] * (1.0f + erff(v[j] * 0.70710678118654752f));
                *(__half2*)(g_h1 + (size_t)(m0 + r) * CC + otile + c) =
                    __floats2half2_rn(v[0], v[1]);
                *(__half2*)(g_h1 + (size_t)(m0 + r + 8) * CC + otile + c) =
                    __floats2half2_rn(v[2], v[3]);
            } else {
                *(float2*)(out_ext + (size_t)(m0 + r) * CC + otile + c) =
                    make_float2(v[0], v[1]);
                *(float2*)(out_ext + (size_t)(m0 + r + 8) * CC + otile + c) =
                    make_float2(v[2], v[3]);
            }
        }
}

// ---------------- k_kv: fp16 split mma, ldmatrix fragments ---------------------
__global__ __launch_bounds__(256) void k_kv() {
    extern __shared__ __half sh[];
    __half *Xs  = sh;                               // [64][72]
    __half *Wkh = sh + 4608,  *Wkl = sh + 9216;
    __half *Wvh = sh + 13824, *Wvl = sh + 18432;
    __half *Kth = sh + 23040, *Ktl = sh + 27648;    // [kr][seq]
    __half *Vth = sh + 32256, *Vtl = sh + 36864;    // [dh][seq]

    const int tid = threadIdx.x, lane = tid & 31, wid = tid >> 5;
    const int wm = wid & 3, wn = wid >> 2;
    const int grp = lane >> 2, tig = lane & 3;
    const int bh = blockIdx.y, b = bh >> 3, h = bh & 7;
    const int r = tid >> 2, c0 = (tid & 3) * 16;

    {   // vectorized weight-split loads
        const int gsrc = r * 64 + c0;
        const int sdst = r * 72 + c0;
        *(uint4*)&Wkh[sdst]     = *(const uint4*)&g_wkh[gsrc];
        *(uint4*)&Wkh[sdst + 8] = *(const uint4*)&g_wkh[gsrc + 8];
        *(uint4*)&Wkl[sdst]     = *(const uint4*)&g_wkl[gsrc];
        *(uint4*)&Wkl[sdst + 8] = *(const uint4*)&g_wkl[gsrc + 8];
        *(uint4*)&Wvh[sdst]     = *(const uint4*)&g_wvh[gsrc];
        *(uint4*)&Wvh[sdst + 8] = *(const uint4*)&g_wvh[gsrc + 8];
        *(uint4*)&Wvl[sdst]     = *(const uint4*)&g_wvl[gsrc];
        *(uint4*)&Wvl[sdst + 8] = *(const uint4*)&g_wvl[gsrc + 8];
    }

    // ldmatrix lane offsets (bytes; stride 144 = 72 halves)
    const int la_r = (lane & 7) + ((lane >> 3) & 1) * 8;
    const unsigned a_off = (unsigned)la_r * 144 + (lane >> 4) * 16;
    const int lb_r = (lane & 7) + (lane >> 4) * 8;
    const unsigned b_off = (unsigned)lb_r * 144 + ((lane >> 3) & 1) * 16;
    const unsigned XsU = smem_u32(Xs);
    const unsigned WkhU = smem_u32(Wkh), WklU = smem_u32(Wkl);
    const unsigned WvhU = smem_u32(Wvh), WvlU = smem_u32(Wvl);
    const unsigned KthU = smem_u32(Kth), KtlU = smem_u32(Ktl);
    const unsigned VthU = smem_u32(Vth), VtlU = smem_u32(Vtl);
    const unsigned aTile = (unsigned)(wm * 16) * 144 + a_off;
    const unsigned nb0 = (unsigned)(wn * 32) * 144 + b_off;
    const unsigned nb1 = nb0 + 16u * 144;

    float kvacc[4][4] = {};
    float csum[8] = {};
    const int mrow = wm * 16 + grp;

    for (int ch = 0; ch < 32; ch++) {
        const int n0 = blockIdx.x * 2048 + ch * 64;
        __syncthreads();
        {
            const __half* xsrc = g_xc + (size_t)(b * NN + n0 + r) * INNER + h * 64 + c0;
            *(uint4*)&Xs[r * 72 + c0]     = *(const uint4*)xsrc;
            *(uint4*)&Xs[r * 72 + c0 + 8] = *(const uint4*)(xsrc + 8);
        }
        __syncthreads();

        float ka[4][4] = {}, va[4][4] = {};
        #pragma unroll
        for (int ks = 0; ks < 4; ks++) {
            const unsigned kcB = (unsigned)ks * 32;
            unsigned a[4];
            lm4(a, XsU + aTile + kcB);
            unsigned kh0[4], kh1[4], kl0[4], kl1[4];
            unsigned vh0[4], vh1[4], vl0[4], vl1[4];
            lm4(kh0, WkhU + nb0 + kcB); lm4(kh1, WkhU + nb1 + kcB);
            lm4(kl0, WklU + nb0 + kcB); lm4(kl1, WklU + nb1 + kcB);
            lm4(vh0, WvhU + nb0 + kcB); lm4(vh1, WvhU + nb1 + kcB);
            lm4(vl0, WvlU + nb0 + kcB); lm4(vl1, WvlU + nb1 + kcB);
            mma_f16(ka[0], a, kh0);     mma_f16(ka[0], a, kl0);
            mma_f16(ka[1], a, kh0 + 2); mma_f16(ka[1], a, kl0 + 2);
            mma_f16(ka[2], a, kh1);     mma_f16(ka[2], a, kl1);
            mma_f16(ka[3], a, kh1 + 2); mma_f16(ka[3], a, kl1 + 2);
            mma_f16(va[0], a, vh0);     mma_f16(va[0], a, vl0);
            mma_f16(va[1], a, vh0 + 2); mma_f16(va[1], a, vl0 + 2);
            mma_f16(va[2], a, vh1);     mma_f16(va[2], a, vl1);
            mma_f16(va[3], a, vh1 + 2); mma_f16(va[3], a, vl1 + 2);
        }
        #pragma unroll
        for (int nt = 0; nt < 4; nt++) {
            const int c = wn * 32 + nt * 8 + tig * 2;
            float e;
            e = __expf(ka[nt][0]); csum[nt*2]   += e; split_h(e, Kth[c*72+mrow],       Ktl[c*72+mrow]);
            e = __expf(ka[nt][1]); csum[nt*2+1] += e; split_h(e, Kth[(c+1)*72+mrow],   Ktl[(c+1)*72+mrow]);
            e = __expf(ka[nt][2]); csum[nt*2]   += e; split_h(e, Kth[c*72+mrow+8],     Ktl[c*72+mrow+8]);
            e = __expf(ka[nt][3]); csum[nt*2+1] += e; split_h(e, Kth[(c+1)*72+mrow+8], Ktl[(c+1)*72+mrow+8]);
            split_h(va[nt][0], Vth[c*72+mrow],       Vtl[c*72+mrow]);
            split_h(va[nt][1], Vth[(c+1)*72+mrow],   Vtl[(c+1)*72+mrow]);
            split_h(va[nt][2], Vth[c*72+mrow+8],     Vtl[c*72+mrow+8]);
            split_h(va[nt][3], Vth[(c+1)*72+mrow+8], Vtl[(c+1)*72+mrow+8]);
        }
        __syncthreads();

        #pragma unroll
        for (int ks = 0; ks < 4; ks++) {
            const unsigned kcB = (unsigned)ks * 32;
            unsigned ah[4], al[4];
            lm4(ah, KthU + aTile + kcB);
            lm4(al, KtlU + aTile + kcB);
            unsigned bh0[4], bh1[4], bl0[4], bl1[4];
            lm4(bh0, VthU + nb0 + kcB); lm4(bh1, VthU + nb1 + kcB);
            lm4(bl0, VtlU + nb0 + kcB); lm4(bl1, VtlU + nb1 + kcB);
            mma_f16(kvacc[0], ah, bh0);     mma_f16(kvacc[0], ah, bl0);     mma_f16(kvacc[0], al, bh0);
            mma_f16(kvacc[1], ah, bh0 + 2); mma_f16(kvacc[1], ah, bl0 + 2); mma_f16(kvacc[1], al, bh0 + 2);
            mma_f16(kvacc[2], ah, bh1);     mma_f16(kvacc[2], ah, bl1);     mma_f16(kvacc[2], al, bh1);
            mma_f16(kvacc[3], ah, bh1 + 2); mma_f16(kvacc[3], ah, bl1 + 2); mma_f16(kvacc[3], al, bh1 + 2);
        }
    }

    float* kvbase = g_kv + (size_t)bh * (KRR * DHH);
    #pragma unroll
    for (int nt = 0; nt < 4; nt++) {
        const int c = wn * 32 + nt * 8 + tig * 2;
        atomicAdd(kvbase + mrow * 64 + c,           kvacc[nt][0]);
        atomicAdd(kvbase + mrow * 64 + c + 1,       kvacc[nt][1]);
        atomicAdd(kvbase + (mrow + 8) * 64 + c,     kvacc[nt][2]);
        atomicAdd(kvbase + (mrow + 8) * 64 + c + 1, kvacc[nt][3]);
    }
    #pragma unroll
    for (int idx = 0; idx < 8; idx++) {
        const int c = wn * 32 + (idx >> 1) * 8 + tig * 2 + (idx & 1);
        atomicAdd(g_colsum + bh * 64 + c, csum[idx]);
    }
}

// ---------------- kv normalize + transpose + split -----------------------------
__global__ void k_kvnorm() {
    int i = blockIdx.x * 256 + threadIdx.x;           // 262144
    float v = g_kv[i] / g_colsum[i >> 6];
    int bh = i >> 12, kr = (i >> 6) & 63, dh = i & 63;
    __half hi, lo;
    split_h(v, hi, lo);
    int o = bh * 4096 + dh * 64 + kr;
    g_kvth[o] = hi;
    g_kvtl[o] = lo;
}

// ---------------- k_qkv: fp16 split mma, ldmatrix fragments --------------------
__global__ __launch_bounds__(256) void k_qkv() {
    extern __shared__ __half sh[];
    __half *Xs   = sh;                               // [128][72]
    __half *Qh   = sh + 9216,  *Ql  = sh + 18432;    // [128][72]
    __half *Wqh  = sh + 27648, *Wql = sh + 32256;    // [64][72]
    __half *kvth = sh + 36864, *kvtl = sh + 41472;   // [dh][kr]
    float  *rsum = (float*)(sh + 46080);
    float  *inv  = rsum + 128;

    const int tid = threadIdx.x, lane = tid & 31, wid = tid >> 5;
    const int wm = wid & 3, wn = wid >> 2;
    const int grp = lane >> 2, tig = lane & 3;
    const int bh = blockIdx.y, b = bh >> 3, h = bh & 7;
    const int n0 = blockIdx.x * 128;

    if (tid < 128) rsum[tid] = 0.f;
    {   // vectorized setup
        const int r = tid >> 2, c0 = (tid & 3) * 16;
        const int gsrc = r * 64 + c0;
        const int sdst = r * 72 + c0;
        *(uint4*)&Wqh[sdst]     = *(const uint4*)&g_wqh[gsrc];
        *(uint4*)&Wqh[sdst + 8] = *(const uint4*)&g_wqh[gsrc + 8];
        *(uint4*)&Wql[sdst]     = *(const uint4*)&g_wql[gsrc];
        *(uint4*)&Wql[sdst + 8] = *(const uint4*)&g_wql[gsrc + 8];
        const __half* kvh = g_kvth + bh * 4096 + gsrc;
        const __half* kvl = g_kvtl + bh * 4096 + gsrc;
        *(uint4*)&kvth[sdst]     = *(const uint4*)kvh;
        *(uint4*)&kvth[sdst + 8] = *(const uint4*)(kvh + 8);
        *(uint4*)&kvtl[sdst]     = *(const uint4*)kvl;
        *(uint4*)&kvtl[sdst + 8] = *(const uint4*)(kvl + 8);
    }
    {
        const int xr = tid >> 1, xc0 = (tid & 1) * 32;
        const __half* xsrc = g_xc + (size_t)(b * NN + n0 + xr) * INNER + h * 64 + xc0;
        #pragma unroll
        for (int j = 0; j < 4; j++)
            *(uint4*)&Xs[xr * 72 + xc0 + j * 8] = *(const uint4*)(xsrc + j * 8);
    }
    __syncthreads();

    const int la_r = (lane & 7) + ((lane >> 3) & 1) * 8;
    const unsigned a_off = (unsigned)la_r * 144 + (lane >> 4) * 16;
    const int lb_r = (lane & 7) + (lane >> 4) * 8;
    const unsigned b_off = (unsigned)lb_r * 144 + ((lane >> 3) & 1) * 16;
    const unsigned XsU = smem_u32(Xs), QhU = smem_u32(Qh), QlU = smem_u32(Ql);
    const unsigned WqhU = smem_u32(Wqh), WqlU = smem_u32(Wql);
    const unsigned kvhU = smem_u32(kvth), kvlU = smem_u32(kvtl);
    const unsigned aT0 = (unsigned)(wm * 32) * 144 + a_off;
    const unsigned aT1 = aT0 + 16u * 144;
    const unsigned nb0 = (unsigned)(wn * 32) * 144 + b_off;
    const unsigned nb1 = nb0 + 16u * 144;

    float qa[2][4][4] = {};
    #pragma unroll
    for (int ks = 0; ks < 4; ks++) {
        const unsigned kcB = (unsigned)ks * 32;
        unsigned a0[4], a1[4];
        lm4(a0, XsU + aT0 + kcB);
        lm4(a1, XsU + aT1 + kcB);
        unsigned qh0[4], qh1[4], ql0[4], ql1[4];
        lm4(qh0, WqhU + nb0 + kcB); lm4(qh1, WqhU + nb1 + kcB);
        lm4(ql0, WqlU + nb0 + kcB); lm4(ql1, WqlU + nb1 + kcB);
        mma_f16(qa[0][0], a0, qh0);     mma_f16(qa[0][0], a0, ql0);
        mma_f16(qa[1][0], a1, qh0);     mma_f16(qa[1][0], a1, ql0);
        mma_f16(qa[0][1], a0, qh0 + 2); mma_f16(qa[0][1], a0, ql0 + 2);
        mma_f16(qa[1][1], a1, qh0 + 2); mma_f16(qa[1][1], a1, ql0 + 2);
        mma_f16(qa[0][2], a0, qh1);     mma_f16(qa[0][2], a0, ql1);
        mma_f16(qa[1][2], a1, qh1);     mma_f16(qa[1][2], a1, ql1);
        mma_f16(qa[0][3], a0, qh1 + 2); mma_f16(qa[0][3], a0, ql1 + 2);
        mma_f16(qa[1][3], a1, qh1 + 2); mma_f16(qa[1][3], a1, ql1 + 2);
    }
    float rp[2][2] = {};
    #pragma unroll
    for (int mt = 0; mt < 2; mt++)
        #pragma unroll
        for (int nt = 0; nt < 4; nt++) {
            const int r = wm * 32 + mt * 16 + grp;
            const int c = wn * 32 + nt * 8 + tig * 2;
            float e0 = __expf(qa[mt][nt][0]), e1 = __expf(qa[mt][nt][1]);
            float e2 = __expf(qa[mt][nt][2]), e3 = __expf(qa[mt][nt][3]);
            rp[mt][0] += e0 + e1; rp[mt][1] += e2 + e3;
            __half h0, l0, h1, l1;
            split_h(e0, h0, l0); split_h(e1, h1, l1);
            *(__half2*)&Qh[r * 72 + c] = __halves2half2(h0, h1);
            *(__half2*)&Ql[r * 72 + c] = __halves2half2(l0, l1);
            split_h(e2, h0, l0); split_h(e3, h1, l1);
            *(__half2*)&Qh[(r + 8) * 72 + c] = __halves2half2(h0, h1);
            *(__half2*)&Ql[(r + 8) * 72 + c] = __halves2half2(l0, l1);
        }
    #pragma unroll
    for (int mt = 0; mt < 2; mt++)
        #pragma unroll
        for (int p = 0; p < 2; p++) {
            float v = rp[mt][p];
            v += __shfl_xor_sync(0xffffffffu, v, 1);
            v += __shfl_xor_sync(0xffffffffu, v, 2);
            if (tig == 0) atomicAdd(&rsum[wm * 32 + mt * 16 + grp + p * 8], v);
        }
    __syncthreads();
    if (tid < 128) inv[tid] = 1.f / rsum[tid];
    __syncthreads();

    float acc[2][4][4] = {};
    #pragma unroll
    for (int ks = 0; ks < 4; ks++) {
        const unsigned kcB = (unsigned)ks * 32;
        unsigned ah0[4], ah1[4], al0[4], al1[4];
        lm4(ah0, QhU + aT0 + kcB); lm4(ah1, QhU + aT1 + kcB);
        lm4(al0, QlU + aT0 + kcB); lm4(al1, QlU + aT1 + kcB);
        unsigned bh0[4], bh1[4], bl0[4], bl1[4];
        lm4(bh0, kvhU + nb0 + kcB); lm4(bh1, kvhU + nb1 + kcB);
        lm4(bl0, kvlU + nb0 + kcB); lm4(bl1, kvlU + nb1 + kcB);
        mma_f16(acc[0][0], ah0, bh0);     mma_f16(acc[0][0], ah0, bl0);     mma_f16(acc[0][0], al0, bh0);
        mma_f16(acc[1][0], ah1, bh0);     mma_f16(acc[1][0], ah1, bl0);     mma_f16(acc[1][0], al1, bh0);
        mma_f16(acc[0][1], ah0, bh0 + 2); mma_f16(acc[0][1], ah0, bl0 + 2); mma_f16(acc[0][1], al0, bh0 + 2);
        mma_f16(acc[1][1], ah1, bh0 + 2); mma_f16(acc[1][1], ah1, bl0 + 2); mma_f16(acc[1][1], al1, bh0 + 2);
        mma_f16(acc[0][2], ah0, bh1);     mma_f16(acc[0][2], ah0, bl1);     mma_f16(acc[0][2], al0, bh1);
        mma_f16(acc[1][2], ah1, bh1);     mma_f16(acc[1][2], ah1, bl1);     mma_f16(acc[1][2], al1, bh1);
        mma_f16(acc[0][3], ah0, bh1 + 2); mma_f16(acc[0][3], ah0, bl1 + 2); mma_f16(acc[0][3], al0, bh1 + 2);
        mma_f16(acc[1][3], ah1, bh1 + 2); mma_f16(acc[1][3], ah1, bl1 + 2); mma_f16(acc[1][3], al1, bh1 + 2);
    }
    #pragma unroll
    for (int mt = 0; mt < 2; mt++)
        #pragma unroll
        for (int nt = 0; nt < 4; nt++) {
            const int r = wm * 32 + mt * 16 + grp;
            const int c = wn * 32 + nt * 8 + tig * 2;
            const float i0 = inv[r], i1 = inv[r + 8];
            __half* d0 = g_qkv + (size_t)(b * NN + n0 + r) * INNER + h * 64 + c;
            __half* d1 = g_qkv + (size_t)(b * NN + n0 + r + 8) * INNER + h * 64 + c;
            *(__half2*)d0 = __floats2half2_rn(acc[mt][nt][0] * i0, acc[mt][nt][1] * i0);
            *(__half2*)d1 = __floats2half2_rn(acc[mt][nt][2] * i1, acc[mt][nt][3] * i1);
        }
}

// ------------------------------------------------------------------------------
extern "C" void kernel_launch(void* const* d_in, const int* in_sizes, int n_in,
                              void* d_out, int out_size) {
    const float* x      = (const float*)d_in[0];
    const float* conv_w = (const float*)d_in[1];
    const float* conv_b = (const float*)d_in[2];
    const float* Wq     = (const float*)d_in[3];
    const float* Wk     = (const float*)d_in[4];
    const float* Wv     = (const float*)d_in[5];
    const float* W1     = (const float*)d_in[6];
    const float* b1     = (const float*)d_in[7];
    const float* W2     = (const float*)d_in[8];
    const float* b2     = (const float*)d_in[9];
    float* out = (float*)d_out;

    using EncFn = decltype(&cuTensorMapEncodeTiled);
    static EncFn enc = nullptr;
    if (!enc) {
        void* fp = nullptr;
        cudaDriverEntryPointQueryResult qr;
        cudaGetDriverEntryPointByVersion("cuTensorMapEncodeTiled", &fp, 12000,
                                         cudaEnableDefault, &qr);
        enc = (EncFn)fp;
    }
    static CUtensorMap mCA, mCB, mA0, mB0, mA1, mB1;
    {
        void *xp, *wp, *qkvp, *w1p, *h1p, *w2p;
        cudaGetSymbolAddress(&xp, g_xh);
        cudaGetSymbolAddress(&wp, g_wch);
        cudaGetSymbolAddress(&qkvp, g_qkv);
        cudaGetSymbolAddress(&w1p, g_w1h);
        cudaGetSymbolAddress(&h1p, g_h1);
        cudaGetSymbolAddress(&w2p, g_w2h);
        cuuint32_t e4[4] = {1, 1, 1, 1};
        cuuint64_t dA[4] = {256, 128, 128, 8};
        cuuint64_t sA[3] = {512, 65536, 8388608};
        cuuint32_t bA[4] = {64, 128, 1, 1};
        enc(&mCA, CU_TENSOR_MAP_DATA_TYPE_FLOAT16, 4, xp, dA, sA, bA, e4,
            CU_TENSOR_MAP_INTERLEAVE_NONE, CU_TENSOR_MAP_SWIZZLE_128B,
            CU_TENSOR_MAP_L2_PROMOTION_L2_128B, CU_TENSOR_MAP_FLOAT_OOB_FILL_NONE);
        cuuint64_t dB[2] = {KCONV, INNER};
        cuuint64_t sB[1] = {KCONV * 2};
        cuuint32_t bB[2] = {64, 128};
        enc(&mCB, CU_TENSOR_MAP_DATA_TYPE_FLOAT16, 2, wp, dB, sB, bB, e4,
            CU_TENSOR_MAP_INTERLEAVE_NONE, CU_TENSOR_MAP_SWIZZLE_128B,
            CU_TENSOR_MAP_L2_PROMOTION_L2_128B, CU_TENSOR_MAP_FLOAT_OOB_FILL_NONE);
        cuuint64_t dA0[2] = {512, 131072}; cuuint64_t sA0[1] = {1024};
        enc(&mA0, CU_TENSOR_MAP_DATA_TYPE_FLOAT16, 2, qkvp, dA0, sA0, bB, e4,
            CU_TENSOR_MAP_INTERLEAVE_NONE, CU_TENSOR_MAP_SWIZZLE_128B,
            CU_TENSOR_MAP_L2_PROMOTION_L2_128B, CU_TENSOR_MAP_FLOAT_OOB_FILL_NONE);
        cuuint64_t dB0[2] = {512, 256}; cuuint64_t sB0[1] = {1024};
        enc(&mB0, CU_TENSOR_MAP_DATA_TYPE_FLOAT16, 2, w1p, dB0, sB0, bB, e4,
            CU_TENSOR_MAP_INTERLEAVE_NONE, CU_TENSOR_MAP_SWIZZLE_128B,
            CU_TENSOR_MAP_L2_PROMOTION_L2_128B, CU_TENSOR_MAP_FLOAT_OOB_FILL_NONE);
        cuuint64_t dA1[2] = {256, 131072}; cuuint64_t sA1[1] = {512};
        enc(&mA1, CU_TENSOR_MAP_DATA_TYPE_FLOAT16, 2, h1p, dA1, sA1, bB, e4,
            CU_TENSOR_MAP_INTERLEAVE_NONE, CU_TENSOR_MAP_SWIZZLE_128B,
            CU_TENSOR_MAP_L2_PROMOTION_L2_128B, CU_TENSOR_MAP_FLOAT_OOB_FILL_NONE);
        cuuint64_t dB1[2] = {256, 256}; cuuint64_t sB1[1] = {512};
        enc(&mB1, CU_TENSOR_MAP_DATA_TYPE_FLOAT16, 2, w2p, dB1, sB1, bB, e4,
            CU_TENSOR_MAP_INTERLEAVE_NONE, CU_TENSOR_MAP_SWIZZLE_128B,
            CU_TENSOR_MAP_L2_PROMOTION_L2_128B, CU_TENSOR_MAP_FLOAT_OOB_FILL_NONE);
    }

    cudaFuncSetAttribute(k_conv, cudaFuncAttributeMaxDynamicSharedMemorySize, 66560);
    cudaFuncSetAttribute(k_mlp<0>, cudaFuncAttributeMaxDynamicSharedMemorySize, 66560);
    cudaFuncSetAttribute(k_mlp<1>, cudaFuncAttributeMaxDynamicSharedMemorySize, 66560);
    cudaFuncSetAttribute(k_kv,   cudaFuncAttributeMaxDynamicSharedMemorySize, 82944);
    cudaFuncSetAttribute(k_qkv,  cudaFuncAttributeMaxDynamicSharedMemorySize, 93184);

    k_wprep<<<(INNER * KCONV + 255) / 256, 256>>>(conv_w);
    k_xprep<<<((BB * NN * CC) / 4 + 255) / 256, 256>>>(x);
    k_wmlp<<<(CC * INNER + 255) / 256, 256>>>(W1, W2);
    k_wsplit<<<16, 256>>>(Wq, Wk, Wv);
    k_init<<<(BB * HEADS * KRR * DHH) / 256, 256>>>();
    k_conv<<<dim3(INNER / 128, (BB * NN) / 128), 256, 66560>>>(mCA, mCB, conv_b);
    k_kv<<<dim3(8, BB * HEADS), 256, 82944>>>();
    k_kvnorm<<<(BB * HEADS * KRR * DHH) / 256, 256>>>();
    k_qkv<<<dim3(128, BB * HEADS), 256, 93184>>>();
    k_mlp<0><<<dim3(CC / 128, (BB * NN) / 128), 256, 66560>>>(mA0, mB0, b1, nullptr);
    k_mlp<1><<<dim3(CC / 128, (BB * NN) / 128), 256, 66560>>>(mA1, mB1, b2, out);
}